// round 1
// baseline (speedup 1.0000x reference)
#include <cuda_runtime.h>
#include <math.h>

#define T_SEQ 4096
#define C_DIM 2048
#define NHEAD 16
#define HS 128
#define NQG 4
#define QKV_DIM 3072
#define SCALE_ATT 0.08838834764831845f  // 1/sqrt(128)

// ---------------- scratch (static device globals; no allocs allowed) ----------------
__device__ float g_qkv[T_SEQ * QKV_DIM];          // 50.3 MB
__device__ float g_q[T_SEQ * NHEAD * HS];         // 33.5 MB  [t][h][d], rope applied
__device__ float g_kd[NQG * HS * T_SEQ];          // 8.4 MB   [g][d][t]  (d-major!), rope applied
__device__ float g_v[T_SEQ * NQG * HS];           // 8.4 MB   [t][g][d]
__device__ float g_y[T_SEQ * C_DIM];              // 33.5 MB  attention output

// ---------------- generic NT GEMM: C[M,N] = A[M,K] * B[N,K]^T ----------------
// BM=BN=128, BK=16, 256 threads, 8x8 microtile per thread.
__global__ __launch_bounds__(256) void gemm_nt(const float* __restrict__ A,
                                               const float* __restrict__ B,
                                               float* __restrict__ C,
                                               int M, int N, int K) {
    __shared__ __align__(16) float As[128 * 16];        // [m][k] untransposed
    __shared__ __align__(16) float Bs[16 * 128];        // [k][n] transposed on store

    int tid = threadIdx.x;
    int tx = tid & 15, ty = tid >> 4;
    int bm = blockIdx.y * 128, bn = blockIdx.x * 128;

    float acc[8][8];
#pragma unroll
    for (int i = 0; i < 8; i++)
#pragma unroll
        for (int j = 0; j < 8; j++) acc[i][j] = 0.f;

    for (int k0 = 0; k0 < K; k0 += 16) {
#pragma unroll
        for (int i = tid; i < 512; i += 256) {
            int m = i >> 2, kk = (i & 3) << 2;
            *(float4*)&As[m * 16 + kk] =
                *(const float4*)&A[(size_t)(bm + m) * K + k0 + kk];
        }
#pragma unroll
        for (int i = tid; i < 512; i += 256) {
            int n = i >> 2, kk = (i & 3) << 2;
            float4 v = *(const float4*)&B[(size_t)(bn + n) * K + k0 + kk];
            Bs[(kk + 0) * 128 + n] = v.x;
            Bs[(kk + 1) * 128 + n] = v.y;
            Bs[(kk + 2) * 128 + n] = v.z;
            Bs[(kk + 3) * 128 + n] = v.w;
        }
        __syncthreads();

#pragma unroll
        for (int kk = 0; kk < 16; kk++) {
            float a[8];
#pragma unroll
            for (int i = 0; i < 8; i++) a[i] = As[(ty * 8 + i) * 16 + kk];  // broadcast
            float4 b0 = *(const float4*)&Bs[kk * 128 + tx * 4];
            float4 b1 = *(const float4*)&Bs[kk * 128 + 64 + tx * 4];
            float b[8] = {b0.x, b0.y, b0.z, b0.w, b1.x, b1.y, b1.z, b1.w};
#pragma unroll
            for (int i = 0; i < 8; i++)
#pragma unroll
                for (int j = 0; j < 8; j++) acc[i][j] += a[i] * b[j];
        }
        __syncthreads();
    }

#pragma unroll
    for (int i = 0; i < 8; i++) {
        int m = bm + ty * 8 + i;
        *(float4*)&C[(size_t)m * N + bn + tx * 4] =
            make_float4(acc[i][0], acc[i][1], acc[i][2], acc[i][3]);
        *(float4*)&C[(size_t)m * N + bn + 64 + tx * 4] =
            make_float4(acc[i][4], acc[i][5], acc[i][6], acc[i][7]);
    }
}

// ---------------- RoPE for Q (+ V split), d-fastest threads (coalesced) ----------------
// h in [0,16): q head rope.  h in [16,20): v group copy.
__global__ __launch_bounds__(256) void rope_qv(const float* __restrict__ cosb,
                                               const float* __restrict__ sinb) {
    int idx = blockIdx.x * blockDim.x + threadIdx.x;  // T*20*64 threads
    if (idx >= T_SEQ * 20 * 64) return;
    int d = idx & 63;
    int h = (idx >> 6) % 20;
    int t = idx / (64 * 20);
    const float* qkv = g_qkv;
    if (h < 16) {
        int base = t * QKV_DIM + (h >> 2) * 768 + (h & 3) * 128;
        float x1 = qkv[base + d];
        float x2 = qkv[base + 64 + d];
        float c = cosb[t * 64 + d], s = sinb[t * 64 + d];
        g_q[t * 2048 + h * 128 + d]      = x1 * c - x2 * s;
        g_q[t * 2048 + h * 128 + 64 + d] = x2 * c + x1 * s;
    } else {
        int g = h - 16;
        int base = t * QKV_DIM + g * 768 + 640;  // slot 5 = v
        g_v[t * 512 + g * 128 + d]      = qkv[base + d];
        g_v[t * 512 + g * 128 + 64 + d] = qkv[base + 64 + d];
    }
}

// ---------------- RoPE for K, t-fastest threads -> coalesced d-major writes ----------------
__global__ __launch_bounds__(256) void rope_k(const float* __restrict__ cosb,
                                              const float* __restrict__ sinb) {
    int idx = blockIdx.x * blockDim.x + threadIdx.x;  // NQG*64*T threads
    if (idx >= NQG * 64 * T_SEQ) return;
    int t = idx & (T_SEQ - 1);
    int d = (idx >> 12) & 63;
    int g = idx >> 18;
    int base = t * QKV_DIM + g * 768 + 512;  // slot 4 = k
    float x1 = g_qkv[base + d];
    float x2 = g_qkv[base + 64 + d];
    float c = cosb[t * 64 + d], s = sinb[t * 64 + d];
    g_kd[(g * 128 + d) * T_SEQ + t]        = x1 * c - x2 * s;
    g_kd[(g * 128 + 64 + d) * T_SEQ + t]   = x2 * c + x1 * s;
}

// ---------------- flash attention: Br=Bc=64, fp32, online softmax ----------------
// grid (64 q-tiles, 16 heads), 256 threads (16x16), 4x4 S microtile, 4x8 O microtile.
__global__ __launch_bounds__(256) void attn_kernel() {
    extern __shared__ __align__(16) float sm[];
    float* Qs = sm;                    // [64][128]
    float* Kt = sm + 64 * 128;         // [128][64]  (d-major)
    float* Vs = Kt + 128 * 64;         // [64][128]
    float* Ps = Vs + 64 * 128;         // [64][64]

    int tid = threadIdx.x;
    int tx = tid & 15, ty = tid >> 4;
    int h = blockIdx.y;
    int qt = 63 - blockIdx.x;          // longest work first
    int g = h >> 2;
    int r0 = ty * 4, c0 = tx * 4;

    // load + scale Q tile
    for (int i = tid; i < 64 * 32; i += 256) {
        int r = i >> 5, d4 = (i & 31) << 2;
        float4 v = *(const float4*)&g_q[(size_t)(qt * 64 + r) * 2048 + h * 128 + d4];
        v.x *= SCALE_ATT; v.y *= SCALE_ATT; v.z *= SCALE_ATT; v.w *= SCALE_ATT;
        *(float4*)&Qs[r * 128 + d4] = v;
    }

    float o[4][8];
#pragma unroll
    for (int i = 0; i < 4; i++)
#pragma unroll
        for (int j = 0; j < 8; j++) o[i][j] = 0.f;
    float m_i[4] = {-1e30f, -1e30f, -1e30f, -1e30f};
    float l_i[4] = {0.f, 0.f, 0.f, 0.f};

    for (int kt = 0; kt <= qt; kt++) {
        __syncthreads();  // prior-iteration consumers done before overwrite
        // K tile: Kt[d][c] <- g_kd[g][d][kt*64+c]  (coalesced LDG, conflict-free STS)
        for (int i = tid; i < 128 * 16; i += 256) {
            int d = i >> 4, c4 = (i & 15) << 2;
            *(float4*)&Kt[d * 64 + c4] =
                *(const float4*)&g_kd[(size_t)(g * 128 + d) * T_SEQ + kt * 64 + c4];
        }
        // V tile
        for (int i = tid; i < 64 * 32; i += 256) {
            int r = i >> 5, d4 = (i & 31) << 2;
            *(float4*)&Vs[r * 128 + d4] =
                *(const float4*)&g_v[(size_t)(kt * 64 + r) * 512 + g * 128 + d4];
        }
        __syncthreads();

        // S = Q K^T  (4x4 per thread)
        float acc[4][4];
#pragma unroll
        for (int i = 0; i < 4; i++)
#pragma unroll
            for (int j = 0; j < 4; j++) acc[i][j] = 0.f;

#pragma unroll 4
        for (int d4 = 0; d4 < 32; d4++) {
            float4 q[4];
#pragma unroll
            for (int i = 0; i < 4; i++)
                q[i] = *(const float4*)&Qs[(r0 + i) * 128 + d4 * 4];
            float kmat[4][4];
#pragma unroll
            for (int dd = 0; dd < 4; dd++) {
                float4 kv = *(const float4*)&Kt[(d4 * 4 + dd) * 64 + c0];
                kmat[dd][0] = kv.x; kmat[dd][1] = kv.y;
                kmat[dd][2] = kv.z; kmat[dd][3] = kv.w;
            }
#pragma unroll
            for (int i = 0; i < 4; i++)
#pragma unroll
                for (int j = 0; j < 4; j++)
                    acc[i][j] += q[i].x * kmat[0][j] + q[i].y * kmat[1][j]
                               + q[i].z * kmat[2][j] + q[i].w * kmat[3][j];
        }

        // causal mask on the diagonal tile
        if (kt == qt) {
#pragma unroll
            for (int i = 0; i < 4; i++)
#pragma unroll
                for (int j = 0; j < 4; j++)
                    if (c0 + j > r0 + i) acc[i][j] = -1e30f;
        }

        // online softmax (row reductions across the 16-lane tx dimension)
#pragma unroll
        for (int i = 0; i < 4; i++) {
            float mt = fmaxf(fmaxf(acc[i][0], acc[i][1]), fmaxf(acc[i][2], acc[i][3]));
#pragma unroll
            for (int w = 1; w < 16; w <<= 1)
                mt = fmaxf(mt, __shfl_xor_sync(0xffffffffu, mt, w));
            float mn = fmaxf(m_i[i], mt);
            float alpha = __expf(m_i[i] - mn);
            m_i[i] = mn;
            float rs = 0.f;
#pragma unroll
            for (int j = 0; j < 4; j++) {
                acc[i][j] = __expf(acc[i][j] - mn);
                rs += acc[i][j];
            }
#pragma unroll
            for (int w = 1; w < 16; w <<= 1)
                rs += __shfl_xor_sync(0xffffffffu, rs, w);
            l_i[i] = l_i[i] * alpha + rs;
#pragma unroll
            for (int j = 0; j < 8; j++) o[i][j] *= alpha;
            *(float4*)&Ps[(r0 + i) * 64 + c0] =
                make_float4(acc[i][0], acc[i][1], acc[i][2], acc[i][3]);
        }
        __syncthreads();

        // O += P V  (4 rows x 8 cols per thread; cols tx*4 and 64+tx*4)
#pragma unroll 2
        for (int s4 = 0; s4 < 16; s4++) {
            float pmat[4][4];
#pragma unroll
            for (int i = 0; i < 4; i++) {
                float4 pv4 = *(const float4*)&Ps[(r0 + i) * 64 + s4 * 4];
                pmat[i][0] = pv4.x; pmat[i][1] = pv4.y;
                pmat[i][2] = pv4.z; pmat[i][3] = pv4.w;
            }
#pragma unroll
            for (int ss = 0; ss < 4; ss++) {
                float4 va  = *(const float4*)&Vs[(s4 * 4 + ss) * 128 + c0];
                float4 vb2 = *(const float4*)&Vs[(s4 * 4 + ss) * 128 + 64 + c0];
#pragma unroll
                for (int i = 0; i < 4; i++) {
                    float pi = pmat[i][ss];
                    o[i][0] += pi * va.x;  o[i][1] += pi * va.y;
                    o[i][2] += pi * va.z;  o[i][3] += pi * va.w;
                    o[i][4] += pi * vb2.x; o[i][5] += pi * vb2.y;
                    o[i][6] += pi * vb2.z; o[i][7] += pi * vb2.w;
                }
            }
        }
    }

    // finalize: O /= l, write y[t][h*128 + d]
#pragma unroll
    for (int i = 0; i < 4; i++) {
        float inv = 1.f / l_i[i];
        size_t row = (size_t)(qt * 64 + r0 + i) * 2048 + h * 128;
        *(float4*)&g_y[row + c0] =
            make_float4(o[i][0] * inv, o[i][1] * inv, o[i][2] * inv, o[i][3] * inv);
        *(float4*)&g_y[row + 64 + c0] =
            make_float4(o[i][4] * inv, o[i][5] * inv, o[i][6] * inv, o[i][7] * inv);
    }
}

// ---------------- launch ----------------
extern "C" void kernel_launch(void* const* d_in, const int* in_sizes, int n_in,
                              void* d_out, int out_size) {
    const float* x    = (const float*)d_in[0];
    const float* cosb = (const float*)d_in[1];
    const float* sinb = (const float*)d_in[2];
    const float* Wa   = (const float*)d_in[3];
    const float* Wp   = (const float*)d_in[4];
    float* out = (float*)d_out;

    float *qkv_p, *y_p;
    cudaGetSymbolAddress((void**)&qkv_p, g_qkv);
    cudaGetSymbolAddress((void**)&y_p, g_y);

    // 1) qkv = x @ W_attn^T   (M=4096, N=3072, K=2048)
    gemm_nt<<<dim3(QKV_DIM / 128, T_SEQ / 128), 256>>>(x, Wa, qkv_p,
                                                       T_SEQ, QKV_DIM, C_DIM);
    // 2) rope q + split v
    rope_qv<<<(T_SEQ * 20 * 64) / 256, 256>>>(cosb, sinb);
    // 3) rope k (d-major output)
    rope_k<<<(NQG * 64 * T_SEQ) / 256, 256>>>(cosb, sinb);
    // 4) attention
    const int smem_bytes = (64 * 128 + 128 * 64 + 64 * 128 + 64 * 64) * sizeof(float);
    cudaFuncSetAttribute(attn_kernel, cudaFuncAttributeMaxDynamicSharedMemorySize,
                         smem_bytes);
    attn_kernel<<<dim3(64, NHEAD), 256, smem_bytes>>>();
    // 5) out = y @ W_proj^T   (M=4096, N=2048, K=2048)
    gemm_nt<<<dim3(C_DIM / 128, T_SEQ / 128), 256>>>(y_p, Wp, out,
                                                     T_SEQ, C_DIM, C_DIM);
}

// round 3
// speedup vs baseline: 1.5510x; 1.5510x over previous
#include <cuda_runtime.h>
#include <cuda_bf16.h>
#include <math.h>
#include <stdint.h>

#define T_SEQ 4096
#define C_DIM 2048
#define NHEAD 16
#define HS 128
#define NQG 4
#define QKV_DIM 3072
#define SCALE_ATT 0.08838834764831845f  // 1/sqrt(128)

// ---------------- scratch ----------------
__device__ float g_qkv[T_SEQ * QKV_DIM];
__device__ float g_q[T_SEQ * NHEAD * HS];
__device__ float g_kd[NQG * HS * T_SEQ];
__device__ float g_v[T_SEQ * NQG * HS];
__device__ float g_y[T_SEQ * C_DIM];

// split-bf16 operand buffers
__device__ __nv_bfloat16 g_xh[T_SEQ * C_DIM];
__device__ __nv_bfloat16 g_xl[T_SEQ * C_DIM];
__device__ __nv_bfloat16 g_wah[QKV_DIM * C_DIM];
__device__ __nv_bfloat16 g_wal[QKV_DIM * C_DIM];
__device__ __nv_bfloat16 g_yh[T_SEQ * C_DIM];
__device__ __nv_bfloat16 g_yl[T_SEQ * C_DIM];
__device__ __nv_bfloat16 g_wph[C_DIM * C_DIM];
__device__ __nv_bfloat16 g_wpl[C_DIM * C_DIM];

// ---------------- PTX helpers (arch-agnostic: ldmatrix / mma.sync / cp.async) ----------------
__device__ __forceinline__ uint32_t smem_u32(const void* p) {
    uint32_t a;
    asm("{ .reg .u64 t; cvta.to.shared.u64 t, %1; cvt.u32.u64 %0, t; }"
        : "=r"(a) : "l"(p));
    return a;
}

__device__ __forceinline__ void cp_async16(uint32_t s, const void* g) {
    asm volatile("cp.async.cg.shared.global [%0], [%1], 16;" :: "r"(s), "l"(g));
}
#define CP_COMMIT() asm volatile("cp.async.commit_group;" ::: "memory")
#define CP_WAIT(n)  asm volatile("cp.async.wait_group %0;" :: "n"(n) : "memory")

__device__ __forceinline__ void ldsm4(uint32_t* f, uint32_t a) {
    asm volatile("ldmatrix.sync.aligned.m8n8.x4.shared.b16 {%0,%1,%2,%3}, [%4];"
                 : "=r"(f[0]), "=r"(f[1]), "=r"(f[2]), "=r"(f[3]) : "r"(a));
}

__device__ __forceinline__ void mma16816(float* d, const uint32_t* a,
                                         uint32_t b0, uint32_t b1) {
    asm volatile(
        "mma.sync.aligned.m16n8k16.row.col.f32.bf16.bf16.f32 "
        "{%0,%1,%2,%3}, {%4,%5,%6,%7}, {%8,%9}, {%0,%1,%2,%3};"
        : "+f"(d[0]), "+f"(d[1]), "+f"(d[2]), "+f"(d[3])
        : "r"(a[0]), "r"(a[1]), "r"(a[2]), "r"(a[3]), "r"(b0), "r"(b1));
}

// smem tile: [128 rows][32 bf16] = rows of 64B, 4x16B chunks, XOR swizzle.
// Verified: ldmatrix 8-row phases hit 8 distinct 16B bank groups (conflict-free).
__device__ __forceinline__ int sw_off(int r, int c) {
    return r * 64 + ((c ^ ((r >> 1) & 3)) << 4);
}

// ---------------- split fp32 -> (hi, lo) bf16 ----------------
__global__ __launch_bounds__(256) void split_bf16(const float* __restrict__ s,
                                                  __nv_bfloat16* __restrict__ h,
                                                  __nv_bfloat16* __restrict__ l, int n) {
    int i = blockIdx.x * 256 + threadIdx.x;
    if (i < n) {
        float x = s[i];
        __nv_bfloat16 hb = __float2bfloat16(x);
        h[i] = hb;
        l[i] = __float2bfloat16(x - __bfloat162float(hb));
    }
}

// ---------------- mma.sync split-bf16 GEMM: C[M,N] = A[M,K] * B[N,K]^T ----------------
// CTA 128x128, BK=32, 8 warps (4 M x 2 N), warp tile 32x64.
// 3 terms: Ah*Bh + Al*Bh + Ah*Bl accumulated into the same f32 regs.
#define BK 32
#define TILE_B 8192          // one 128x32 bf16 tile
#define STAGE_B (4 * TILE_B) // Ah, Al, Bh, Bl

__global__ __launch_bounds__(256) void gemm_mma(const __nv_bfloat16* __restrict__ Ah,
                                                const __nv_bfloat16* __restrict__ Al,
                                                const __nv_bfloat16* __restrict__ Bh,
                                                const __nv_bfloat16* __restrict__ Bl,
                                                float* __restrict__ C, int N, int K) {
    extern __shared__ __align__(128) char smem[];
    int tid = threadIdx.x;
    int lane = tid & 31, w = tid >> 5;
    int bm = blockIdx.y * 128, bn = blockIdx.x * 128;
    int mw = (w & 3) * 32;   // warp M offset in CTA tile
    int nw = (w >> 2) * 64;  // warp N offset
    uint32_t sbase = smem_u32(smem);

    float acc[2][8][4];
#pragma unroll
    for (int i = 0; i < 2; i++)
#pragma unroll
        for (int j = 0; j < 8; j++)
#pragma unroll
            for (int q = 0; q < 4; q++) acc[i][j][q] = 0.f;

    const int NC = K / BK;
    int lr = tid >> 2, lc = tid & 3;  // load row/chunk assignment

    // ---- stage loader (8 x 16B cp.async per thread) ----
    auto issue = [&](int c, int buf) {
        uint32_t st = sbase + buf * STAGE_B;
        int kc = c * BK;
#pragma unroll
        for (int half = 0; half < 2; half++) {
            int rr = lr + half * 64;
            int so = sw_off(rr, lc);
            size_t gA = (size_t)(bm + rr) * K + kc + lc * 8;
            size_t gB = (size_t)(bn + rr) * K + kc + lc * 8;
            cp_async16(st + so, Ah + gA);
            cp_async16(st + TILE_B + so, Al + gA);
            cp_async16(st + 2 * TILE_B + so, Bh + gB);
            cp_async16(st + 3 * TILE_B + so, Bl + gB);
        }
    };

    issue(0, 0);
    CP_COMMIT();

    int rA = mw + (lane & 15);
    int rB = nw + (lane & 15);

    for (int c = 0; c < NC; c++) {
        if (c + 1 < NC) {
            issue(c + 1, (c + 1) & 1);
            CP_COMMIT();
            CP_WAIT(1);
        } else {
            CP_WAIT(0);
        }
        __syncthreads();

        uint32_t st = sbase + (c & 1) * STAGE_B;
#pragma unroll
        for (int k16 = 0; k16 < 2; k16++) {
            int cchunk = k16 * 2 + (lane >> 4);
            uint32_t ah[2][4], al[2][4], bh[4][4], bl[4][4];
#pragma unroll
            for (int mi = 0; mi < 2; mi++)
                ldsm4(ah[mi], st + sw_off(rA + mi * 16, cchunk));
#pragma unroll
            for (int ni = 0; ni < 4; ni++)
                ldsm4(bh[ni], st + 2 * TILE_B + sw_off(rB + ni * 16, cchunk));
            // term 1: Ah*Bh
#pragma unroll
            for (int mi = 0; mi < 2; mi++)
#pragma unroll
                for (int ni = 0; ni < 4; ni++)
#pragma unroll
                    for (int s = 0; s < 2; s++)
                        mma16816(acc[mi][ni * 2 + s], ah[mi], bh[ni][s], bh[ni][2 + s]);
            // term 2: Al*Bh
#pragma unroll
            for (int mi = 0; mi < 2; mi++)
                ldsm4(al[mi], st + TILE_B + sw_off(rA + mi * 16, cchunk));
#pragma unroll
            for (int mi = 0; mi < 2; mi++)
#pragma unroll
                for (int ni = 0; ni < 4; ni++)
#pragma unroll
                    for (int s = 0; s < 2; s++)
                        mma16816(acc[mi][ni * 2 + s], al[mi], bh[ni][s], bh[ni][2 + s]);
            // term 3: Ah*Bl
#pragma unroll
            for (int ni = 0; ni < 4; ni++)
                ldsm4(bl[ni], st + 3 * TILE_B + sw_off(rB + ni * 16, cchunk));
#pragma unroll
            for (int mi = 0; mi < 2; mi++)
#pragma unroll
                for (int ni = 0; ni < 4; ni++)
#pragma unroll
                    for (int s = 0; s < 2; s++)
                        mma16816(acc[mi][ni * 2 + s], ah[mi], bl[ni][s], bl[ni][2 + s]);
        }
        __syncthreads();
    }

    // epilogue: direct f32 stores
    int gid = lane >> 2, q = lane & 3;
#pragma unroll
    for (int mi = 0; mi < 2; mi++)
#pragma unroll
        for (int j = 0; j < 8; j++) {
            int row = bm + mw + mi * 16 + gid;
            int col = bn + nw + j * 8 + q * 2;
            *(float2*)&C[(size_t)row * N + col] =
                make_float2(acc[mi][j][0], acc[mi][j][1]);
            *(float2*)&C[(size_t)(row + 8) * N + col] =
                make_float2(acc[mi][j][2], acc[mi][j][3]);
        }
}

// ---------------- RoPE for Q (+ V split) ----------------
__global__ __launch_bounds__(256) void rope_qv(const float* __restrict__ cosb,
                                               const float* __restrict__ sinb) {
    int idx = blockIdx.x * blockDim.x + threadIdx.x;
    if (idx >= T_SEQ * 20 * 64) return;
    int d = idx & 63;
    int h = (idx >> 6) % 20;
    int t = idx / (64 * 20);
    const float* qkv = g_qkv;
    if (h < 16) {
        int base = t * QKV_DIM + (h >> 2) * 768 + (h & 3) * 128;
        float x1 = qkv[base + d];
        float x2 = qkv[base + 64 + d];
        float c = cosb[t * 64 + d], s = sinb[t * 64 + d];
        g_q[t * 2048 + h * 128 + d]      = x1 * c - x2 * s;
        g_q[t * 2048 + h * 128 + 64 + d] = x2 * c + x1 * s;
    } else {
        int g = h - 16;
        int base = t * QKV_DIM + g * 768 + 640;
        g_v[t * 512 + g * 128 + d]      = qkv[base + d];
        g_v[t * 512 + g * 128 + 64 + d] = qkv[base + 64 + d];
    }
}

// ---------------- RoPE for K (d-major output) ----------------
__global__ __launch_bounds__(256) void rope_k(const float* __restrict__ cosb,
                                              const float* __restrict__ sinb) {
    int idx = blockIdx.x * blockDim.x + threadIdx.x;
    if (idx >= NQG * 64 * T_SEQ) return;
    int t = idx & (T_SEQ - 1);
    int d = (idx >> 12) & 63;
    int g = idx >> 18;
    int base = t * QKV_DIM + g * 768 + 512;
    float x1 = g_qkv[base + d];
    float x2 = g_qkv[base + 64 + d];
    float c = cosb[t * 64 + d], s = sinb[t * 64 + d];
    g_kd[(g * 128 + d) * T_SEQ + t]      = x1 * c - x2 * s;
    g_kd[(g * 128 + 64 + d) * T_SEQ + t] = x2 * c + x1 * s;
}

// ---------------- flash attention (fp32 SIMT, unchanged from R1) ----------------
__global__ __launch_bounds__(256) void attn_kernel() {
    extern __shared__ __align__(16) float sm[];
    float* Qs = sm;
    float* Kt = sm + 64 * 128;
    float* Vs = Kt + 128 * 64;
    float* Ps = Vs + 64 * 128;

    int tid = threadIdx.x;
    int tx = tid & 15, ty = tid >> 4;
    int h = blockIdx.y;
    int qt = 63 - blockIdx.x;
    int g = h >> 2;
    int r0 = ty * 4, c0 = tx * 4;

    for (int i = tid; i < 64 * 32; i += 256) {
        int r = i >> 5, d4 = (i & 31) << 2;
        float4 v = *(const float4*)&g_q[(size_t)(qt * 64 + r) * 2048 + h * 128 + d4];
        v.x *= SCALE_ATT; v.y *= SCALE_ATT; v.z *= SCALE_ATT; v.w *= SCALE_ATT;
        *(float4*)&Qs[r * 128 + d4] = v;
    }

    float o[4][8];
#pragma unroll
    for (int i = 0; i < 4; i++)
#pragma unroll
        for (int j = 0; j < 8; j++) o[i][j] = 0.f;
    float m_i[4] = {-1e30f, -1e30f, -1e30f, -1e30f};
    float l_i[4] = {0.f, 0.f, 0.f, 0.f};

    for (int kt = 0; kt <= qt; kt++) {
        __syncthreads();
        for (int i = tid; i < 128 * 16; i += 256) {
            int d = i >> 4, c4 = (i & 15) << 2;
            *(float4*)&Kt[d * 64 + c4] =
                *(const float4*)&g_kd[(size_t)(g * 128 + d) * T_SEQ + kt * 64 + c4];
        }
        for (int i = tid; i < 64 * 32; i += 256) {
            int r = i >> 5, d4 = (i & 31) << 2;
            *(float4*)&Vs[r * 128 + d4] =
                *(const float4*)&g_v[(size_t)(kt * 64 + r) * 512 + g * 128 + d4];
        }
        __syncthreads();

        float acc[4][4];
#pragma unroll
        for (int i = 0; i < 4; i++)
#pragma unroll
            for (int j = 0; j < 4; j++) acc[i][j] = 0.f;

#pragma unroll 4
        for (int d4 = 0; d4 < 32; d4++) {
            float4 q[4];
#pragma unroll
            for (int i = 0; i < 4; i++)
                q[i] = *(const float4*)&Qs[(r0 + i) * 128 + d4 * 4];
            float kmat[4][4];
#pragma unroll
            for (int dd = 0; dd < 4; dd++) {
                float4 kv = *(const float4*)&Kt[(d4 * 4 + dd) * 64 + c0];
                kmat[dd][0] = kv.x; kmat[dd][1] = kv.y;
                kmat[dd][2] = kv.z; kmat[dd][3] = kv.w;
            }
#pragma unroll
            for (int i = 0; i < 4; i++)
#pragma unroll
                for (int j = 0; j < 4; j++)
                    acc[i][j] += q[i].x * kmat[0][j] + q[i].y * kmat[1][j]
                               + q[i].z * kmat[2][j] + q[i].w * kmat[3][j];
        }

        if (kt == qt) {
#pragma unroll
            for (int i = 0; i < 4; i++)
#pragma unroll
                for (int j = 0; j < 4; j++)
                    if (c0 + j > r0 + i) acc[i][j] = -1e30f;
        }

#pragma unroll
        for (int i = 0; i < 4; i++) {
            float mt = fmaxf(fmaxf(acc[i][0], acc[i][1]), fmaxf(acc[i][2], acc[i][3]));
#pragma unroll
            for (int w = 1; w < 16; w <<= 1)
                mt = fmaxf(mt, __shfl_xor_sync(0xffffffffu, mt, w));
            float mn = fmaxf(m_i[i], mt);
            float alpha = __expf(m_i[i] - mn);
            m_i[i] = mn;
            float rs = 0.f;
#pragma unroll
            for (int j = 0; j < 4; j++) {
                acc[i][j] = __expf(acc[i][j] - mn);
                rs += acc[i][j];
            }
#pragma unroll
            for (int w = 1; w < 16; w <<= 1)
                rs += __shfl_xor_sync(0xffffffffu, rs, w);
            l_i[i] = l_i[i] * alpha + rs;
#pragma unroll
            for (int j = 0; j < 8; j++) o[i][j] *= alpha;
            *(float4*)&Ps[(r0 + i) * 64 + c0] =
                make_float4(acc[i][0], acc[i][1], acc[i][2], acc[i][3]);
        }
        __syncthreads();

#pragma unroll 2
        for (int s4 = 0; s4 < 16; s4++) {
            float pmat[4][4];
#pragma unroll
            for (int i = 0; i < 4; i++) {
                float4 pv4 = *(const float4*)&Ps[(r0 + i) * 64 + s4 * 4];
                pmat[i][0] = pv4.x; pmat[i][1] = pv4.y;
                pmat[i][2] = pv4.z; pmat[i][3] = pv4.w;
            }
#pragma unroll
            for (int ss = 0; ss < 4; ss++) {
                float4 va  = *(const float4*)&Vs[(s4 * 4 + ss) * 128 + c0];
                float4 vb2 = *(const float4*)&Vs[(s4 * 4 + ss) * 128 + 64 + c0];
#pragma unroll
                for (int i = 0; i < 4; i++) {
                    float pi = pmat[i][ss];
                    o[i][0] += pi * va.x;  o[i][1] += pi * va.y;
                    o[i][2] += pi * va.z;  o[i][3] += pi * va.w;
                    o[i][4] += pi * vb2.x; o[i][5] += pi * vb2.y;
                    o[i][6] += pi * vb2.z; o[i][7] += pi * vb2.w;
                }
            }
        }
    }

#pragma unroll
    for (int i = 0; i < 4; i++) {
        float inv = 1.f / l_i[i];
        size_t row = (size_t)(qt * 64 + r0 + i) * 2048 + h * 128;
        *(float4*)&g_y[row + c0] =
            make_float4(o[i][0] * inv, o[i][1] * inv, o[i][2] * inv, o[i][3] * inv);
        *(float4*)&g_y[row + 64 + c0] =
            make_float4(o[i][4] * inv, o[i][5] * inv, o[i][6] * inv, o[i][7] * inv);
    }
}

// ---------------- launch ----------------
extern "C" void kernel_launch(void* const* d_in, const int* in_sizes, int n_in,
                              void* d_out, int out_size) {
    const float* x    = (const float*)d_in[0];
    const float* cosb = (const float*)d_in[1];
    const float* sinb = (const float*)d_in[2];
    const float* Wa   = (const float*)d_in[3];
    const float* Wp   = (const float*)d_in[4];
    float* out = (float*)d_out;

    float *qkv_p, *y_p;
    cudaGetSymbolAddress((void**)&qkv_p, g_qkv);
    cudaGetSymbolAddress((void**)&y_p, g_y);
    __nv_bfloat16 *xh, *xl, *wah, *wal, *yh, *yl, *wph, *wpl;
    cudaGetSymbolAddress((void**)&xh, g_xh);   cudaGetSymbolAddress((void**)&xl, g_xl);
    cudaGetSymbolAddress((void**)&wah, g_wah); cudaGetSymbolAddress((void**)&wal, g_wal);
    cudaGetSymbolAddress((void**)&yh, g_yh);   cudaGetSymbolAddress((void**)&yl, g_yl);
    cudaGetSymbolAddress((void**)&wph, g_wph); cudaGetSymbolAddress((void**)&wpl, g_wpl);

    const int gemm_smem = 2 * STAGE_B;  // 64 KB
    cudaFuncSetAttribute(gemm_mma, cudaFuncAttributeMaxDynamicSharedMemorySize, gemm_smem);

    // 1) split x, W_attn into bf16 hi/lo
    split_bf16<<<(T_SEQ * C_DIM + 255) / 256, 256>>>(x, xh, xl, T_SEQ * C_DIM);
    split_bf16<<<(QKV_DIM * C_DIM + 255) / 256, 256>>>(Wa, wah, wal, QKV_DIM * C_DIM);

    // 2) qkv = x @ W_attn^T  (mma.sync, M=4096 N=3072 K=2048)
    gemm_mma<<<dim3(QKV_DIM / 128, T_SEQ / 128), 256, gemm_smem>>>(
        xh, xl, wah, wal, qkv_p, QKV_DIM, C_DIM);

    // 3) rope q + v split, rope k
    rope_qv<<<(T_SEQ * 20 * 64) / 256, 256>>>(cosb, sinb);
    rope_k<<<(NQG * 64 * T_SEQ) / 256, 256>>>(cosb, sinb);

    // 4) attention
    const int attn_smem = (64 * 128 + 128 * 64 + 64 * 128 + 64 * 64) * sizeof(float);
    cudaFuncSetAttribute(attn_kernel, cudaFuncAttributeMaxDynamicSharedMemorySize, attn_smem);
    attn_kernel<<<dim3(64, NHEAD), 256, attn_smem>>>();

    // 5) split y, W_proj; out = y @ W_proj^T (mma.sync, M=4096 N=2048 K=2048)
    split_bf16<<<(T_SEQ * C_DIM + 255) / 256, 256>>>(y_p, yh, yl, T_SEQ * C_DIM);
    split_bf16<<<(C_DIM * C_DIM + 255) / 256, 256>>>(Wp, wph, wpl, C_DIM * C_DIM);
    gemm_mma<<<dim3(C_DIM / 128, T_SEQ / 128), 256, gemm_smem>>>(
        yh, yl, wph, wpl, out, C_DIM, C_DIM);
}

// round 4
// speedup vs baseline: 2.7848x; 1.7955x over previous
#include <cuda_runtime.h>
#include <cuda_bf16.h>
#include <math.h>
#include <stdint.h>

#define T_SEQ 4096
#define C_DIM 2048
#define NHEAD 16
#define HS 128
#define NQG 4
#define QKV_DIM 3072
#define SCALE_ATT 0.08838834764831845f  // 1/sqrt(128)

// ---------------- scratch ----------------
__device__ float g_qkv[T_SEQ * QKV_DIM];

__device__ __nv_bfloat16 g_xh[T_SEQ * C_DIM];
__device__ __nv_bfloat16 g_xl[T_SEQ * C_DIM];
__device__ __nv_bfloat16 g_wah[QKV_DIM * C_DIM];
__device__ __nv_bfloat16 g_wal[QKV_DIM * C_DIM];
__device__ __nv_bfloat16 g_wph[C_DIM * C_DIM];
__device__ __nv_bfloat16 g_wpl[C_DIM * C_DIM];

// attention operands (bf16 hi/lo)
__device__ __nv_bfloat16 g_qh[T_SEQ * NHEAD * HS];   // [t][h*128+d], pre-scaled
__device__ __nv_bfloat16 g_ql[T_SEQ * NHEAD * HS];
__device__ __nv_bfloat16 g_kh[NQG * T_SEQ * HS];     // [g][t][d]
__device__ __nv_bfloat16 g_kl[NQG * T_SEQ * HS];
__device__ __nv_bfloat16 g_vh[NQG * HS * T_SEQ];     // [g][d][t]  (d-major)
__device__ __nv_bfloat16 g_vl[NQG * HS * T_SEQ];
// attention output (bf16 hi/lo, feeds GEMM2 directly)
__device__ __nv_bfloat16 g_yh[T_SEQ * C_DIM];
__device__ __nv_bfloat16 g_yl[T_SEQ * C_DIM];

// ---------------- PTX helpers ----------------
__device__ __forceinline__ uint32_t smem_u32(const void* p) {
    uint32_t a;
    asm("{ .reg .u64 t; cvta.to.shared.u64 t, %1; cvt.u32.u64 %0, t; }"
        : "=r"(a) : "l"(p));
    return a;
}
__device__ __forceinline__ void cp_async16(uint32_t s, const void* g) {
    asm volatile("cp.async.cg.shared.global [%0], [%1], 16;" :: "r"(s), "l"(g));
}
#define CP_COMMIT() asm volatile("cp.async.commit_group;" ::: "memory")
#define CP_WAIT(n)  asm volatile("cp.async.wait_group %0;" :: "n"(n) : "memory")

__device__ __forceinline__ void ldsm4(uint32_t* f, uint32_t a) {
    asm volatile("ldmatrix.sync.aligned.m8n8.x4.shared.b16 {%0,%1,%2,%3}, [%4];"
                 : "=r"(f[0]), "=r"(f[1]), "=r"(f[2]), "=r"(f[3]) : "r"(a));
}
__device__ __forceinline__ void mma16816(float* d, const uint32_t* a,
                                         uint32_t b0, uint32_t b1) {
    asm volatile(
        "mma.sync.aligned.m16n8k16.row.col.f32.bf16.bf16.f32 "
        "{%0,%1,%2,%3}, {%4,%5,%6,%7}, {%8,%9}, {%0,%1,%2,%3};"
        : "+f"(d[0]), "+f"(d[1]), "+f"(d[2]), "+f"(d[3])
        : "r"(a[0]), "r"(a[1]), "r"(a[2]), "r"(a[3]), "r"(b0), "r"(b1));
}
// pack two f32 -> bf16x2 (lo = first element)
__device__ __forceinline__ uint32_t pack2bf(float lo, float hi) {
    uint32_t r;
    asm("cvt.rn.bf16x2.f32 %0, %1, %2;" : "=r"(r) : "f"(hi), "f"(lo));
    return r;
}
__device__ __forceinline__ float lo_f(uint32_t u) { return __uint_as_float(u << 16); }
__device__ __forceinline__ float hi_f(uint32_t u) { return __uint_as_float(u & 0xffff0000u); }

// 64B-row XOR swizzle (rows of 32 bf16, 4x16B chunks) — conflict-free ldmatrix phases
__device__ __forceinline__ int sw_off(int r, int c) {
    return r * 64 + ((c ^ ((r >> 1) & 3)) << 4);
}

// ---------------- split fp32 -> (hi, lo) bf16 ----------------
__global__ __launch_bounds__(256) void split_bf16(const float* __restrict__ s,
                                                  __nv_bfloat16* __restrict__ h,
                                                  __nv_bfloat16* __restrict__ l, int n) {
    int i = blockIdx.x * 256 + threadIdx.x;
    if (i < n) {
        float x = s[i];
        __nv_bfloat16 hb = __float2bfloat16(x);
        h[i] = hb;
        l[i] = __float2bfloat16(x - __bfloat162float(hb));
    }
}

// ---------------- mma.sync split-bf16 GEMM (from R3, unchanged) ----------------
#define BK 32
#define TILE_B 8192
#define STAGE_B (4 * TILE_B)

__global__ __launch_bounds__(256) void gemm_mma(const __nv_bfloat16* __restrict__ Ah,
                                                const __nv_bfloat16* __restrict__ Al,
                                                const __nv_bfloat16* __restrict__ Bh,
                                                const __nv_bfloat16* __restrict__ Bl,
                                                float* __restrict__ C, int N, int K) {
    extern __shared__ __align__(128) char smem[];
    int tid = threadIdx.x;
    int lane = tid & 31, w = tid >> 5;
    int bm = blockIdx.y * 128, bn = blockIdx.x * 128;
    int mw = (w & 3) * 32, nw = (w >> 2) * 64;
    uint32_t sbase = smem_u32(smem);

    float acc[2][8][4];
#pragma unroll
    for (int i = 0; i < 2; i++)
#pragma unroll
        for (int j = 0; j < 8; j++)
#pragma unroll
            for (int q = 0; q < 4; q++) acc[i][j][q] = 0.f;

    const int NC = K / BK;
    int lr = tid >> 2, lc = tid & 3;

    auto issue = [&](int c, int buf) {
        uint32_t st = sbase + buf * STAGE_B;
        int kc = c * BK;
#pragma unroll
        for (int half = 0; half < 2; half++) {
            int rr = lr + half * 64;
            int so = sw_off(rr, lc);
            size_t gA = (size_t)(bm + rr) * K + kc + lc * 8;
            size_t gB = (size_t)(bn + rr) * K + kc + lc * 8;
            cp_async16(st + so, Ah + gA);
            cp_async16(st + TILE_B + so, Al + gA);
            cp_async16(st + 2 * TILE_B + so, Bh + gB);
            cp_async16(st + 3 * TILE_B + so, Bl + gB);
        }
    };

    issue(0, 0);
    CP_COMMIT();

    int rA = mw + (lane & 15);
    int rB = nw + (lane & 15);

    for (int c = 0; c < NC; c++) {
        if (c + 1 < NC) {
            issue(c + 1, (c + 1) & 1);
            CP_COMMIT();
            CP_WAIT(1);
        } else {
            CP_WAIT(0);
        }
        __syncthreads();

        uint32_t st = sbase + (c & 1) * STAGE_B;
#pragma unroll
        for (int k16 = 0; k16 < 2; k16++) {
            int cchunk = k16 * 2 + (lane >> 4);
            uint32_t ah[2][4], al[2][4], bh[4][4], bl[4][4];
#pragma unroll
            for (int mi = 0; mi < 2; mi++)
                ldsm4(ah[mi], st + sw_off(rA + mi * 16, cchunk));
#pragma unroll
            for (int ni = 0; ni < 4; ni++)
                ldsm4(bh[ni], st + 2 * TILE_B + sw_off(rB + ni * 16, cchunk));
#pragma unroll
            for (int mi = 0; mi < 2; mi++)
#pragma unroll
                for (int ni = 0; ni < 4; ni++)
#pragma unroll
                    for (int s = 0; s < 2; s++)
                        mma16816(acc[mi][ni * 2 + s], ah[mi], bh[ni][s], bh[ni][2 + s]);
#pragma unroll
            for (int mi = 0; mi < 2; mi++)
                ldsm4(al[mi], st + TILE_B + sw_off(rA + mi * 16, cchunk));
#pragma unroll
            for (int mi = 0; mi < 2; mi++)
#pragma unroll
                for (int ni = 0; ni < 4; ni++)
#pragma unroll
                    for (int s = 0; s < 2; s++)
                        mma16816(acc[mi][ni * 2 + s], al[mi], bh[ni][s], bh[ni][2 + s]);
#pragma unroll
            for (int ni = 0; ni < 4; ni++)
                ldsm4(bl[ni], st + 3 * TILE_B + sw_off(rB + ni * 16, cchunk));
#pragma unroll
            for (int mi = 0; mi < 2; mi++)
#pragma unroll
                for (int ni = 0; ni < 4; ni++)
#pragma unroll
                    for (int s = 0; s < 2; s++)
                        mma16816(acc[mi][ni * 2 + s], ah[mi], bl[ni][s], bl[ni][2 + s]);
        }
        __syncthreads();
    }

    int gid = lane >> 2, q = lane & 3;
#pragma unroll
    for (int mi = 0; mi < 2; mi++)
#pragma unroll
        for (int j = 0; j < 8; j++) {
            int row = bm + mw + mi * 16 + gid;
            int col = bn + nw + j * 8 + q * 2;
            *(float2*)&C[(size_t)row * N + col] =
                make_float2(acc[mi][j][0], acc[mi][j][1]);
            *(float2*)&C[(size_t)(row + 8) * N + col] =
                make_float2(acc[mi][j][2], acc[mi][j][3]);
        }
}

// ---------------- RoPE: Q (scaled) + K -> bf16 hi/lo ----------------
__global__ __launch_bounds__(256) void rope_qk(const float* __restrict__ cosb,
                                               const float* __restrict__ sinb) {
    int idx = blockIdx.x * blockDim.x + threadIdx.x;
    if (idx >= T_SEQ * 20 * 64) return;
    int d = idx & 63;
    int h = (idx >> 6) % 20;
    int t = idx / (64 * 20);
    float c = cosb[t * 64 + d], sn = sinb[t * 64 + d];
    if (h < 16) {
        int base = t * QKV_DIM + (h >> 2) * 768 + (h & 3) * 128;
        float x1 = g_qkv[base + d], x2 = g_qkv[base + 64 + d];
        float o1 = (x1 * c - x2 * sn) * SCALE_ATT;
        float o2 = (x2 * c + x1 * sn) * SCALE_ATT;
        size_t o = (size_t)t * 2048 + h * 128 + d;
        __nv_bfloat16 h1 = __float2bfloat16(o1);
        __nv_bfloat16 h2 = __float2bfloat16(o2);
        g_qh[o] = h1;      g_ql[o] = __float2bfloat16(o1 - __bfloat162float(h1));
        g_qh[o + 64] = h2; g_ql[o + 64] = __float2bfloat16(o2 - __bfloat162float(h2));
    } else {
        int gi = h - 16;
        int base = t * QKV_DIM + gi * 768 + 512;
        float x1 = g_qkv[base + d], x2 = g_qkv[base + 64 + d];
        float o1 = x1 * c - x2 * sn;
        float o2 = x2 * c + x1 * sn;
        size_t o = ((size_t)gi * T_SEQ + t) * 128 + d;
        __nv_bfloat16 h1 = __float2bfloat16(o1);
        __nv_bfloat16 h2 = __float2bfloat16(o2);
        g_kh[o] = h1;      g_kl[o] = __float2bfloat16(o1 - __bfloat162float(h1));
        g_kh[o + 64] = h2; g_kl[o + 64] = __float2bfloat16(o2 - __bfloat162float(h2));
    }
}

// ---------------- V transpose/split -> [g][d][t] bf16 hi/lo ----------------
__global__ __launch_bounds__(256) void v_trans() {
    int idx = blockIdx.x * blockDim.x + threadIdx.x;
    if (idx >= NQG * 128 * T_SEQ) return;
    int t = idx & (T_SEQ - 1);
    int d = (idx >> 12) & 127;
    int gi = idx >> 19;
    float v = g_qkv[t * QKV_DIM + gi * 768 + 640 + d];
    size_t o = ((size_t)gi * 128 + d) * T_SEQ + t;
    __nv_bfloat16 hv = __float2bfloat16(v);
    g_vh[o] = hv;
    g_vl[o] = __float2bfloat16(v - __bfloat162float(hv));
}

// ---------------- mma.sync flash attention ----------------
// CTA: 128 q rows x 1 head; 8 warps, 16 rows each. Bc=64.
// smem: Qh[0:32K) Ql[32K:64K) stages{KH 16K, KL 16K, VH 16K, VL 16K} x2 = 192KB.
#define AT_Q_BYTES 32768
#define AT_STG_OFF 65536
#define AT_STG_B   65536

__global__ __launch_bounds__(256, 1) void attn_mma() {
    extern __shared__ __align__(128) char smem[];
    uint32_t sb = smem_u32(smem);
    int tid = threadIdx.x;
    int lane = tid & 31, w = tid >> 5;
    int qb = 31 - blockIdx.x;   // longest first
    int h = blockIdx.y;
    int g = h >> 2;
    int rw = w * 16;
    int ktmax = 2 * qb + 1;

    // ---- Q load (once) ----
#pragma unroll
    for (int i = 0; i < 8; i++) {
        int chunk = tid + 256 * i;          // 0..2047
        int r = chunk >> 4, cd = chunk & 15;
        size_t src = (size_t)(qb * 128 + r) * 2048 + h * 128 + cd * 8;
        uint32_t dst = sb + (cd >> 2) * 8192 + sw_off(r, cd & 3);
        cp_async16(dst, g_qh + src);
        cp_async16(dst + AT_Q_BYTES, g_ql + src);
    }

    auto issueKV = [&](int kt, int stg) {
        uint32_t st = sb + AT_STG_OFF + stg * AT_STG_B;
#pragma unroll
        for (int i = 0; i < 4; i++) {
            int chunk = tid + 256 * i;      // 0..1023
            int r = chunk >> 4, cd = chunk & 15;
            size_t src = ((size_t)g * T_SEQ + kt * 64 + r) * 128 + cd * 8;
            uint32_t dst = st + (cd >> 2) * 4096 + sw_off(r, cd & 3);
            cp_async16(dst, g_kh + src);
            cp_async16(dst + 16384, g_kl + src);
        }
#pragma unroll
        for (int i = 0; i < 4; i++) {
            int chunk = tid + 256 * i;
            int d = chunk >> 3, sc = chunk & 7;
            size_t src = ((size_t)g * 128 + d) * T_SEQ + kt * 64 + sc * 8;
            uint32_t dst = st + 32768 + (sc >> 2) * 8192 + sw_off(d, sc & 3);
            cp_async16(dst, g_vh + src);
            cp_async16(dst + 16384, g_vl + src);
        }
    };

    issueKV(0, 0);
    CP_COMMIT();

    float oacc[16][4];
#pragma unroll
    for (int i = 0; i < 16; i++)
#pragma unroll
        for (int j = 0; j < 4; j++) oacc[i][j] = 0.f;
    float mi0 = -1e30f, mi1 = -1e30f, li0 = 0.f, li1 = 0.f;

    int rK = lane & 15, cH = lane >> 4;
    int qr1 = qb * 128 + rw + (lane >> 2);

    for (int kt = 0; kt <= ktmax; kt++) {
        if (kt < ktmax) {
            issueKV(kt + 1, (kt + 1) & 1);
            CP_COMMIT();
            CP_WAIT(1);
        } else {
            CP_WAIT(0);
        }
        __syncthreads();

        uint32_t KH = sb + AT_STG_OFF + (kt & 1) * AT_STG_B;
        uint32_t KL = KH + 16384, VH = KH + 32768, VL = KH + 49152;

        // ---- S = Q K^T (3 terms) ----
        float s[8][4];
#pragma unroll
        for (int j = 0; j < 8; j++)
#pragma unroll
            for (int e = 0; e < 4; e++) s[j][e] = 0.f;

#pragma unroll
        for (int kk = 0; kk < 8; kk++) {
            int c = ((kk & 1) << 1) + cH;
            uint32_t qpan = sb + (kk >> 1) * 8192;
            uint32_t ah[4], al2[4];
            ldsm4(ah, qpan + sw_off(rw + rK, c));
            ldsm4(al2, qpan + AT_Q_BYTES + sw_off(rw + rK, c));
            uint32_t kpan = (kk >> 1) * 4096;
#pragma unroll
            for (int ni = 0; ni < 4; ni++) {
                uint32_t kh4[4], kl4[4];
                int so = sw_off(ni * 16 + rK, c);
                ldsm4(kh4, KH + kpan + so);
                ldsm4(kl4, KL + kpan + so);
#pragma unroll
                for (int ss = 0; ss < 2; ss++) {
                    mma16816(s[ni * 2 + ss], ah, kh4[ss], kh4[2 + ss]);
                    mma16816(s[ni * 2 + ss], al2, kh4[ss], kh4[2 + ss]);
                    mma16816(s[ni * 2 + ss], ah, kl4[ss], kl4[2 + ss]);
                }
            }
        }

        // ---- causal mask (diagonal CTA tiles only) ----
        if (kt >= 2 * qb) {
            int colb = kt * 64 + ((lane & 3) << 1);
#pragma unroll
            for (int j = 0; j < 8; j++) {
                int c0 = colb + j * 8;
                if (c0 > qr1)     s[j][0] = -1e30f;
                if (c0 + 1 > qr1) s[j][1] = -1e30f;
                if (c0 > qr1 + 8)     s[j][2] = -1e30f;
                if (c0 + 1 > qr1 + 8) s[j][3] = -1e30f;
            }
        }

        // ---- online softmax ----
        float mx0 = -1e30f, mx1 = -1e30f;
#pragma unroll
        for (int j = 0; j < 8; j++) {
            mx0 = fmaxf(mx0, fmaxf(s[j][0], s[j][1]));
            mx1 = fmaxf(mx1, fmaxf(s[j][2], s[j][3]));
        }
        mx0 = fmaxf(mx0, __shfl_xor_sync(0xffffffffu, mx0, 1));
        mx0 = fmaxf(mx0, __shfl_xor_sync(0xffffffffu, mx0, 2));
        mx1 = fmaxf(mx1, __shfl_xor_sync(0xffffffffu, mx1, 1));
        mx1 = fmaxf(mx1, __shfl_xor_sync(0xffffffffu, mx1, 2));
        float mn0 = fmaxf(mi0, mx0), mn1 = fmaxf(mi1, mx1);
        float a0 = __expf(mi0 - mn0), a1 = __expf(mi1 - mn1);
        mi0 = mn0; mi1 = mn1;
        float sum0 = 0.f, sum1 = 0.f;
#pragma unroll
        for (int j = 0; j < 8; j++) {
            s[j][0] = __expf(s[j][0] - mn0);
            s[j][1] = __expf(s[j][1] - mn0);
            s[j][2] = __expf(s[j][2] - mn1);
            s[j][3] = __expf(s[j][3] - mn1);
            sum0 += s[j][0] + s[j][1];
            sum1 += s[j][2] + s[j][3];
        }
        sum0 += __shfl_xor_sync(0xffffffffu, sum0, 1);
        sum0 += __shfl_xor_sync(0xffffffffu, sum0, 2);
        sum1 += __shfl_xor_sync(0xffffffffu, sum1, 1);
        sum1 += __shfl_xor_sync(0xffffffffu, sum1, 2);
        li0 = li0 * a0 + sum0;
        li1 = li1 * a1 + sum1;
#pragma unroll
        for (int ni = 0; ni < 16; ni++) {
            oacc[ni][0] *= a0; oacc[ni][1] *= a0;
            oacc[ni][2] *= a1; oacc[ni][3] *= a1;
        }

        // ---- O += P V (3 terms), P from registers ----
#pragma unroll
        for (int kk2 = 0; kk2 < 4; kk2++) {
            uint32_t hp[4], lp[4];
            {
                float* p0 = s[2 * kk2];
                float* p1 = s[2 * kk2 + 1];
                hp[0] = pack2bf(p0[0], p0[1]);
                hp[1] = pack2bf(p0[2], p0[3]);
                hp[2] = pack2bf(p1[0], p1[1]);
                hp[3] = pack2bf(p1[2], p1[3]);
                lp[0] = pack2bf(p0[0] - lo_f(hp[0]), p0[1] - hi_f(hp[0]));
                lp[1] = pack2bf(p0[2] - lo_f(hp[1]), p0[3] - hi_f(hp[1]));
                lp[2] = pack2bf(p1[0] - lo_f(hp[2]), p1[1] - hi_f(hp[2]));
                lp[3] = pack2bf(p1[2] - lo_f(hp[3]), p1[3] - hi_f(hp[3]));
            }
            int c = ((kk2 & 1) << 1) + cH;
            uint32_t vpan = (kk2 >> 1) * 8192;
#pragma unroll
            for (int ni = 0; ni < 8; ni++) {
                uint32_t vh4[4], vl4[4];
                int so = sw_off(ni * 16 + rK, c);
                ldsm4(vh4, VH + vpan + so);
                ldsm4(vl4, VL + vpan + so);
#pragma unroll
                for (int ss = 0; ss < 2; ss++) {
                    mma16816(oacc[ni * 2 + ss], hp, vh4[ss], vh4[2 + ss]);
                    mma16816(oacc[ni * 2 + ss], lp, vh4[ss], vh4[2 + ss]);
                    mma16816(oacc[ni * 2 + ss], hp, vl4[ss], vl4[2 + ss]);
                }
            }
        }
        __syncthreads();
    }

    // ---- epilogue: O/l -> bf16 hi/lo ----
    float inv0 = 1.f / li0, inv1 = 1.f / li1;
    size_t row1 = (size_t)qr1 * 2048 + h * 128;
    size_t row2 = row1 + (size_t)8 * 2048;
#pragma unroll
    for (int ni = 0; ni < 16; ni++) {
        int colo = ni * 8 + ((lane & 3) << 1);
        float f0 = oacc[ni][0] * inv0, f1 = oacc[ni][1] * inv0;
        float f2 = oacc[ni][2] * inv1, f3 = oacc[ni][3] * inv1;
        uint32_t h0 = pack2bf(f0, f1);
        uint32_t l0 = pack2bf(f0 - lo_f(h0), f1 - hi_f(h0));
        uint32_t h1 = pack2bf(f2, f3);
        uint32_t l1 = pack2bf(f2 - lo_f(h1), f3 - hi_f(h1));
        *(uint32_t*)&g_yh[row1 + colo] = h0;
        *(uint32_t*)&g_yl[row1 + colo] = l0;
        *(uint32_t*)&g_yh[row2 + colo] = h1;
        *(uint32_t*)&g_yl[row2 + colo] = l1;
    }
}

// ---------------- launch ----------------
extern "C" void kernel_launch(void* const* d_in, const int* in_sizes, int n_in,
                              void* d_out, int out_size) {
    const float* x    = (const float*)d_in[0];
    const float* cosb = (const float*)d_in[1];
    const float* sinb = (const float*)d_in[2];
    const float* Wa   = (const float*)d_in[3];
    const float* Wp   = (const float*)d_in[4];
    float* out = (float*)d_out;

    float* qkv_p;
    cudaGetSymbolAddress((void**)&qkv_p, g_qkv);
    __nv_bfloat16 *xh, *xl, *wah, *wal, *wph, *wpl, *yh, *yl;
    cudaGetSymbolAddress((void**)&xh, g_xh);   cudaGetSymbolAddress((void**)&xl, g_xl);
    cudaGetSymbolAddress((void**)&wah, g_wah); cudaGetSymbolAddress((void**)&wal, g_wal);
    cudaGetSymbolAddress((void**)&wph, g_wph); cudaGetSymbolAddress((void**)&wpl, g_wpl);
    cudaGetSymbolAddress((void**)&yh, g_yh);   cudaGetSymbolAddress((void**)&yl, g_yl);

    const int gemm_smem = 2 * STAGE_B;  // 64 KB
    cudaFuncSetAttribute(gemm_mma, cudaFuncAttributeMaxDynamicSharedMemorySize, gemm_smem);
    const int attn_smem = AT_STG_OFF + 2 * AT_STG_B;  // 192 KB
    cudaFuncSetAttribute(attn_mma, cudaFuncAttributeMaxDynamicSharedMemorySize, attn_smem);

    // 1) split inputs
    split_bf16<<<(T_SEQ * C_DIM + 255) / 256, 256>>>(x, xh, xl, T_SEQ * C_DIM);
    split_bf16<<<(QKV_DIM * C_DIM + 255) / 256, 256>>>(Wa, wah, wal, QKV_DIM * C_DIM);

    // 2) qkv = x @ W_attn^T
    gemm_mma<<<dim3(QKV_DIM / 128, T_SEQ / 128), 256, gemm_smem>>>(
        xh, xl, wah, wal, qkv_p, QKV_DIM, C_DIM);

    // 3) rope + split + v transpose
    rope_qk<<<(T_SEQ * 20 * 64) / 256, 256>>>(cosb, sinb);
    v_trans<<<(NQG * 128 * T_SEQ) / 256, 256>>>();

    // 4) attention (writes yh/yl directly)
    attn_mma<<<dim3(32, NHEAD), 256, attn_smem>>>();

    // 5) out = y @ W_proj^T
    split_bf16<<<(C_DIM * C_DIM + 255) / 256, 256>>>(Wp, wph, wpl, C_DIM * C_DIM);
    gemm_mma<<<dim3(C_DIM / 128, T_SEQ / 128), 256, gemm_smem>>>(
        yh, yl, wph, wpl, out, C_DIM, C_DIM);
}

// round 5
// speedup vs baseline: 2.9185x; 1.0480x over previous
#include <cuda_runtime.h>
#include <cuda_bf16.h>
#include <math.h>
#include <stdint.h>

#define T_SEQ 4096
#define C_DIM 2048
#define NHEAD 16
#define HS 128
#define NQG 4
#define QKV_DIM 3072
#define SCALE_ATT 0.08838834764831845f       // 1/sqrt(128)
#define SCALE_LOG2 0.1275071050830161f       // SCALE_ATT * log2(e)

// ---------------- scratch ----------------
__device__ float g_qkv[T_SEQ * QKV_DIM];

__device__ __nv_bfloat16 g_xh[T_SEQ * C_DIM];
__device__ __nv_bfloat16 g_xl[T_SEQ * C_DIM];
__device__ __nv_bfloat16 g_wah[QKV_DIM * C_DIM];
__device__ __nv_bfloat16 g_wal[QKV_DIM * C_DIM];
__device__ __nv_bfloat16 g_wph[C_DIM * C_DIM];
__device__ __nv_bfloat16 g_wpl[C_DIM * C_DIM];

// attention operands (bf16 hi/lo)
__device__ __nv_bfloat16 g_qh[T_SEQ * NHEAD * HS];   // [t][h*128+d], scaled by SCALE_LOG2
__device__ __nv_bfloat16 g_ql[T_SEQ * NHEAD * HS];
__device__ __nv_bfloat16 g_kh[NQG * T_SEQ * HS];     // [g][t][d]
__device__ __nv_bfloat16 g_kl[NQG * T_SEQ * HS];
__device__ __nv_bfloat16 g_vh[NQG * HS * T_SEQ];     // [g][d][t]  (d-major)
__device__ __nv_bfloat16 g_vl[NQG * HS * T_SEQ];
__device__ __nv_bfloat16 g_yh[T_SEQ * C_DIM];
__device__ __nv_bfloat16 g_yl[T_SEQ * C_DIM];

// ---------------- PTX helpers ----------------
__device__ __forceinline__ uint32_t smem_u32(const void* p) {
    uint32_t a;
    asm("{ .reg .u64 t; cvta.to.shared.u64 t, %1; cvt.u32.u64 %0, t; }"
        : "=r"(a) : "l"(p));
    return a;
}
__device__ __forceinline__ void cp_async16(uint32_t s, const void* g) {
    asm volatile("cp.async.cg.shared.global [%0], [%1], 16;" :: "r"(s), "l"(g));
}
#define CP_COMMIT() asm volatile("cp.async.commit_group;" ::: "memory")
#define CP_WAIT(n)  asm volatile("cp.async.wait_group %0;" :: "n"(n) : "memory")

__device__ __forceinline__ void ldsm4(uint32_t* f, uint32_t a) {
    asm volatile("ldmatrix.sync.aligned.m8n8.x4.shared.b16 {%0,%1,%2,%3}, [%4];"
                 : "=r"(f[0]), "=r"(f[1]), "=r"(f[2]), "=r"(f[3]) : "r"(a));
}
__device__ __forceinline__ void mma16816(float* d, const uint32_t* a,
                                         uint32_t b0, uint32_t b1) {
    asm volatile(
        "mma.sync.aligned.m16n8k16.row.col.f32.bf16.bf16.f32 "
        "{%0,%1,%2,%3}, {%4,%5,%6,%7}, {%8,%9}, {%0,%1,%2,%3};"
        : "+f"(d[0]), "+f"(d[1]), "+f"(d[2]), "+f"(d[3])
        : "r"(a[0]), "r"(a[1]), "r"(a[2]), "r"(a[3]), "r"(b0), "r"(b1));
}
__device__ __forceinline__ uint32_t pack2bf(float lo, float hi) {
    uint32_t r;
    asm("cvt.rn.bf16x2.f32 %0, %1, %2;" : "=r"(r) : "f"(hi), "f"(lo));
    return r;
}
__device__ __forceinline__ float lo_f(uint32_t u) { return __uint_as_float(u << 16); }
__device__ __forceinline__ float hi_f(uint32_t u) { return __uint_as_float(u & 0xffff0000u); }

// 64B-row XOR swizzle (rows of 32 bf16, 4x16B chunks) — conflict-free ldmatrix phases
__device__ __forceinline__ int sw_off(int r, int c) {
    return r * 64 + ((c ^ ((r >> 1) & 3)) << 4);
}

// ---------------- split fp32 -> (hi, lo) bf16 ----------------
__global__ __launch_bounds__(256) void split_bf16(const float* __restrict__ s,
                                                  __nv_bfloat16* __restrict__ h,
                                                  __nv_bfloat16* __restrict__ l, int n) {
    int i = blockIdx.x * 256 + threadIdx.x;
    if (i < n) {
        float x = s[i];
        __nv_bfloat16 hb = __float2bfloat16(x);
        h[i] = hb;
        l[i] = __float2bfloat16(x - __bfloat162float(hb));
    }
}

// ---------------- mma.sync split-bf16 GEMM, 2 CTAs/SM ----------------
#define BK 32
#define TILE_B 8192
#define STAGE_B (4 * TILE_B)

__global__ __launch_bounds__(256, 2) void gemm_mma(const __nv_bfloat16* __restrict__ Ah,
                                                   const __nv_bfloat16* __restrict__ Al,
                                                   const __nv_bfloat16* __restrict__ Bh,
                                                   const __nv_bfloat16* __restrict__ Bl,
                                                   float* __restrict__ C, int N, int K) {
    extern __shared__ __align__(128) char smem[];
    int tid = threadIdx.x;
    int lane = tid & 31, w = tid >> 5;
    int bm = blockIdx.y * 128, bn = blockIdx.x * 128;
    int mw = (w & 3) * 32, nw = (w >> 2) * 64;
    uint32_t sbase = smem_u32(smem);

    float acc[2][8][4];
#pragma unroll
    for (int i = 0; i < 2; i++)
#pragma unroll
        for (int j = 0; j < 8; j++)
#pragma unroll
            for (int q = 0; q < 4; q++) acc[i][j][q] = 0.f;

    const int NC = K / BK;
    int lr = tid >> 2, lc = tid & 3;

    auto issue = [&](int c, int buf) {
        uint32_t st = sbase + buf * STAGE_B;
        int kc = c * BK;
#pragma unroll
        for (int half = 0; half < 2; half++) {
            int rr = lr + half * 64;
            int so = sw_off(rr, lc);
            size_t gA = (size_t)(bm + rr) * K + kc + lc * 8;
            size_t gB = (size_t)(bn + rr) * K + kc + lc * 8;
            cp_async16(st + so, Ah + gA);
            cp_async16(st + TILE_B + so, Al + gA);
            cp_async16(st + 2 * TILE_B + so, Bh + gB);
            cp_async16(st + 3 * TILE_B + so, Bl + gB);
        }
    };

    issue(0, 0);
    CP_COMMIT();

    int rA = mw + (lane & 15);
    int rB = nw + (lane & 15);

    for (int c = 0; c < NC; c++) {
        if (c + 1 < NC) {
            issue(c + 1, (c + 1) & 1);
            CP_COMMIT();
            CP_WAIT(1);
        } else {
            CP_WAIT(0);
        }
        __syncthreads();

        uint32_t st = sbase + (c & 1) * STAGE_B;
#pragma unroll
        for (int k16 = 0; k16 < 2; k16++) {
            int cchunk = k16 * 2 + (lane >> 4);
            uint32_t ah[2][4], al[2][4];
            ldsm4(ah[0], st + sw_off(rA, cchunk));
            ldsm4(ah[1], st + sw_off(rA + 16, cchunk));
            ldsm4(al[0], st + TILE_B + sw_off(rA, cchunk));
            ldsm4(al[1], st + TILE_B + sw_off(rA + 16, cchunk));
#pragma unroll
            for (int ni = 0; ni < 4; ni++) {
                uint32_t bh[4], bl[4];
                int so = sw_off(rB + ni * 16, cchunk);
                ldsm4(bh, st + 2 * TILE_B + so);
#pragma unroll
                for (int s = 0; s < 2; s++) {
                    mma16816(acc[0][ni * 2 + s], ah[0], bh[s], bh[2 + s]);
                    mma16816(acc[1][ni * 2 + s], ah[1], bh[s], bh[2 + s]);
                    mma16816(acc[0][ni * 2 + s], al[0], bh[s], bh[2 + s]);
                    mma16816(acc[1][ni * 2 + s], al[1], bh[s], bh[2 + s]);
                }
                ldsm4(bl, st + 3 * TILE_B + so);
#pragma unroll
                for (int s = 0; s < 2; s++) {
                    mma16816(acc[0][ni * 2 + s], ah[0], bl[s], bl[2 + s]);
                    mma16816(acc[1][ni * 2 + s], ah[1], bl[s], bl[2 + s]);
                }
            }
        }
        __syncthreads();
    }

    int gid = lane >> 2, q = lane & 3;
#pragma unroll
    for (int mi = 0; mi < 2; mi++)
#pragma unroll
        for (int j = 0; j < 8; j++) {
            int row = bm + mw + mi * 16 + gid;
            int col = bn + nw + j * 8 + q * 2;
            *(float2*)&C[(size_t)row * N + col] =
                make_float2(acc[mi][j][0], acc[mi][j][1]);
            *(float2*)&C[(size_t)(row + 8) * N + col] =
                make_float2(acc[mi][j][2], acc[mi][j][3]);
        }
}

// ---------------- RoPE: Q (scaled by SCALE_LOG2) + K -> bf16 hi/lo ----------------
__global__ __launch_bounds__(256) void rope_qk(const float* __restrict__ cosb,
                                               const float* __restrict__ sinb) {
    int idx = blockIdx.x * blockDim.x + threadIdx.x;
    if (idx >= T_SEQ * 20 * 64) return;
    int d = idx & 63;
    int h = (idx >> 6) % 20;
    int t = idx / (64 * 20);
    float c = cosb[t * 64 + d], sn = sinb[t * 64 + d];
    if (h < 16) {
        int base = t * QKV_DIM + (h >> 2) * 768 + (h & 3) * 128;
        float x1 = g_qkv[base + d], x2 = g_qkv[base + 64 + d];
        float o1 = (x1 * c - x2 * sn) * SCALE_LOG2;
        float o2 = (x2 * c + x1 * sn) * SCALE_LOG2;
        size_t o = (size_t)t * 2048 + h * 128 + d;
        __nv_bfloat16 h1 = __float2bfloat16(o1);
        __nv_bfloat16 h2 = __float2bfloat16(o2);
        g_qh[o] = h1;      g_ql[o] = __float2bfloat16(o1 - __bfloat162float(h1));
        g_qh[o + 64] = h2; g_ql[o + 64] = __float2bfloat16(o2 - __bfloat162float(h2));
    } else {
        int gi = h - 16;
        int base = t * QKV_DIM + gi * 768 + 512;
        float x1 = g_qkv[base + d], x2 = g_qkv[base + 64 + d];
        float o1 = x1 * c - x2 * sn;
        float o2 = x2 * c + x1 * sn;
        size_t o = ((size_t)gi * T_SEQ + t) * 128 + d;
        __nv_bfloat16 h1 = __float2bfloat16(o1);
        __nv_bfloat16 h2 = __float2bfloat16(o2);
        g_kh[o] = h1;      g_kl[o] = __float2bfloat16(o1 - __bfloat162float(h1));
        g_kh[o + 64] = h2; g_kl[o + 64] = __float2bfloat16(o2 - __bfloat162float(h2));
    }
}

// ---------------- V transpose/split -> [g][d][t] bf16 hi/lo ----------------
__global__ __launch_bounds__(256) void v_trans() {
    int idx = blockIdx.x * blockDim.x + threadIdx.x;
    if (idx >= NQG * 128 * T_SEQ) return;
    int t = idx & (T_SEQ - 1);
    int d = (idx >> 12) & 127;
    int gi = idx >> 19;
    float v = g_qkv[t * QKV_DIM + gi * 768 + 640 + d];
    size_t o = ((size_t)gi * 128 + d) * T_SEQ + t;
    __nv_bfloat16 hv = __float2bfloat16(v);
    g_vh[o] = hv;
    g_vl[o] = __float2bfloat16(v - __bfloat162float(hv));
}

// ---------------- mma.sync flash attention ----------------
#define AT_Q_BYTES 32768
#define AT_STG_OFF 65536
#define AT_STG_B   65536

__global__ __launch_bounds__(256, 1) void attn_mma() {
    extern __shared__ __align__(128) char smem[];
    uint32_t sb = smem_u32(smem);
    int tid = threadIdx.x;
    int lane = tid & 31, w = tid >> 5;
    int qb = 31 - blockIdx.x;   // longest first
    int h = blockIdx.y;
    int g = h >> 2;
    int rw = w * 16;
    int ktmax = 2 * qb + 1;

    // ---- Q load (once) ----
#pragma unroll
    for (int i = 0; i < 8; i++) {
        int chunk = tid + 256 * i;
        int r = chunk >> 4, cd = chunk & 15;
        size_t src = (size_t)(qb * 128 + r) * 2048 + h * 128 + cd * 8;
        uint32_t dst = sb + (cd >> 2) * 8192 + sw_off(r, cd & 3);
        cp_async16(dst, g_qh + src);
        cp_async16(dst + AT_Q_BYTES, g_ql + src);
    }

    auto issueKV = [&](int kt, int stg) {
        uint32_t st = sb + AT_STG_OFF + stg * AT_STG_B;
#pragma unroll
        for (int i = 0; i < 4; i++) {
            int chunk = tid + 256 * i;
            int r = chunk >> 4, cd = chunk & 15;
            size_t src = ((size_t)g * T_SEQ + kt * 64 + r) * 128 + cd * 8;
            uint32_t dst = st + (cd >> 2) * 4096 + sw_off(r, cd & 3);
            cp_async16(dst, g_kh + src);
            cp_async16(dst + 16384, g_kl + src);
        }
#pragma unroll
        for (int i = 0; i < 4; i++) {
            int chunk = tid + 256 * i;
            int d = chunk >> 3, sc = chunk & 7;
            size_t src = ((size_t)g * 128 + d) * T_SEQ + kt * 64 + sc * 8;
            uint32_t dst = st + 32768 + (sc >> 2) * 8192 + sw_off(d, sc & 3);
            cp_async16(dst, g_vh + src);
            cp_async16(dst + 16384, g_vl + src);
        }
    };

    issueKV(0, 0);
    CP_COMMIT();

    float oacc[16][4];
#pragma unroll
    for (int i = 0; i < 16; i++)
#pragma unroll
        for (int j = 0; j < 4; j++) oacc[i][j] = 0.f;
    float mi0 = -1e30f, mi1 = -1e30f, li0 = 0.f, li1 = 0.f;

    int rK = lane & 15, cH = lane >> 4;
    int qr1 = qb * 128 + rw + (lane >> 2);

    for (int kt = 0; kt <= ktmax; kt++) {
        if (kt < ktmax) {
            issueKV(kt + 1, (kt + 1) & 1);
            CP_COMMIT();
            CP_WAIT(1);
        } else {
            CP_WAIT(0);
        }
        __syncthreads();

        uint32_t KH = sb + AT_STG_OFF + (kt & 1) * AT_STG_B;
        uint32_t KL = KH + 16384, VH = KH + 32768, VL = KH + 49152;

        // ---- S = Q K^T (3 terms, log2-scaled) ----
        float s[8][4];
#pragma unroll
        for (int j = 0; j < 8; j++)
#pragma unroll
            for (int e = 0; e < 4; e++) s[j][e] = 0.f;

#pragma unroll
        for (int kk = 0; kk < 8; kk++) {
            int c = ((kk & 1) << 1) + cH;
            uint32_t qpan = sb + (kk >> 1) * 8192;
            uint32_t ah[4], al2[4];
            ldsm4(ah, qpan + sw_off(rw + rK, c));
            ldsm4(al2, qpan + AT_Q_BYTES + sw_off(rw + rK, c));
            uint32_t kpan = (kk >> 1) * 4096;
#pragma unroll
            for (int ni = 0; ni < 4; ni++) {
                uint32_t kh4[4], kl4[4];
                int so = sw_off(ni * 16 + rK, c);
                ldsm4(kh4, KH + kpan + so);
#pragma unroll
                for (int ss = 0; ss < 2; ss++) {
                    mma16816(s[ni * 2 + ss], ah, kh4[ss], kh4[2 + ss]);
                    mma16816(s[ni * 2 + ss], al2, kh4[ss], kh4[2 + ss]);
                }
                ldsm4(kl4, KL + kpan + so);
#pragma unroll
                for (int ss = 0; ss < 2; ss++)
                    mma16816(s[ni * 2 + ss], ah, kl4[ss], kl4[2 + ss]);
            }
        }

        // ---- causal mask (diagonal CTA tiles only) ----
        if (kt >= 2 * qb) {
            int colb = kt * 64 + ((lane & 3) << 1);
#pragma unroll
            for (int j = 0; j < 8; j++) {
                int c0 = colb + j * 8;
                if (c0 > qr1)     s[j][0] = -1e30f;
                if (c0 + 1 > qr1) s[j][1] = -1e30f;
                if (c0 > qr1 + 8)     s[j][2] = -1e30f;
                if (c0 + 1 > qr1 + 8) s[j][3] = -1e30f;
            }
        }

        // ---- online softmax (base-2) ----
        float mx0 = -1e30f, mx1 = -1e30f;
#pragma unroll
        for (int j = 0; j < 8; j++) {
            mx0 = fmaxf(mx0, fmaxf(s[j][0], s[j][1]));
            mx1 = fmaxf(mx1, fmaxf(s[j][2], s[j][3]));
        }
        mx0 = fmaxf(mx0, __shfl_xor_sync(0xffffffffu, mx0, 1));
        mx0 = fmaxf(mx0, __shfl_xor_sync(0xffffffffu, mx0, 2));
        mx1 = fmaxf(mx1, __shfl_xor_sync(0xffffffffu, mx1, 1));
        mx1 = fmaxf(mx1, __shfl_xor_sync(0xffffffffu, mx1, 2));
        float mn0 = fmaxf(mi0, mx0), mn1 = fmaxf(mi1, mx1);
        float a0 = exp2f(mi0 - mn0), a1 = exp2f(mi1 - mn1);
        mi0 = mn0; mi1 = mn1;
        float sum0 = 0.f, sum1 = 0.f;
#pragma unroll
        for (int j = 0; j < 8; j++) {
            s[j][0] = exp2f(s[j][0] - mn0);
            s[j][1] = exp2f(s[j][1] - mn0);
            s[j][2] = exp2f(s[j][2] - mn1);
            s[j][3] = exp2f(s[j][3] - mn1);
            sum0 += s[j][0] + s[j][1];
            sum1 += s[j][2] + s[j][3];
        }
        sum0 += __shfl_xor_sync(0xffffffffu, sum0, 1);
        sum0 += __shfl_xor_sync(0xffffffffu, sum0, 2);
        sum1 += __shfl_xor_sync(0xffffffffu, sum1, 1);
        sum1 += __shfl_xor_sync(0xffffffffu, sum1, 2);
        li0 = li0 * a0 + sum0;
        li1 = li1 * a1 + sum1;
        if (a0 != 1.f || a1 != 1.f) {
#pragma unroll
            for (int ni = 0; ni < 16; ni++) {
                oacc[ni][0] *= a0; oacc[ni][1] *= a0;
                oacc[ni][2] *= a1; oacc[ni][3] *= a1;
            }
        }

        // ---- O += P V (3 terms), P from registers ----
#pragma unroll
        for (int kk2 = 0; kk2 < 4; kk2++) {
            uint32_t hp[4], lp[4];
            {
                float* p0 = s[2 * kk2];
                float* p1 = s[2 * kk2 + 1];
                hp[0] = pack2bf(p0[0], p0[1]);
                hp[1] = pack2bf(p0[2], p0[3]);
                hp[2] = pack2bf(p1[0], p1[1]);
                hp[3] = pack2bf(p1[2], p1[3]);
                lp[0] = pack2bf(p0[0] - lo_f(hp[0]), p0[1] - hi_f(hp[0]));
                lp[1] = pack2bf(p0[2] - lo_f(hp[1]), p0[3] - hi_f(hp[1]));
                lp[2] = pack2bf(p1[0] - lo_f(hp[2]), p1[1] - hi_f(hp[2]));
                lp[3] = pack2bf(p1[2] - lo_f(hp[3]), p1[3] - hi_f(hp[3]));
            }
            int c = ((kk2 & 1) << 1) + cH;
            uint32_t vpan = (kk2 >> 1) * 8192;
#pragma unroll
            for (int ni = 0; ni < 8; ni++) {
                uint32_t vh4[4], vl4[4];
                int so = sw_off(ni * 16 + rK, c);
                ldsm4(vh4, VH + vpan + so);
#pragma unroll
                for (int ss = 0; ss < 2; ss++) {
                    mma16816(oacc[ni * 2 + ss], hp, vh4[ss], vh4[2 + ss]);
                    mma16816(oacc[ni * 2 + ss], lp, vh4[ss], vh4[2 + ss]);
                }
                ldsm4(vl4, VL + vpan + so);
#pragma unroll
                for (int ss = 0; ss < 2; ss++)
                    mma16816(oacc[ni * 2 + ss], hp, vl4[ss], vl4[2 + ss]);
            }
        }
        __syncthreads();
    }

    // ---- epilogue: O/l -> bf16 hi/lo ----
    float inv0 = 1.f / li0, inv1 = 1.f / li1;
    size_t row1 = (size_t)qr1 * 2048 + h * 128;
    size_t row2 = row1 + (size_t)8 * 2048;
#pragma unroll
    for (int ni = 0; ni < 16; ni++) {
        int colo = ni * 8 + ((lane & 3) << 1);
        float f0 = oacc[ni][0] * inv0, f1 = oacc[ni][1] * inv0;
        float f2 = oacc[ni][2] * inv1, f3 = oacc[ni][3] * inv1;
        uint32_t h0 = pack2bf(f0, f1);
        uint32_t l0 = pack2bf(f0 - lo_f(h0), f1 - hi_f(h0));
        uint32_t h1 = pack2bf(f2, f3);
        uint32_t l1 = pack2bf(f2 - lo_f(h1), f3 - hi_f(h1));
        *(uint32_t*)&g_yh[row1 + colo] = h0;
        *(uint32_t*)&g_yl[row1 + colo] = l0;
        *(uint32_t*)&g_yh[row2 + colo] = h1;
        *(uint32_t*)&g_yl[row2 + colo] = l1;
    }
}

// ---------------- launch ----------------
extern "C" void kernel_launch(void* const* d_in, const int* in_sizes, int n_in,
                              void* d_out, int out_size) {
    const float* x    = (const float*)d_in[0];
    const float* cosb = (const float*)d_in[1];
    const float* sinb = (const float*)d_in[2];
    const float* Wa   = (const float*)d_in[3];
    const float* Wp   = (const float*)d_in[4];
    float* out = (float*)d_out;

    float* qkv_p;
    cudaGetSymbolAddress((void**)&qkv_p, g_qkv);
    __nv_bfloat16 *xh, *xl, *wah, *wal, *wph, *wpl, *yh, *yl;
    cudaGetSymbolAddress((void**)&xh, g_xh);   cudaGetSymbolAddress((void**)&xl, g_xl);
    cudaGetSymbolAddress((void**)&wah, g_wah); cudaGetSymbolAddress((void**)&wal, g_wal);
    cudaGetSymbolAddress((void**)&wph, g_wph); cudaGetSymbolAddress((void**)&wpl, g_wpl);
    cudaGetSymbolAddress((void**)&yh, g_yh);   cudaGetSymbolAddress((void**)&yl, g_yl);

    const int gemm_smem = 2 * STAGE_B;  // 64 KB
    cudaFuncSetAttribute(gemm_mma, cudaFuncAttributeMaxDynamicSharedMemorySize, gemm_smem);
    const int attn_smem = AT_STG_OFF + 2 * AT_STG_B;  // 192 KB
    cudaFuncSetAttribute(attn_mma, cudaFuncAttributeMaxDynamicSharedMemorySize, attn_smem);

    // 1) split inputs
    split_bf16<<<(T_SEQ * C_DIM + 255) / 256, 256>>>(x, xh, xl, T_SEQ * C_DIM);
    split_bf16<<<(QKV_DIM * C_DIM + 255) / 256, 256>>>(Wa, wah, wal, QKV_DIM * C_DIM);

    // 2) qkv = x @ W_attn^T
    gemm_mma<<<dim3(QKV_DIM / 128, T_SEQ / 128), 256, gemm_smem>>>(
        xh, xl, wah, wal, qkv_p, QKV_DIM, C_DIM);

    // 3) rope + split + v transpose
    rope_qk<<<(T_SEQ * 20 * 64) / 256, 256>>>(cosb, sinb);
    v_trans<<<(NQG * 128 * T_SEQ) / 256, 256>>>();

    // 4) attention (writes yh/yl directly)
    attn_mma<<<dim3(32, NHEAD), 256, attn_smem>>>();

    // 5) out = y @ W_proj^T
    split_bf16<<<(C_DIM * C_DIM + 255) / 256, 256>>>(Wp, wph, wpl, C_DIM * C_DIM);
    gemm_mma<<<dim3(C_DIM / 128, T_SEQ / 128), 256, gemm_smem>>>(
        yh, yl, wph, wpl, out, C_DIM, C_DIM);
}

// round 6
// speedup vs baseline: 4.3063x; 1.4755x over previous
#include <cuda_runtime.h>
#include <cuda_fp16.h>
#include <math.h>
#include <stdint.h>

#define T_SEQ 4096
#define C_DIM 2048
#define NHEAD 16
#define HS 128
#define NQG 4
#define QKV_DIM 3072
#define SCALE_LOG2 0.1275071050830161f       // (1/sqrt(128)) * log2(e)

// ---------------- scratch ----------------
__device__ float g_qkv[T_SEQ * QKV_DIM];

__device__ __half g_xh[T_SEQ * C_DIM];
__device__ __half g_xl[T_SEQ * C_DIM];
__device__ __half g_wa[QKV_DIM * C_DIM];
__device__ __half g_wp[C_DIM * C_DIM];

__device__ __half g_qh[T_SEQ * NHEAD * HS];   // [t][h*128+d], scaled by SCALE_LOG2
__device__ __half g_ql[T_SEQ * NHEAD * HS];
__device__ __half g_kh[NQG * T_SEQ * HS];     // [g][t][d]
__device__ __half g_vh[NQG * HS * T_SEQ];     // [g][d][t]  (d-major)
__device__ __half g_yh[T_SEQ * C_DIM];
__device__ __half g_yl[T_SEQ * C_DIM];

// ---------------- PTX helpers ----------------
__device__ __forceinline__ uint32_t smem_u32(const void* p) {
    uint32_t a;
    asm("{ .reg .u64 t; cvta.to.shared.u64 t, %1; cvt.u32.u64 %0, t; }"
        : "=r"(a) : "l"(p));
    return a;
}
__device__ __forceinline__ void cp_async16(uint32_t s, const void* g) {
    asm volatile("cp.async.cg.shared.global [%0], [%1], 16;" :: "r"(s), "l"(g));
}
#define CP_COMMIT() asm volatile("cp.async.commit_group;" ::: "memory")
#define CP_WAIT(n)  asm volatile("cp.async.wait_group %0;" :: "n"(n) : "memory")

__device__ __forceinline__ void ldsm4(uint32_t* f, uint32_t a) {
    asm volatile("ldmatrix.sync.aligned.m8n8.x4.shared.b16 {%0,%1,%2,%3}, [%4];"
                 : "=r"(f[0]), "=r"(f[1]), "=r"(f[2]), "=r"(f[3]) : "r"(a));
}
__device__ __forceinline__ void mma16816(float* d, const uint32_t* a,
                                         uint32_t b0, uint32_t b1) {
    asm volatile(
        "mma.sync.aligned.m16n8k16.row.col.f32.f16.f16.f32 "
        "{%0,%1,%2,%3}, {%4,%5,%6,%7}, {%8,%9}, {%0,%1,%2,%3};"
        : "+f"(d[0]), "+f"(d[1]), "+f"(d[2]), "+f"(d[3])
        : "r"(a[0]), "r"(a[1]), "r"(a[2]), "r"(a[3]), "r"(b0), "r"(b1));
}
// pack two f32 -> f16x2 (low half = first arg)
__device__ __forceinline__ uint32_t pack2h(float lo, float hi) {
    uint32_t r;
    asm("cvt.rn.f16x2.f32 %0, %1, %2;" : "=r"(r) : "f"(hi), "f"(lo));
    return r;
}
__device__ __forceinline__ float lo_h(uint32_t u) {
    return __half2float(__ushort_as_half((unsigned short)(u & 0xffffu)));
}
__device__ __forceinline__ float hi_h(uint32_t u) {
    return __half2float(__ushort_as_half((unsigned short)(u >> 16)));
}

// 64B-row XOR swizzle (rows of 32 halves, 4x16B chunks) — conflict-free ldmatrix phases
__device__ __forceinline__ int sw_off(int r, int c) {
    return r * 64 + ((c ^ ((r >> 1) & 3)) << 4);
}

// ---------------- split fp32 -> (hi, lo) fp16, vectorized x4 ----------------
__global__ __launch_bounds__(256) void split_fp16(const float4* __restrict__ s,
                                                  uint32_t* __restrict__ h,
                                                  uint32_t* __restrict__ l, int n4) {
    int i = blockIdx.x * 256 + threadIdx.x;
    if (i < n4) {
        float4 v = s[i];
        uint32_t h0 = pack2h(v.x, v.y), h1 = pack2h(v.z, v.w);
        uint32_t l0 = pack2h(v.x - lo_h(h0), v.y - hi_h(h0));
        uint32_t l1 = pack2h(v.z - lo_h(h1), v.w - hi_h(h1));
        h[2 * i] = h0;     h[2 * i + 1] = h1;
        l[2 * i] = l0;     l[2 * i + 1] = l1;
    }
}
// fp32 -> fp16 single (weights), vectorized x4
__global__ __launch_bounds__(256) void conv_fp16(const float4* __restrict__ s,
                                                 uint32_t* __restrict__ h, int n4) {
    int i = blockIdx.x * 256 + threadIdx.x;
    if (i < n4) {
        float4 v = s[i];
        h[2 * i]     = pack2h(v.x, v.y);
        h[2 * i + 1] = pack2h(v.z, v.w);
    }
}

// ---------------- mma.sync 2-term fp16 GEMM: C = (Ah+Al) * B^T ----------------
// CTA 128x128, BK=32, 8 warps (4Mx2N), 2 CTAs/SM, stage = Ah+Al+B = 24KB.
#define BK 32
#define TILE_B 8192
#define STAGE_B (3 * TILE_B)

__global__ __launch_bounds__(256, 2) void gemm_mma(const __half* __restrict__ Ah,
                                                   const __half* __restrict__ Al,
                                                   const __half* __restrict__ B,
                                                   float* __restrict__ C, int N, int K) {
    extern __shared__ __align__(128) char smem[];
    int tid = threadIdx.x;
    int lane = tid & 31, w = tid >> 5;
    int bm = blockIdx.y * 128, bn = blockIdx.x * 128;
    int mw = (w & 3) * 32, nw = (w >> 2) * 64;
    uint32_t sbase = smem_u32(smem);

    float acc[2][8][4];
#pragma unroll
    for (int i = 0; i < 2; i++)
#pragma unroll
        for (int j = 0; j < 8; j++)
#pragma unroll
            for (int q = 0; q < 4; q++) acc[i][j][q] = 0.f;

    const int NC = K / BK;
    int lr = tid >> 2, lc = tid & 3;

    auto issue = [&](int c, int buf) {
        uint32_t st = sbase + buf * STAGE_B;
        int kc = c * BK;
#pragma unroll
        for (int half = 0; half < 2; half++) {
            int rr = lr + half * 64;
            int so = sw_off(rr, lc);
            size_t gA = (size_t)(bm + rr) * K + kc + lc * 8;
            size_t gB = (size_t)(bn + rr) * K + kc + lc * 8;
            cp_async16(st + so, Ah + gA);
            cp_async16(st + TILE_B + so, Al + gA);
            cp_async16(st + 2 * TILE_B + so, B + gB);
        }
    };

    issue(0, 0);
    CP_COMMIT();

    int rA = mw + (lane & 15);
    int rB = nw + (lane & 15);

    for (int c = 0; c < NC; c++) {
        if (c + 1 < NC) {
            issue(c + 1, (c + 1) & 1);
            CP_COMMIT();
            CP_WAIT(1);
        } else {
            CP_WAIT(0);
        }
        __syncthreads();

        uint32_t st = sbase + (c & 1) * STAGE_B;
#pragma unroll
        for (int k16 = 0; k16 < 2; k16++) {
            int cchunk = k16 * 2 + (lane >> 4);
            uint32_t ah[2][4], al[2][4];
            ldsm4(ah[0], st + sw_off(rA, cchunk));
            ldsm4(ah[1], st + sw_off(rA + 16, cchunk));
            ldsm4(al[0], st + TILE_B + sw_off(rA, cchunk));
            ldsm4(al[1], st + TILE_B + sw_off(rA + 16, cchunk));
#pragma unroll
            for (int ni = 0; ni < 4; ni++) {
                uint32_t b[4];
                ldsm4(b, st + 2 * TILE_B + sw_off(rB + ni * 16, cchunk));
#pragma unroll
                for (int s = 0; s < 2; s++) {
                    mma16816(acc[0][ni * 2 + s], ah[0], b[s], b[2 + s]);
                    mma16816(acc[1][ni * 2 + s], ah[1], b[s], b[2 + s]);
                    mma16816(acc[0][ni * 2 + s], al[0], b[s], b[2 + s]);
                    mma16816(acc[1][ni * 2 + s], al[1], b[s], b[2 + s]);
                }
            }
        }
        __syncthreads();
    }

    int gid = lane >> 2, q = lane & 3;
#pragma unroll
    for (int mi = 0; mi < 2; mi++)
#pragma unroll
        for (int j = 0; j < 8; j++) {
            int row = bm + mw + mi * 16 + gid;
            int col = bn + nw + j * 8 + q * 2;
            *(float2*)&C[(size_t)row * N + col] =
                make_float2(acc[mi][j][0], acc[mi][j][1]);
            *(float2*)&C[(size_t)(row + 8) * N + col] =
                make_float2(acc[mi][j][2], acc[mi][j][3]);
        }
}

// ---------------- RoPE: Q (scaled, hi/lo) + K (single) -> fp16 ----------------
__global__ __launch_bounds__(256) void rope_qk(const float* __restrict__ cosb,
                                               const float* __restrict__ sinb) {
    int idx = blockIdx.x * blockDim.x + threadIdx.x;
    if (idx >= T_SEQ * 20 * 64) return;
    int d = idx & 63;
    int h = (idx >> 6) % 20;
    int t = idx / (64 * 20);
    float c = cosb[t * 64 + d], sn = sinb[t * 64 + d];
    if (h < 16) {
        int base = t * QKV_DIM + (h >> 2) * 768 + (h & 3) * 128;
        float x1 = g_qkv[base + d], x2 = g_qkv[base + 64 + d];
        float o1 = (x1 * c - x2 * sn) * SCALE_LOG2;
        float o2 = (x2 * c + x1 * sn) * SCALE_LOG2;
        size_t o = (size_t)t * 2048 + h * 128 + d;
        __half h1 = __float2half_rn(o1);
        __half h2 = __float2half_rn(o2);
        g_qh[o] = h1;      g_ql[o] = __float2half_rn(o1 - __half2float(h1));
        g_qh[o + 64] = h2; g_ql[o + 64] = __float2half_rn(o2 - __half2float(h2));
    } else {
        int gi = h - 16;
        int base = t * QKV_DIM + gi * 768 + 512;
        float x1 = g_qkv[base + d], x2 = g_qkv[base + 64 + d];
        size_t o = ((size_t)gi * T_SEQ + t) * 128 + d;
        g_kh[o]      = __float2half_rn(x1 * c - x2 * sn);
        g_kh[o + 64] = __float2half_rn(x2 * c + x1 * sn);
    }
}

// ---------------- V transpose -> [g][d][t] fp16 ----------------
__global__ __launch_bounds__(256) void v_trans() {
    int idx = blockIdx.x * blockDim.x + threadIdx.x;
    if (idx >= NQG * 128 * T_SEQ) return;
    int t = idx & (T_SEQ - 1);
    int d = (idx >> 12) & 127;
    int gi = idx >> 19;
    float v = g_qkv[t * QKV_DIM + gi * 768 + 640 + d];
    g_vh[((size_t)gi * 128 + d) * T_SEQ + t] = __float2half_rn(v);
}

// ---------------- mma.sync flash attention (2-term fp16) ----------------
// smem: Qh[0:32K) Ql[32K:64K) stages{K 16K, V 16K} x2 at 64K. Total 128KB.
#define AT_Q_BYTES 32768
#define AT_STG_OFF 65536
#define AT_STG_B   32768

__global__ __launch_bounds__(256, 1) void attn_mma() {
    extern __shared__ __align__(128) char smem[];
    uint32_t sb = smem_u32(smem);
    int tid = threadIdx.x;
    int lane = tid & 31, w = tid >> 5;
    int qb = 31 - blockIdx.x;   // longest first
    int h = blockIdx.y;
    int g = h >> 2;
    int rw = w * 16;
    int ktmax = 2 * qb + 1;

    // ---- Q load (once) ----
#pragma unroll
    for (int i = 0; i < 8; i++) {
        int chunk = tid + 256 * i;
        int r = chunk >> 4, cd = chunk & 15;
        size_t src = (size_t)(qb * 128 + r) * 2048 + h * 128 + cd * 8;
        uint32_t dst = sb + (cd >> 2) * 8192 + sw_off(r, cd & 3);
        cp_async16(dst, g_qh + src);
        cp_async16(dst + AT_Q_BYTES, g_ql + src);
    }

    auto issueKV = [&](int kt, int stg) {
        uint32_t st = sb + AT_STG_OFF + stg * AT_STG_B;
#pragma unroll
        for (int i = 0; i < 4; i++) {
            int chunk = tid + 256 * i;
            int r = chunk >> 4, cd = chunk & 15;
            size_t src = ((size_t)g * T_SEQ + kt * 64 + r) * 128 + cd * 8;
            uint32_t dst = st + (cd >> 2) * 4096 + sw_off(r, cd & 3);
            cp_async16(dst, g_kh + src);
        }
#pragma unroll
        for (int i = 0; i < 4; i++) {
            int chunk = tid + 256 * i;
            int d = chunk >> 3, sc = chunk & 7;
            size_t src = ((size_t)g * 128 + d) * T_SEQ + kt * 64 + sc * 8;
            uint32_t dst = st + 16384 + (sc >> 2) * 8192 + sw_off(d, sc & 3);
            cp_async16(dst, g_vh + src);
        }
    };

    issueKV(0, 0);
    CP_COMMIT();

    float oacc[16][4];
#pragma unroll
    for (int i = 0; i < 16; i++)
#pragma unroll
        for (int j = 0; j < 4; j++) oacc[i][j] = 0.f;
    float mi0 = -1e30f, mi1 = -1e30f, li0 = 0.f, li1 = 0.f;

    int rK = lane & 15, cH = lane >> 4;
    int qr1 = qb * 128 + rw + (lane >> 2);

    for (int kt = 0; kt <= ktmax; kt++) {
        if (kt < ktmax) {
            issueKV(kt + 1, (kt + 1) & 1);
            CP_COMMIT();
            CP_WAIT(1);
        } else {
            CP_WAIT(0);
        }
        __syncthreads();

        uint32_t KH = sb + AT_STG_OFF + (kt & 1) * AT_STG_B;
        uint32_t VH = KH + 16384;

        // ---- S = (Qh+Ql) K^T (log2-scaled) ----
        float s[8][4];
#pragma unroll
        for (int j = 0; j < 8; j++)
#pragma unroll
            for (int e = 0; e < 4; e++) s[j][e] = 0.f;

#pragma unroll
        for (int kk = 0; kk < 8; kk++) {
            int c = ((kk & 1) << 1) + cH;
            uint32_t qpan = sb + (kk >> 1) * 8192;
            uint32_t ah[4], al2[4];
            ldsm4(ah, qpan + sw_off(rw + rK, c));
            ldsm4(al2, qpan + AT_Q_BYTES + sw_off(rw + rK, c));
            uint32_t kpan = (kk >> 1) * 4096;
#pragma unroll
            for (int ni = 0; ni < 4; ni++) {
                uint32_t kh4[4];
                ldsm4(kh4, KH + kpan + sw_off(ni * 16 + rK, c));
#pragma unroll
                for (int ss = 0; ss < 2; ss++) {
                    mma16816(s[ni * 2 + ss], ah, kh4[ss], kh4[2 + ss]);
                    mma16816(s[ni * 2 + ss], al2, kh4[ss], kh4[2 + ss]);
                }
            }
        }

        // ---- causal mask (diagonal CTA tiles only) ----
        if (kt >= 2 * qb) {
            int colb = kt * 64 + ((lane & 3) << 1);
#pragma unroll
            for (int j = 0; j < 8; j++) {
                int c0 = colb + j * 8;
                if (c0 > qr1)     s[j][0] = -1e30f;
                if (c0 + 1 > qr1) s[j][1] = -1e30f;
                if (c0 > qr1 + 8)     s[j][2] = -1e30f;
                if (c0 + 1 > qr1 + 8) s[j][3] = -1e30f;
            }
        }

        // ---- online softmax (base-2) ----
        float mx0 = -1e30f, mx1 = -1e30f;
#pragma unroll
        for (int j = 0; j < 8; j++) {
            mx0 = fmaxf(mx0, fmaxf(s[j][0], s[j][1]));
            mx1 = fmaxf(mx1, fmaxf(s[j][2], s[j][3]));
        }
        mx0 = fmaxf(mx0, __shfl_xor_sync(0xffffffffu, mx0, 1));
        mx0 = fmaxf(mx0, __shfl_xor_sync(0xffffffffu, mx0, 2));
        mx1 = fmaxf(mx1, __shfl_xor_sync(0xffffffffu, mx1, 1));
        mx1 = fmaxf(mx1, __shfl_xor_sync(0xffffffffu, mx1, 2));
        float mn0 = fmaxf(mi0, mx0), mn1 = fmaxf(mi1, mx1);
        float a0 = exp2f(mi0 - mn0), a1 = exp2f(mi1 - mn1);
        mi0 = mn0; mi1 = mn1;
        float sum0 = 0.f, sum1 = 0.f;
#pragma unroll
        for (int j = 0; j < 8; j++) {
            s[j][0] = exp2f(s[j][0] - mn0);
            s[j][1] = exp2f(s[j][1] - mn0);
            s[j][2] = exp2f(s[j][2] - mn1);
            s[j][3] = exp2f(s[j][3] - mn1);
            sum0 += s[j][0] + s[j][1];
            sum1 += s[j][2] + s[j][3];
        }
        sum0 += __shfl_xor_sync(0xffffffffu, sum0, 1);
        sum0 += __shfl_xor_sync(0xffffffffu, sum0, 2);
        sum1 += __shfl_xor_sync(0xffffffffu, sum1, 1);
        sum1 += __shfl_xor_sync(0xffffffffu, sum1, 2);
        li0 = li0 * a0 + sum0;
        li1 = li1 * a1 + sum1;
        if (a0 != 1.f || a1 != 1.f) {
#pragma unroll
            for (int ni = 0; ni < 16; ni++) {
                oacc[ni][0] *= a0; oacc[ni][1] *= a0;
                oacc[ni][2] *= a1; oacc[ni][3] *= a1;
            }
        }

        // ---- O += (Ph+Pl) V, P from registers ----
#pragma unroll
        for (int kk2 = 0; kk2 < 4; kk2++) {
            uint32_t hp[4], lp[4];
            {
                float* p0 = s[2 * kk2];
                float* p1 = s[2 * kk2 + 1];
                hp[0] = pack2h(p0[0], p0[1]);
                hp[1] = pack2h(p0[2], p0[3]);
                hp[2] = pack2h(p1[0], p1[1]);
                hp[3] = pack2h(p1[2], p1[3]);
                lp[0] = pack2h(p0[0] - lo_h(hp[0]), p0[1] - hi_h(hp[0]));
                lp[1] = pack2h(p0[2] - lo_h(hp[1]), p0[3] - hi_h(hp[1]));
                lp[2] = pack2h(p1[0] - lo_h(hp[2]), p1[1] - hi_h(hp[2]));
                lp[3] = pack2h(p1[2] - lo_h(hp[3]), p1[3] - hi_h(hp[3]));
            }
            int c = ((kk2 & 1) << 1) + cH;
            uint32_t vpan = (kk2 >> 1) * 8192;
#pragma unroll
            for (int ni = 0; ni < 8; ni++) {
                uint32_t vh4[4];
                ldsm4(vh4, VH + vpan + sw_off(ni * 16 + rK, c));
#pragma unroll
                for (int ss = 0; ss < 2; ss++) {
                    mma16816(oacc[ni * 2 + ss], hp, vh4[ss], vh4[2 + ss]);
                    mma16816(oacc[ni * 2 + ss], lp, vh4[ss], vh4[2 + ss]);
                }
            }
        }
        __syncthreads();
    }

    // ---- epilogue: O/l -> fp16 hi/lo ----
    float inv0 = 1.f / li0, inv1 = 1.f / li1;
    size_t row1 = (size_t)qr1 * 2048 + h * 128;
    size_t row2 = row1 + (size_t)8 * 2048;
#pragma unroll
    for (int ni = 0; ni < 16; ni++) {
        int colo = ni * 8 + ((lane & 3) << 1);
        float f0 = oacc[ni][0] * inv0, f1 = oacc[ni][1] * inv0;
        float f2 = oacc[ni][2] * inv1, f3 = oacc[ni][3] * inv1;
        uint32_t h0 = pack2h(f0, f1);
        uint32_t l0 = pack2h(f0 - lo_h(h0), f1 - hi_h(h0));
        uint32_t h1 = pack2h(f2, f3);
        uint32_t l1 = pack2h(f2 - lo_h(h1), f3 - hi_h(h1));
        *(uint32_t*)&g_yh[row1 + colo] = h0;
        *(uint32_t*)&g_yl[row1 + colo] = l0;
        *(uint32_t*)&g_yh[row2 + colo] = h1;
        *(uint32_t*)&g_yl[row2 + colo] = l1;
    }
}

// ---------------- launch ----------------
extern "C" void kernel_launch(void* const* d_in, const int* in_sizes, int n_in,
                              void* d_out, int out_size) {
    const float* x    = (const float*)d_in[0];
    const float* cosb = (const float*)d_in[1];
    const float* sinb = (const float*)d_in[2];
    const float* Wa   = (const float*)d_in[3];
    const float* Wp   = (const float*)d_in[4];
    float* out = (float*)d_out;

    float* qkv_p;
    cudaGetSymbolAddress((void**)&qkv_p, g_qkv);
    __half *xh, *xl, *wa, *wp, *yh, *yl;
    cudaGetSymbolAddress((void**)&xh, g_xh); cudaGetSymbolAddress((void**)&xl, g_xl);
    cudaGetSymbolAddress((void**)&wa, g_wa); cudaGetSymbolAddress((void**)&wp, g_wp);
    cudaGetSymbolAddress((void**)&yh, g_yh); cudaGetSymbolAddress((void**)&yl, g_yl);

    const int gemm_smem = 2 * STAGE_B;  // 48 KB
    cudaFuncSetAttribute(gemm_mma, cudaFuncAttributeMaxDynamicSharedMemorySize, gemm_smem);
    const int attn_smem = AT_STG_OFF + 2 * AT_STG_B;  // 128 KB
    cudaFuncSetAttribute(attn_mma, cudaFuncAttributeMaxDynamicSharedMemorySize, attn_smem);

    // 1) split x (hi/lo); convert weights (single fp16)
    {
        int n4 = T_SEQ * C_DIM / 4;
        split_fp16<<<(n4 + 255) / 256, 256>>>((const float4*)x, (uint32_t*)xh,
                                              (uint32_t*)xl, n4);
        int w4 = QKV_DIM * C_DIM / 4;
        conv_fp16<<<(w4 + 255) / 256, 256>>>((const float4*)Wa, (uint32_t*)wa, w4);
        int p4 = C_DIM * C_DIM / 4;
        conv_fp16<<<(p4 + 255) / 256, 256>>>((const float4*)Wp, (uint32_t*)wp, p4);
    }

    // 2) qkv = x @ W_attn^T
    gemm_mma<<<dim3(QKV_DIM / 128, T_SEQ / 128), 256, gemm_smem>>>(
        xh, xl, wa, qkv_p, QKV_DIM, C_DIM);

    // 3) rope + split + v transpose
    rope_qk<<<(T_SEQ * 20 * 64) / 256, 256>>>(cosb, sinb);
    v_trans<<<(NQG * 128 * T_SEQ) / 256, 256>>>();

    // 4) attention (writes yh/yl directly)
    attn_mma<<<dim3(32, NHEAD), 256, attn_smem>>>();

    // 5) out = y @ W_proj^T
    gemm_mma<<<dim3(C_DIM / 128, T_SEQ / 128), 256, gemm_smem>>>(
        yh, yl, wp, out, C_DIM, C_DIM);
}

// round 7
// speedup vs baseline: 4.8984x; 1.1375x over previous
#include <cuda_runtime.h>
#include <cuda_fp16.h>
#include <math.h>
#include <stdint.h>

#define T_SEQ 4096
#define C_DIM 2048
#define NHEAD 16
#define HS 128
#define NQG 4
#define QKV_DIM 3072
#define SCALE_LOG2 0.1275071050830161f       // (1/sqrt(128)) * log2(e)

// ---------------- scratch ----------------
__device__ float g_qkv[T_SEQ * QKV_DIM];

__device__ __half g_xh[T_SEQ * C_DIM];
__device__ __half g_xl[T_SEQ * C_DIM];
__device__ __half g_wa[QKV_DIM * C_DIM];
__device__ __half g_wp[C_DIM * C_DIM];

__device__ __half g_qh[T_SEQ * NHEAD * HS];   // [t][h*128+d], scaled by SCALE_LOG2
__device__ __half g_ql[T_SEQ * NHEAD * HS];
__device__ __half g_kh[NQG * T_SEQ * HS];     // [g][t][d]
__device__ __half g_vh[NQG * HS * T_SEQ];     // [g][d][t]  (d-major)
__device__ __half g_yh[T_SEQ * C_DIM];
__device__ __half g_yl[T_SEQ * C_DIM];

// ---------------- PTX helpers ----------------
__device__ __forceinline__ uint32_t smem_u32(const void* p) {
    uint32_t a;
    asm("{ .reg .u64 t; cvta.to.shared.u64 t, %1; cvt.u32.u64 %0, t; }"
        : "=r"(a) : "l"(p));
    return a;
}
__device__ __forceinline__ void cp_async16(uint32_t s, const void* g) {
    asm volatile("cp.async.cg.shared.global [%0], [%1], 16;" :: "r"(s), "l"(g));
}
#define CP_COMMIT() asm volatile("cp.async.commit_group;" ::: "memory")
#define CP_WAIT(n)  asm volatile("cp.async.wait_group %0;" :: "n"(n) : "memory")

__device__ __forceinline__ void ldsm4(uint32_t* f, uint32_t a) {
    asm volatile("ldmatrix.sync.aligned.m8n8.x4.shared.b16 {%0,%1,%2,%3}, [%4];"
                 : "=r"(f[0]), "=r"(f[1]), "=r"(f[2]), "=r"(f[3]) : "r"(a));
}
__device__ __forceinline__ void mma16816(float* d, const uint32_t* a,
                                         uint32_t b0, uint32_t b1) {
    asm volatile(
        "mma.sync.aligned.m16n8k16.row.col.f32.f16.f16.f32 "
        "{%0,%1,%2,%3}, {%4,%5,%6,%7}, {%8,%9}, {%0,%1,%2,%3};"
        : "+f"(d[0]), "+f"(d[1]), "+f"(d[2]), "+f"(d[3])
        : "r"(a[0]), "r"(a[1]), "r"(a[2]), "r"(a[3]), "r"(b0), "r"(b1));
}
__device__ __forceinline__ uint32_t pack2h(float lo, float hi) {
    uint32_t r;
    asm("cvt.rn.f16x2.f32 %0, %1, %2;" : "=r"(r) : "f"(hi), "f"(lo));
    return r;
}
__device__ __forceinline__ float lo_h(uint32_t u) {
    return __half2float(__ushort_as_half((unsigned short)(u & 0xffffu)));
}
__device__ __forceinline__ float hi_h(uint32_t u) {
    return __half2float(__ushort_as_half((unsigned short)(u >> 16)));
}

// 64B-row XOR swizzle (rows of 32 halves, 4x16B chunks) — conflict-free ldmatrix phases
__device__ __forceinline__ int sw_off(int r, int c) {
    return r * 64 + ((c ^ ((r >> 1) & 3)) << 4);
}

// ---------------- split fp32 -> (hi, lo) fp16, vectorized x4 ----------------
__global__ __launch_bounds__(256) void split_fp16(const float4* __restrict__ s,
                                                  uint32_t* __restrict__ h,
                                                  uint32_t* __restrict__ l, int n4) {
    int i = blockIdx.x * 256 + threadIdx.x;
    if (i < n4) {
        float4 v = s[i];
        uint32_t h0 = pack2h(v.x, v.y), h1 = pack2h(v.z, v.w);
        uint32_t l0 = pack2h(v.x - lo_h(h0), v.y - hi_h(h0));
        uint32_t l1 = pack2h(v.z - lo_h(h1), v.w - hi_h(h1));
        h[2 * i] = h0;     h[2 * i + 1] = h1;
        l[2 * i] = l0;     l[2 * i + 1] = l1;
    }
}
__global__ __launch_bounds__(256) void conv_fp16(const float4* __restrict__ s,
                                                 uint32_t* __restrict__ h, int n4) {
    int i = blockIdx.x * 256 + threadIdx.x;
    if (i < n4) {
        float4 v = s[i];
        h[2 * i]     = pack2h(v.x, v.y);
        h[2 * i + 1] = pack2h(v.z, v.w);
    }
}

// ---------------- mma.sync 2-term fp16 GEMM: C = (Ah+Al) * B^T ----------------
// CTA 128x128, BK=32, 8 warps (4Mx2N), 2 CTAs/SM.
// 3-stage cp.async pipeline, ONE __syncthreads per K-chunk.
#define BK 32
#define TILE_B 8192
#define STAGE_B (3 * TILE_B)   // Ah, Al, B tiles per stage = 24KB

__global__ __launch_bounds__(256, 2) void gemm_mma(const __half* __restrict__ Ah,
                                                   const __half* __restrict__ Al,
                                                   const __half* __restrict__ B,
                                                   float* __restrict__ C, int N, int K) {
    extern __shared__ __align__(128) char smem[];
    int tid = threadIdx.x;
    int lane = tid & 31, w = tid >> 5;
    int bm = blockIdx.y * 128, bn = blockIdx.x * 128;
    int mw = (w & 3) * 32, nw = (w >> 2) * 64;
    uint32_t sbase = smem_u32(smem);

    float acc[2][8][4];
#pragma unroll
    for (int i = 0; i < 2; i++)
#pragma unroll
        for (int j = 0; j < 8; j++)
#pragma unroll
            for (int q = 0; q < 4; q++) acc[i][j][q] = 0.f;

    const int NC = K / BK;
    int lr = tid >> 2, lc = tid & 3;

    auto issue = [&](int c, int buf) {
        uint32_t st = sbase + buf * STAGE_B;
        int kc = c * BK;
#pragma unroll
        for (int half = 0; half < 2; half++) {
            int rr = lr + half * 64;
            int so = sw_off(rr, lc);
            size_t gA = (size_t)(bm + rr) * K + kc + lc * 8;
            size_t gB = (size_t)(bn + rr) * K + kc + lc * 8;
            cp_async16(st + so, Ah + gA);
            cp_async16(st + TILE_B + so, Al + gA);
            cp_async16(st + 2 * TILE_B + so, B + gB);
        }
    };

    issue(0, 0); CP_COMMIT();
    issue(1, 1); CP_COMMIT();

    int rA = mw + (lane & 15);
    int rB = nw + (lane & 15);

    for (int c = 0; c < NC; c++) {
        CP_WAIT(1);
        __syncthreads();

        uint32_t st = sbase + (c % 3) * STAGE_B;
#pragma unroll
        for (int k16 = 0; k16 < 2; k16++) {
            int cchunk = k16 * 2 + (lane >> 4);
            uint32_t ah[2][4], al[2][4];
            ldsm4(ah[0], st + sw_off(rA, cchunk));
            ldsm4(ah[1], st + sw_off(rA + 16, cchunk));
            ldsm4(al[0], st + TILE_B + sw_off(rA, cchunk));
            ldsm4(al[1], st + TILE_B + sw_off(rA + 16, cchunk));
#pragma unroll
            for (int ni = 0; ni < 4; ni++) {
                uint32_t b[4];
                ldsm4(b, st + 2 * TILE_B + sw_off(rB + ni * 16, cchunk));
#pragma unroll
                for (int s = 0; s < 2; s++) {
                    mma16816(acc[0][ni * 2 + s], ah[0], b[s], b[2 + s]);
                    mma16816(acc[1][ni * 2 + s], ah[1], b[s], b[2 + s]);
                    mma16816(acc[0][ni * 2 + s], al[0], b[s], b[2 + s]);
                    mma16816(acc[1][ni * 2 + s], al[1], b[s], b[2 + s]);
                }
            }
        }
        if (c + 2 < NC) issue(c + 2, (c + 2) % 3);
        CP_COMMIT();
    }

    int gid = lane >> 2, q = lane & 3;
#pragma unroll
    for (int mi = 0; mi < 2; mi++)
#pragma unroll
        for (int j = 0; j < 8; j++) {
            int row = bm + mw + mi * 16 + gid;
            int col = bn + nw + j * 8 + q * 2;
            *(float2*)&C[(size_t)row * N + col] =
                make_float2(acc[mi][j][0], acc[mi][j][1]);
            *(float2*)&C[(size_t)(row + 8) * N + col] =
                make_float2(acc[mi][j][2], acc[mi][j][3]);
        }
}

// ---------------- RoPE: Q (scaled, hi/lo) + K (single) -> fp16 ----------------
__global__ __launch_bounds__(256) void rope_qk(const float* __restrict__ cosb,
                                               const float* __restrict__ sinb) {
    int idx = blockIdx.x * blockDim.x + threadIdx.x;
    if (idx >= T_SEQ * 20 * 64) return;
    int d = idx & 63;
    int h = (idx >> 6) % 20;
    int t = idx / (64 * 20);
    float c = cosb[t * 64 + d], sn = sinb[t * 64 + d];
    if (h < 16) {
        int base = t * QKV_DIM + (h >> 2) * 768 + (h & 3) * 128;
        float x1 = g_qkv[base + d], x2 = g_qkv[base + 64 + d];
        float o1 = (x1 * c - x2 * sn) * SCALE_LOG2;
        float o2 = (x2 * c + x1 * sn) * SCALE_LOG2;
        size_t o = (size_t)t * 2048 + h * 128 + d;
        __half h1 = __float2half_rn(o1);
        __half h2 = __float2half_rn(o2);
        g_qh[o] = h1;      g_ql[o] = __float2half_rn(o1 - __half2float(h1));
        g_qh[o + 64] = h2; g_ql[o + 64] = __float2half_rn(o2 - __half2float(h2));
    } else {
        int gi = h - 16;
        int base = t * QKV_DIM + gi * 768 + 512;
        float x1 = g_qkv[base + d], x2 = g_qkv[base + 64 + d];
        size_t o = ((size_t)gi * T_SEQ + t) * 128 + d;
        g_kh[o]      = __float2half_rn(x1 * c - x2 * sn);
        g_kh[o + 64] = __float2half_rn(x2 * c + x1 * sn);
    }
}

// ---------------- V transpose -> [g][d][t] fp16 ----------------
__global__ __launch_bounds__(256) void v_trans() {
    int idx = blockIdx.x * blockDim.x + threadIdx.x;
    if (idx >= NQG * 128 * T_SEQ) return;
    int t = idx & (T_SEQ - 1);
    int d = (idx >> 12) & 127;
    int gi = idx >> 19;
    float v = g_qkv[t * QKV_DIM + gi * 768 + 640 + d];
    g_vh[((size_t)gi * 128 + d) * T_SEQ + t] = __float2half_rn(v);
}

// ---------------- mma.sync flash attention ----------------
// 2-term QK (Q hi/lo), SINGLE-term PV. 3-stage KV pipeline, 1 sync/iter.
// smem: Qh[0:32K) Ql[32K:64K) stages{K 16K, V 16K} x3 at 64K. Total 160KB.
#define AT_Q_BYTES 32768
#define AT_STG_OFF 65536
#define AT_STG_B   32768

__global__ __launch_bounds__(256, 1) void attn_mma() {
    extern __shared__ __align__(128) char smem[];
    uint32_t sb = smem_u32(smem);
    int tid = threadIdx.x;
    int lane = tid & 31, w = tid >> 5;
    int qb = 31 - blockIdx.x;   // longest first
    int h = blockIdx.y;
    int g = h >> 2;
    int rw = w * 16;
    int ktmax = 2 * qb + 1;

    // ---- Q load (folded into first commit group) ----
#pragma unroll
    for (int i = 0; i < 8; i++) {
        int chunk = tid + 256 * i;
        int r = chunk >> 4, cd = chunk & 15;
        size_t src = (size_t)(qb * 128 + r) * 2048 + h * 128 + cd * 8;
        uint32_t dst = sb + (cd >> 2) * 8192 + sw_off(r, cd & 3);
        cp_async16(dst, g_qh + src);
        cp_async16(dst + AT_Q_BYTES, g_ql + src);
    }

    auto issueKV = [&](int kt, int stg) {
        uint32_t st = sb + AT_STG_OFF + stg * AT_STG_B;
#pragma unroll
        for (int i = 0; i < 4; i++) {
            int chunk = tid + 256 * i;
            int r = chunk >> 4, cd = chunk & 15;
            size_t src = ((size_t)g * T_SEQ + kt * 64 + r) * 128 + cd * 8;
            uint32_t dst = st + (cd >> 2) * 4096 + sw_off(r, cd & 3);
            cp_async16(dst, g_kh + src);
        }
#pragma unroll
        for (int i = 0; i < 4; i++) {
            int chunk = tid + 256 * i;
            int d = chunk >> 3, sc = chunk & 7;
            size_t src = ((size_t)g * 128 + d) * T_SEQ + kt * 64 + sc * 8;
            uint32_t dst = st + 16384 + (sc >> 2) * 8192 + sw_off(d, sc & 3);
            cp_async16(dst, g_vh + src);
        }
    };

    issueKV(0, 0); CP_COMMIT();
    issueKV(1, 1); CP_COMMIT();   // ktmax >= 1 always

    float oacc[16][4];
#pragma unroll
    for (int i = 0; i < 16; i++)
#pragma unroll
        for (int j = 0; j < 4; j++) oacc[i][j] = 0.f;
    float mi0 = -1e30f, mi1 = -1e30f, li0 = 0.f, li1 = 0.f;

    int rK = lane & 15, cH = lane >> 4;
    int qr1 = qb * 128 + rw + (lane >> 2);

    for (int kt = 0; kt <= ktmax; kt++) {
        CP_WAIT(1);
        __syncthreads();

        uint32_t KH = sb + AT_STG_OFF + (kt % 3) * AT_STG_B;
        uint32_t VH = KH + 16384;

        // ---- S = (Qh+Ql) K^T (log2-scaled) ----
        float s[8][4];
#pragma unroll
        for (int j = 0; j < 8; j++)
#pragma unroll
            for (int e = 0; e < 4; e++) s[j][e] = 0.f;

#pragma unroll
        for (int kk = 0; kk < 8; kk++) {
            int c = ((kk & 1) << 1) + cH;
            uint32_t qpan = sb + (kk >> 1) * 8192;
            uint32_t ah[4], al2[4];
            ldsm4(ah, qpan + sw_off(rw + rK, c));
            ldsm4(al2, qpan + AT_Q_BYTES + sw_off(rw + rK, c));
            uint32_t kpan = (kk >> 1) * 4096;
#pragma unroll
            for (int ni = 0; ni < 4; ni++) {
                uint32_t kh4[4];
                ldsm4(kh4, KH + kpan + sw_off(ni * 16 + rK, c));
#pragma unroll
                for (int ss = 0; ss < 2; ss++) {
                    mma16816(s[ni * 2 + ss], ah, kh4[ss], kh4[2 + ss]);
                    mma16816(s[ni * 2 + ss], al2, kh4[ss], kh4[2 + ss]);
                }
            }
        }

        // ---- causal mask (diagonal CTA tiles only) ----
        if (kt >= 2 * qb) {
            int colb = kt * 64 + ((lane & 3) << 1);
#pragma unroll
            for (int j = 0; j < 8; j++) {
                int c0 = colb + j * 8;
                if (c0 > qr1)     s[j][0] = -1e30f;
                if (c0 + 1 > qr1) s[j][1] = -1e30f;
                if (c0 > qr1 + 8)     s[j][2] = -1e30f;
                if (c0 + 1 > qr1 + 8) s[j][3] = -1e30f;
            }
        }

        // ---- online softmax (base-2) ----
        float mx0 = -1e30f, mx1 = -1e30f;
#pragma unroll
        for (int j = 0; j < 8; j++) {
            mx0 = fmaxf(mx0, fmaxf(s[j][0], s[j][1]));
            mx1 = fmaxf(mx1, fmaxf(s[j][2], s[j][3]));
        }
        mx0 = fmaxf(mx0, __shfl_xor_sync(0xffffffffu, mx0, 1));
        mx0 = fmaxf(mx0, __shfl_xor_sync(0xffffffffu, mx0, 2));
        mx1 = fmaxf(mx1, __shfl_xor_sync(0xffffffffu, mx1, 1));
        mx1 = fmaxf(mx1, __shfl_xor_sync(0xffffffffu, mx1, 2));
        float mn0 = fmaxf(mi0, mx0), mn1 = fmaxf(mi1, mx1);
        float a0 = exp2f(mi0 - mn0), a1 = exp2f(mi1 - mn1);
        mi0 = mn0; mi1 = mn1;
        float sum0 = 0.f, sum1 = 0.f;
#pragma unroll
        for (int j = 0; j < 8; j++) {
            s[j][0] = exp2f(s[j][0] - mn0);
            s[j][1] = exp2f(s[j][1] - mn0);
            s[j][2] = exp2f(s[j][2] - mn1);
            s[j][3] = exp2f(s[j][3] - mn1);
            sum0 += s[j][0] + s[j][1];
            sum1 += s[j][2] + s[j][3];
        }
        sum0 += __shfl_xor_sync(0xffffffffu, sum0, 1);
        sum0 += __shfl_xor_sync(0xffffffffu, sum0, 2);
        sum1 += __shfl_xor_sync(0xffffffffu, sum1, 1);
        sum1 += __shfl_xor_sync(0xffffffffu, sum1, 2);
        li0 = li0 * a0 + sum0;
        li1 = li1 * a1 + sum1;
        if (a0 != 1.f || a1 != 1.f) {
#pragma unroll
            for (int ni = 0; ni < 16; ni++) {
                oacc[ni][0] *= a0; oacc[ni][1] *= a0;
                oacc[ni][2] *= a1; oacc[ni][3] *= a1;
            }
        }

        // ---- O += P V (single term), P from registers ----
#pragma unroll
        for (int kk2 = 0; kk2 < 4; kk2++) {
            uint32_t hp[4];
            {
                float* p0 = s[2 * kk2];
                float* p1 = s[2 * kk2 + 1];
                hp[0] = pack2h(p0[0], p0[1]);
                hp[1] = pack2h(p0[2], p0[3]);
                hp[2] = pack2h(p1[0], p1[1]);
                hp[3] = pack2h(p1[2], p1[3]);
            }
            int c = ((kk2 & 1) << 1) + cH;
            uint32_t vpan = (kk2 >> 1) * 8192;
#pragma unroll
            for (int ni = 0; ni < 8; ni++) {
                uint32_t vh4[4];
                ldsm4(vh4, VH + vpan + sw_off(ni * 16 + rK, c));
#pragma unroll
                for (int ss = 0; ss < 2; ss++)
                    mma16816(oacc[ni * 2 + ss], hp, vh4[ss], vh4[2 + ss]);
            }
        }

        if (kt + 2 <= ktmax) issueKV(kt + 2, (kt + 2) % 3);
        CP_COMMIT();
    }

    // ---- epilogue: O/l -> fp16 hi/lo ----
    float inv0 = 1.f / li0, inv1 = 1.f / li1;
    size_t row1 = (size_t)qr1 * 2048 + h * 128;
    size_t row2 = row1 + (size_t)8 * 2048;
#pragma unroll
    for (int ni = 0; ni < 16; ni++) {
        int colo = ni * 8 + ((lane & 3) << 1);
        float f0 = oacc[ni][0] * inv0, f1 = oacc[ni][1] * inv0;
        float f2 = oacc[ni][2] * inv1, f3 = oacc[ni][3] * inv1;
        uint32_t h0 = pack2h(f0, f1);
        uint32_t l0 = pack2h(f0 - lo_h(h0), f1 - hi_h(h0));
        uint32_t h1 = pack2h(f2, f3);
        uint32_t l1 = pack2h(f2 - lo_h(h1), f3 - hi_h(h1));
        *(uint32_t*)&g_yh[row1 + colo] = h0;
        *(uint32_t*)&g_yl[row1 + colo] = l0;
        *(uint32_t*)&g_yh[row2 + colo] = h1;
        *(uint32_t*)&g_yl[row2 + colo] = l1;
    }
}

// ---------------- launch ----------------
extern "C" void kernel_launch(void* const* d_in, const int* in_sizes, int n_in,
                              void* d_out, int out_size) {
    const float* x    = (const float*)d_in[0];
    const float* cosb = (const float*)d_in[1];
    const float* sinb = (const float*)d_in[2];
    const float* Wa   = (const float*)d_in[3];
    const float* Wp   = (const float*)d_in[4];
    float* out = (float*)d_out;

    float* qkv_p;
    cudaGetSymbolAddress((void**)&qkv_p, g_qkv);
    __half *xh, *xl, *wa, *wp, *yh, *yl;
    cudaGetSymbolAddress((void**)&xh, g_xh); cudaGetSymbolAddress((void**)&xl, g_xl);
    cudaGetSymbolAddress((void**)&wa, g_wa); cudaGetSymbolAddress((void**)&wp, g_wp);
    cudaGetSymbolAddress((void**)&yh, g_yh); cudaGetSymbolAddress((void**)&yl, g_yl);

    const int gemm_smem = 3 * STAGE_B;                 // 72 KB (3 stages)
    cudaFuncSetAttribute(gemm_mma, cudaFuncAttributeMaxDynamicSharedMemorySize, gemm_smem);
    const int attn_smem = AT_STG_OFF + 3 * AT_STG_B;   // 160 KB
    cudaFuncSetAttribute(attn_mma, cudaFuncAttributeMaxDynamicSharedMemorySize, attn_smem);

    // 1) split x (hi/lo); convert weights (single fp16)
    {
        int n4 = T_SEQ * C_DIM / 4;
        split_fp16<<<(n4 + 255) / 256, 256>>>((const float4*)x, (uint32_t*)xh,
                                              (uint32_t*)xl, n4);
        int w4 = QKV_DIM * C_DIM / 4;
        conv_fp16<<<(w4 + 255) / 256, 256>>>((const float4*)Wa, (uint32_t*)wa, w4);
        int p4 = C_DIM * C_DIM / 4;
        conv_fp16<<<(p4 + 255) / 256, 256>>>((const float4*)Wp, (uint32_t*)wp, p4);
    }

    // 2) qkv = x @ W_attn^T
    gemm_mma<<<dim3(QKV_DIM / 128, T_SEQ / 128), 256, gemm_smem>>>(
        xh, xl, wa, qkv_p, QKV_DIM, C_DIM);

    // 3) rope + split + v transpose
    rope_qk<<<(T_SEQ * 20 * 64) / 256, 256>>>(cosb, sinb);
    v_trans<<<(NQG * 128 * T_SEQ) / 256, 256>>>();

    // 4) attention (writes yh/yl directly)
    attn_mma<<<dim3(32, NHEAD), 256, attn_smem>>>();

    // 5) out = y @ W_proj^T
    gemm_mma<<<dim3(C_DIM / 128, T_SEQ / 128), 256, gemm_smem>>>(
        yh, yl, wp, out, C_DIM, C_DIM);
}

// round 8
// speedup vs baseline: 6.3448x; 1.2953x over previous
#include <cuda_runtime.h>
#include <cuda_fp16.h>
#include <math.h>
#include <stdint.h>

#define T_SEQ 4096
#define C_DIM 2048
#define NHEAD 16
#define HS 128
#define NQG 4
#define QKV_DIM 3072
#define SCALE_LOG2 0.1275071050830161f       // (1/sqrt(128)) * log2(e)

// ---------------- scratch ----------------
__device__ float g_qkv[T_SEQ * QKV_DIM];

__device__ __half g_xh[T_SEQ * C_DIM];        // x as fp16 (single)
__device__ __half g_wa[QKV_DIM * C_DIM];
__device__ __half g_wp[C_DIM * C_DIM];

__device__ __half g_qh[T_SEQ * NHEAD * HS];   // [t][h*128+d], scaled by SCALE_LOG2
__device__ __half g_ql[T_SEQ * NHEAD * HS];   // Q lo residual (2-term QK kept)
__device__ __half g_kh[NQG * T_SEQ * HS];     // [g][t][d]
__device__ __half g_vh[NQG * HS * T_SEQ];     // [g][d][t]  (d-major)
__device__ __half g_yh[T_SEQ * C_DIM];        // attention out, fp16 single

// ---------------- PTX helpers ----------------
__device__ __forceinline__ uint32_t smem_u32(const void* p) {
    uint32_t a;
    asm("{ .reg .u64 t; cvta.to.shared.u64 t, %1; cvt.u32.u64 %0, t; }"
        : "=r"(a) : "l"(p));
    return a;
}
__device__ __forceinline__ void cp_async16(uint32_t s, const void* g) {
    asm volatile("cp.async.cg.shared.global [%0], [%1], 16;" :: "r"(s), "l"(g));
}
#define CP_COMMIT() asm volatile("cp.async.commit_group;" ::: "memory")
#define CP_WAIT(n)  asm volatile("cp.async.wait_group %0;" :: "n"(n) : "memory")

__device__ __forceinline__ void ldsm4(uint32_t* f, uint32_t a) {
    asm volatile("ldmatrix.sync.aligned.m8n8.x4.shared.b16 {%0,%1,%2,%3}, [%4];"
                 : "=r"(f[0]), "=r"(f[1]), "=r"(f[2]), "=r"(f[3]) : "r"(a));
}
__device__ __forceinline__ void mma16816(float* d, const uint32_t* a,
                                         uint32_t b0, uint32_t b1) {
    asm volatile(
        "mma.sync.aligned.m16n8k16.row.col.f32.f16.f16.f32 "
        "{%0,%1,%2,%3}, {%4,%5,%6,%7}, {%8,%9}, {%0,%1,%2,%3};"
        : "+f"(d[0]), "+f"(d[1]), "+f"(d[2]), "+f"(d[3])
        : "r"(a[0]), "r"(a[1]), "r"(a[2]), "r"(a[3]), "r"(b0), "r"(b1));
}
__device__ __forceinline__ uint32_t pack2h(float lo, float hi) {
    uint32_t r;
    asm("cvt.rn.f16x2.f32 %0, %1, %2;" : "=r"(r) : "f"(hi), "f"(lo));
    return r;
}
__device__ __forceinline__ float lo_h(uint32_t u) {
    return __half2float(__ushort_as_half((unsigned short)(u & 0xffffu)));
}
__device__ __forceinline__ float hi_h(uint32_t u) {
    return __half2float(__ushort_as_half((unsigned short)(u >> 16)));
}

// 64B-row XOR swizzle (rows of 32 halves, 4x16B chunks) — conflict-free ldmatrix phases
__device__ __forceinline__ int sw_off(int r, int c) {
    return r * 64 + ((c ^ ((r >> 1) & 3)) << 4);
}

// ---------------- fp32 -> fp16 convert, vectorized x4 ----------------
__global__ __launch_bounds__(256) void conv_fp16(const float4* __restrict__ s,
                                                 uint32_t* __restrict__ h, int n4) {
    int i = blockIdx.x * 256 + threadIdx.x;
    if (i < n4) {
        float4 v = s[i];
        h[2 * i]     = pack2h(v.x, v.y);
        h[2 * i + 1] = pack2h(v.z, v.w);
    }
}

// ---------------- mma.sync single-term fp16 GEMM: C = A * B^T ----------------
// CTA 128x128, BK=32, 8 warps (4Mx2N), 2 CTAs/SM, 3-stage pipeline, 1 sync/chunk.
#define BK 32
#define TILE_B 8192
#define STAGE_B (2 * TILE_B)   // A, B tiles per stage = 16KB

__global__ __launch_bounds__(256, 2) void gemm_mma(const __half* __restrict__ A,
                                                   const __half* __restrict__ B,
                                                   float* __restrict__ C, int N, int K) {
    extern __shared__ __align__(128) char smem[];
    int tid = threadIdx.x;
    int lane = tid & 31, w = tid >> 5;
    int bm = blockIdx.y * 128, bn = blockIdx.x * 128;
    int mw = (w & 3) * 32, nw = (w >> 2) * 64;
    uint32_t sbase = smem_u32(smem);

    float acc[2][8][4];
#pragma unroll
    for (int i = 0; i < 2; i++)
#pragma unroll
        for (int j = 0; j < 8; j++)
#pragma unroll
            for (int q = 0; q < 4; q++) acc[i][j][q] = 0.f;

    const int NC = K / BK;
    int lr = tid >> 2, lc = tid & 3;

    auto issue = [&](int c, int buf) {
        uint32_t st = sbase + buf * STAGE_B;
        int kc = c * BK;
#pragma unroll
        for (int half = 0; half < 2; half++) {
            int rr = lr + half * 64;
            int so = sw_off(rr, lc);
            size_t gA = (size_t)(bm + rr) * K + kc + lc * 8;
            size_t gB = (size_t)(bn + rr) * K + kc + lc * 8;
            cp_async16(st + so, A + gA);
            cp_async16(st + TILE_B + so, B + gB);
        }
    };

    issue(0, 0); CP_COMMIT();
    issue(1, 1); CP_COMMIT();

    int rA = mw + (lane & 15);
    int rB = nw + (lane & 15);

    for (int c = 0; c < NC; c++) {
        CP_WAIT(1);
        __syncthreads();

        uint32_t st = sbase + (c % 3) * STAGE_B;
#pragma unroll
        for (int k16 = 0; k16 < 2; k16++) {
            int cchunk = k16 * 2 + (lane >> 4);
            uint32_t ah[2][4];
            ldsm4(ah[0], st + sw_off(rA, cchunk));
            ldsm4(ah[1], st + sw_off(rA + 16, cchunk));
#pragma unroll
            for (int ni = 0; ni < 4; ni++) {
                uint32_t b[4];
                ldsm4(b, st + TILE_B + sw_off(rB + ni * 16, cchunk));
#pragma unroll
                for (int s = 0; s < 2; s++) {
                    mma16816(acc[0][ni * 2 + s], ah[0], b[s], b[2 + s]);
                    mma16816(acc[1][ni * 2 + s], ah[1], b[s], b[2 + s]);
                }
            }
        }
        if (c + 2 < NC) issue(c + 2, (c + 2) % 3);
        CP_COMMIT();
    }

    int gid = lane >> 2, q = lane & 3;
#pragma unroll
    for (int mi = 0; mi < 2; mi++)
#pragma unroll
        for (int j = 0; j < 8; j++) {
            int row = bm + mw + mi * 16 + gid;
            int col = bn + nw + j * 8 + q * 2;
            *(float2*)&C[(size_t)row * N + col] =
                make_float2(acc[mi][j][0], acc[mi][j][1]);
            *(float2*)&C[(size_t)(row + 8) * N + col] =
                make_float2(acc[mi][j][2], acc[mi][j][3]);
        }
}

// ---------------- RoPE: Q (scaled, hi/lo) + K (single) -> fp16 ----------------
__global__ __launch_bounds__(256) void rope_qk(const float* __restrict__ cosb,
                                               const float* __restrict__ sinb) {
    int idx = blockIdx.x * blockDim.x + threadIdx.x;
    if (idx >= T_SEQ * 20 * 64) return;
    int d = idx & 63;
    int h = (idx >> 6) % 20;
    int t = idx / (64 * 20);
    float c = cosb[t * 64 + d], sn = sinb[t * 64 + d];
    if (h < 16) {
        int base = t * QKV_DIM + (h >> 2) * 768 + (h & 3) * 128;
        float x1 = g_qkv[base + d], x2 = g_qkv[base + 64 + d];
        float o1 = (x1 * c - x2 * sn) * SCALE_LOG2;
        float o2 = (x2 * c + x1 * sn) * SCALE_LOG2;
        size_t o = (size_t)t * 2048 + h * 128 + d;
        __half h1 = __float2half_rn(o1);
        __half h2 = __float2half_rn(o2);
        g_qh[o] = h1;      g_ql[o] = __float2half_rn(o1 - __half2float(h1));
        g_qh[o + 64] = h2; g_ql[o + 64] = __float2half_rn(o2 - __half2float(h2));
    } else {
        int gi = h - 16;
        int base = t * QKV_DIM + gi * 768 + 512;
        float x1 = g_qkv[base + d], x2 = g_qkv[base + 64 + d];
        size_t o = ((size_t)gi * T_SEQ + t) * 128 + d;
        g_kh[o]      = __float2half_rn(x1 * c - x2 * sn);
        g_kh[o + 64] = __float2half_rn(x2 * c + x1 * sn);
    }
}

// ---------------- V transpose -> [g][d][t] fp16 ----------------
__global__ __launch_bounds__(256) void v_trans() {
    int idx = blockIdx.x * blockDim.x + threadIdx.x;
    if (idx >= NQG * 128 * T_SEQ) return;
    int t = idx & (T_SEQ - 1);
    int d = (idx >> 12) & 127;
    int gi = idx >> 19;
    float v = g_qkv[t * QKV_DIM + gi * 768 + 640 + d];
    g_vh[((size_t)gi * 128 + d) * T_SEQ + t] = __float2half_rn(v);
}

// ---------------- mma.sync flash attention ----------------
// 2-term QK (Q hi/lo), single-term PV. 3-stage KV pipeline, 1 sync/iter.
// smem: Qh[0:32K) Ql[32K:64K) stages{K 16K, V 16K} x3 at 64K. Total 160KB.
#define AT_Q_BYTES 32768
#define AT_STG_OFF 65536
#define AT_STG_B   32768

__global__ __launch_bounds__(256, 1) void attn_mma() {
    extern __shared__ __align__(128) char smem[];
    uint32_t sb = smem_u32(smem);
    int tid = threadIdx.x;
    int lane = tid & 31, w = tid >> 5;
    int qb = 31 - blockIdx.x;   // longest first
    int h = blockIdx.y;
    int g = h >> 2;
    int rw = w * 16;
    int ktmax = 2 * qb + 1;

    // ---- Q load (folded into first commit group) ----
#pragma unroll
    for (int i = 0; i < 8; i++) {
        int chunk = tid + 256 * i;
        int r = chunk >> 4, cd = chunk & 15;
        size_t src = (size_t)(qb * 128 + r) * 2048 + h * 128 + cd * 8;
        uint32_t dst = sb + (cd >> 2) * 8192 + sw_off(r, cd & 3);
        cp_async16(dst, g_qh + src);
        cp_async16(dst + AT_Q_BYTES, g_ql + src);
    }

    auto issueKV = [&](int kt, int stg) {
        uint32_t st = sb + AT_STG_OFF + stg * AT_STG_B;
#pragma unroll
        for (int i = 0; i < 4; i++) {
            int chunk = tid + 256 * i;
            int r = chunk >> 4, cd = chunk & 15;
            size_t src = ((size_t)g * T_SEQ + kt * 64 + r) * 128 + cd * 8;
            uint32_t dst = st + (cd >> 2) * 4096 + sw_off(r, cd & 3);
            cp_async16(dst, g_kh + src);
        }
#pragma unroll
        for (int i = 0; i < 4; i++) {
            int chunk = tid + 256 * i;
            int d = chunk >> 3, sc = chunk & 7;
            size_t src = ((size_t)g * 128 + d) * T_SEQ + kt * 64 + sc * 8;
            uint32_t dst = st + 16384 + (sc >> 2) * 8192 + sw_off(d, sc & 3);
            cp_async16(dst, g_vh + src);
        }
    };

    issueKV(0, 0); CP_COMMIT();
    issueKV(1, 1); CP_COMMIT();   // ktmax >= 1 always

    float oacc[16][4];
#pragma unroll
    for (int i = 0; i < 16; i++)
#pragma unroll
        for (int j = 0; j < 4; j++) oacc[i][j] = 0.f;
    float mi0 = -1e30f, mi1 = -1e30f, li0 = 0.f, li1 = 0.f;

    int rK = lane & 15, cH = lane >> 4;
    int qr1 = qb * 128 + rw + (lane >> 2);

    for (int kt = 0; kt <= ktmax; kt++) {
        CP_WAIT(1);
        __syncthreads();

        uint32_t KH = sb + AT_STG_OFF + (kt % 3) * AT_STG_B;
        uint32_t VH = KH + 16384;

        // ---- S = (Qh+Ql) K^T (log2-scaled) ----
        float s[8][4];
#pragma unroll
        for (int j = 0; j < 8; j++)
#pragma unroll
            for (int e = 0; e < 4; e++) s[j][e] = 0.f;

#pragma unroll
        for (int kk = 0; kk < 8; kk++) {
            int c = ((kk & 1) << 1) + cH;
            uint32_t qpan = sb + (kk >> 1) * 8192;
            uint32_t ah[4], al2[4];
            ldsm4(ah, qpan + sw_off(rw + rK, c));
            ldsm4(al2, qpan + AT_Q_BYTES + sw_off(rw + rK, c));
            uint32_t kpan = (kk >> 1) * 4096;
#pragma unroll
            for (int ni = 0; ni < 4; ni++) {
                uint32_t kh4[4];
                ldsm4(kh4, KH + kpan + sw_off(ni * 16 + rK, c));
#pragma unroll
                for (int ss = 0; ss < 2; ss++) {
                    mma16816(s[ni * 2 + ss], ah, kh4[ss], kh4[2 + ss]);
                    mma16816(s[ni * 2 + ss], al2, kh4[ss], kh4[2 + ss]);
                }
            }
        }

        // ---- causal mask (diagonal CTA tiles only) ----
        if (kt >= 2 * qb) {
            int colb = kt * 64 + ((lane & 3) << 1);
#pragma unroll
            for (int j = 0; j < 8; j++) {
                int c0 = colb + j * 8;
                if (c0 > qr1)     s[j][0] = -1e30f;
                if (c0 + 1 > qr1) s[j][1] = -1e30f;
                if (c0 > qr1 + 8)     s[j][2] = -1e30f;
                if (c0 + 1 > qr1 + 8) s[j][3] = -1e30f;
            }
        }

        // ---- online softmax (base-2) ----
        float mx0 = -1e30f, mx1 = -1e30f;
#pragma unroll
        for (int j = 0; j < 8; j++) {
            mx0 = fmaxf(mx0, fmaxf(s[j][0], s[j][1]));
            mx1 = fmaxf(mx1, fmaxf(s[j][2], s[j][3]));
        }
        mx0 = fmaxf(mx0, __shfl_xor_sync(0xffffffffu, mx0, 1));
        mx0 = fmaxf(mx0, __shfl_xor_sync(0xffffffffu, mx0, 2));
        mx1 = fmaxf(mx1, __shfl_xor_sync(0xffffffffu, mx1, 1));
        mx1 = fmaxf(mx1, __shfl_xor_sync(0xffffffffu, mx1, 2));
        float mn0 = fmaxf(mi0, mx0), mn1 = fmaxf(mi1, mx1);
        float a0 = exp2f(mi0 - mn0), a1 = exp2f(mi1 - mn1);
        mi0 = mn0; mi1 = mn1;
        float sum0 = 0.f, sum1 = 0.f;
#pragma unroll
        for (int j = 0; j < 8; j++) {
            s[j][0] = exp2f(s[j][0] - mn0);
            s[j][1] = exp2f(s[j][1] - mn0);
            s[j][2] = exp2f(s[j][2] - mn1);
            s[j][3] = exp2f(s[j][3] - mn1);
            sum0 += s[j][0] + s[j][1];
            sum1 += s[j][2] + s[j][3];
        }
        sum0 += __shfl_xor_sync(0xffffffffu, sum0, 1);
        sum0 += __shfl_xor_sync(0xffffffffu, sum0, 2);
        sum1 += __shfl_xor_sync(0xffffffffu, sum1, 1);
        sum1 += __shfl_xor_sync(0xffffffffu, sum1, 2);
        li0 = li0 * a0 + sum0;
        li1 = li1 * a1 + sum1;
        if (a0 != 1.f || a1 != 1.f) {
#pragma unroll
            for (int ni = 0; ni < 16; ni++) {
                oacc[ni][0] *= a0; oacc[ni][1] *= a0;
                oacc[ni][2] *= a1; oacc[ni][3] *= a1;
            }
        }

        // ---- O += P V (single term), P from registers ----
#pragma unroll
        for (int kk2 = 0; kk2 < 4; kk2++) {
            uint32_t hp[4];
            {
                float* p0 = s[2 * kk2];
                float* p1 = s[2 * kk2 + 1];
                hp[0] = pack2h(p0[0], p0[1]);
                hp[1] = pack2h(p0[2], p0[3]);
                hp[2] = pack2h(p1[0], p1[1]);
                hp[3] = pack2h(p1[2], p1[3]);
            }
            int c = ((kk2 & 1) << 1) + cH;
            uint32_t vpan = (kk2 >> 1) * 8192;
#pragma unroll
            for (int ni = 0; ni < 8; ni++) {
                uint32_t vh4[4];
                ldsm4(vh4, VH + vpan + sw_off(ni * 16 + rK, c));
#pragma unroll
                for (int ss = 0; ss < 2; ss++)
                    mma16816(oacc[ni * 2 + ss], hp, vh4[ss], vh4[2 + ss]);
            }
        }

        if (kt + 2 <= ktmax) issueKV(kt + 2, (kt + 2) % 3);
        CP_COMMIT();
    }

    // ---- epilogue: O/l -> fp16 (single) ----
    float inv0 = 1.f / li0, inv1 = 1.f / li1;
    size_t row1 = (size_t)qr1 * 2048 + h * 128;
    size_t row2 = row1 + (size_t)8 * 2048;
#pragma unroll
    for (int ni = 0; ni < 16; ni++) {
        int colo = ni * 8 + ((lane & 3) << 1);
        *(uint32_t*)&g_yh[row1 + colo] = pack2h(oacc[ni][0] * inv0, oacc[ni][1] * inv0);
        *(uint32_t*)&g_yh[row2 + colo] = pack2h(oacc[ni][2] * inv1, oacc[ni][3] * inv1);
    }
}

// ---------------- launch ----------------
extern "C" void kernel_launch(void* const* d_in, const int* in_sizes, int n_in,
                              void* d_out, int out_size) {
    const float* x    = (const float*)d_in[0];
    const float* cosb = (const float*)d_in[1];
    const float* sinb = (const float*)d_in[2];
    const float* Wa   = (const float*)d_in[3];
    const float* Wp   = (const float*)d_in[4];
    float* out = (float*)d_out;

    float* qkv_p;
    cudaGetSymbolAddress((void**)&qkv_p, g_qkv);
    __half *xh, *wa, *wp, *yh;
    cudaGetSymbolAddress((void**)&xh, g_xh);
    cudaGetSymbolAddress((void**)&wa, g_wa);
    cudaGetSymbolAddress((void**)&wp, g_wp);
    cudaGetSymbolAddress((void**)&yh, g_yh);

    const int gemm_smem = 3 * STAGE_B;                 // 48 KB (3 stages)
    cudaFuncSetAttribute(gemm_mma, cudaFuncAttributeMaxDynamicSharedMemorySize, gemm_smem);
    const int attn_smem = AT_STG_OFF + 3 * AT_STG_B;   // 160 KB
    cudaFuncSetAttribute(attn_mma, cudaFuncAttributeMaxDynamicSharedMemorySize, attn_smem);

    // 1) convert x and weights to fp16
    {
        int n4 = T_SEQ * C_DIM / 4;
        conv_fp16<<<(n4 + 255) / 256, 256>>>((const float4*)x, (uint32_t*)xh, n4);
        int w4 = QKV_DIM * C_DIM / 4;
        conv_fp16<<<(w4 + 255) / 256, 256>>>((const float4*)Wa, (uint32_t*)wa, w4);
        int p4 = C_DIM * C_DIM / 4;
        conv_fp16<<<(p4 + 255) / 256, 256>>>((const float4*)Wp, (uint32_t*)wp, p4);
    }

    // 2) qkv = x @ W_attn^T (single-term fp16)
    gemm_mma<<<dim3(QKV_DIM / 128, T_SEQ / 128), 256, gemm_smem>>>(
        xh, wa, qkv_p, QKV_DIM, C_DIM);

    // 3) rope + split + v transpose
    rope_qk<<<(T_SEQ * 20 * 64) / 256, 256>>>(cosb, sinb);
    v_trans<<<(NQG * 128 * T_SEQ) / 256, 256>>>();

    // 4) attention (writes yh directly)
    attn_mma<<<dim3(32, NHEAD), 256, attn_smem>>>();

    // 5) out = y @ W_proj^T (single-term fp16)
    gemm_mma<<<dim3(C_DIM / 128, T_SEQ / 128), 256, gemm_smem>>>(
        yh, wp, out, C_DIM, C_DIM);
}

// round 9
// speedup vs baseline: 6.6191x; 1.0432x over previous
#include <cuda_runtime.h>
#include <cuda_fp16.h>
#include <math.h>
#include <stdint.h>

#define T_SEQ 4096
#define C_DIM 2048
#define NHEAD 16
#define HS 128
#define NQG 4
#define QKV_DIM 3072
#define SCALE_LOG2 0.1275071050830161f       // (1/sqrt(128)) * log2(e)

// ---------------- scratch ----------------
__device__ float g_qkv[T_SEQ * QKV_DIM];

__device__ __half g_xh[T_SEQ * C_DIM];        // x as fp16 (single)
__device__ __half g_wa[QKV_DIM * C_DIM];
__device__ __half g_wp[C_DIM * C_DIM];

__device__ __half g_qh[T_SEQ * NHEAD * HS];   // [t][h*128+d], scaled by SCALE_LOG2
__device__ __half g_ql[T_SEQ * NHEAD * HS];   // Q lo residual (2-term QK kept)
__device__ __half g_kh[NQG * T_SEQ * HS];     // [g][t][d]
__device__ __half g_vh[NQG * HS * T_SEQ];     // [g][d][t]  (d-major)
__device__ __half g_yh[T_SEQ * C_DIM];        // attention out, fp16 single

// ---------------- PTX helpers ----------------
__device__ __forceinline__ uint32_t smem_u32(const void* p) {
    uint32_t a;
    asm("{ .reg .u64 t; cvta.to.shared.u64 t, %1; cvt.u32.u64 %0, t; }"
        : "=r"(a) : "l"(p));
    return a;
}
__device__ __forceinline__ void cp_async16(uint32_t s, const void* g) {
    asm volatile("cp.async.cg.shared.global [%0], [%1], 16;" :: "r"(s), "l"(g));
}
#define CP_COMMIT() asm volatile("cp.async.commit_group;" ::: "memory")
#define CP_WAIT(n)  asm volatile("cp.async.wait_group %0;" :: "n"(n) : "memory")

__device__ __forceinline__ void ldsm4(uint32_t* f, uint32_t a) {
    asm volatile("ldmatrix.sync.aligned.m8n8.x4.shared.b16 {%0,%1,%2,%3}, [%4];"
                 : "=r"(f[0]), "=r"(f[1]), "=r"(f[2]), "=r"(f[3]) : "r"(a));
}
__device__ __forceinline__ void mma16816(float* d, const uint32_t* a,
                                         uint32_t b0, uint32_t b1) {
    asm volatile(
        "mma.sync.aligned.m16n8k16.row.col.f32.f16.f16.f32 "
        "{%0,%1,%2,%3}, {%4,%5,%6,%7}, {%8,%9}, {%0,%1,%2,%3};"
        : "+f"(d[0]), "+f"(d[1]), "+f"(d[2]), "+f"(d[3])
        : "r"(a[0]), "r"(a[1]), "r"(a[2]), "r"(a[3]), "r"(b0), "r"(b1));
}
__device__ __forceinline__ uint32_t pack2h(float lo, float hi) {
    uint32_t r;
    asm("cvt.rn.f16x2.f32 %0, %1, %2;" : "=r"(r) : "f"(hi), "f"(lo));
    return r;
}

// 64B-row XOR swizzle (rows of 32 halves, 4x16B chunks) — conflict-free ldmatrix phases
__device__ __forceinline__ int sw_off(int r, int c) {
    return r * 64 + ((c ^ ((r >> 1) & 3)) << 4);
}

// ---------------- fp32 -> fp16 convert, vectorized x4 ----------------
__global__ __launch_bounds__(256) void conv_fp16(const float4* __restrict__ s,
                                                 uint32_t* __restrict__ h, int n4) {
    int i = blockIdx.x * 256 + threadIdx.x;
    if (i < n4) {
        float4 v = s[i];
        h[2 * i]     = pack2h(v.x, v.y);
        h[2 * i + 1] = pack2h(v.z, v.w);
    }
}

// ---------------- mma.sync single-term fp16 GEMM: C = A * B^T ----------------
// CTA 128x128, BK=32, 8 warps (4Mx2N), 2 CTAs/SM, 4-stage pipeline, 1 sync/chunk.
#define BK 32
#define TILE_B 8192
#define STAGE_B (2 * TILE_B)   // A, B tiles per stage = 16KB

__global__ __launch_bounds__(256, 2) void gemm_mma(const __half* __restrict__ A,
                                                   const __half* __restrict__ B,
                                                   float* __restrict__ C, int N, int K) {
    extern __shared__ __align__(128) char smem[];
    int tid = threadIdx.x;
    int lane = tid & 31, w = tid >> 5;
    int bm = blockIdx.y * 128, bn = blockIdx.x * 128;
    int mw = (w & 3) * 32, nw = (w >> 2) * 64;
    uint32_t sbase = smem_u32(smem);

    float acc[2][8][4];
#pragma unroll
    for (int i = 0; i < 2; i++)
#pragma unroll
        for (int j = 0; j < 8; j++)
#pragma unroll
            for (int q = 0; q < 4; q++) acc[i][j][q] = 0.f;

    const int NC = K / BK;
    int lr = tid >> 2, lc = tid & 3;

    auto issue = [&](int c, int buf) {
        uint32_t st = sbase + buf * STAGE_B;
        int kc = c * BK;
#pragma unroll
        for (int half = 0; half < 2; half++) {
            int rr = lr + half * 64;
            int so = sw_off(rr, lc);
            size_t gA = (size_t)(bm + rr) * K + kc + lc * 8;
            size_t gB = (size_t)(bn + rr) * K + kc + lc * 8;
            cp_async16(st + so, A + gA);
            cp_async16(st + TILE_B + so, B + gB);
        }
    };

    issue(0, 0); CP_COMMIT();
    issue(1, 1); CP_COMMIT();
    issue(2, 2); CP_COMMIT();

    int rA = mw + (lane & 15);
    int rB = nw + (lane & 15);

    for (int c = 0; c < NC; c++) {
        CP_WAIT(2);
        __syncthreads();

        uint32_t st = sbase + (c & 3) * STAGE_B;
#pragma unroll
        for (int k16 = 0; k16 < 2; k16++) {
            int cchunk = k16 * 2 + (lane >> 4);
            uint32_t ah[2][4];
            ldsm4(ah[0], st + sw_off(rA, cchunk));
            ldsm4(ah[1], st + sw_off(rA + 16, cchunk));
#pragma unroll
            for (int ni = 0; ni < 4; ni++) {
                uint32_t b[4];
                ldsm4(b, st + TILE_B + sw_off(rB + ni * 16, cchunk));
#pragma unroll
                for (int s = 0; s < 2; s++) {
                    mma16816(acc[0][ni * 2 + s], ah[0], b[s], b[2 + s]);
                    mma16816(acc[1][ni * 2 + s], ah[1], b[s], b[2 + s]);
                }
            }
        }
        if (c + 3 < NC) issue(c + 3, (c + 3) & 3);
        CP_COMMIT();
    }

    int gid = lane >> 2, q = lane & 3;
#pragma unroll
    for (int mi = 0; mi < 2; mi++)
#pragma unroll
        for (int j = 0; j < 8; j++) {
            int row = bm + mw + mi * 16 + gid;
            int col = bn + nw + j * 8 + q * 2;
            *(float2*)&C[(size_t)row * N + col] =
                make_float2(acc[mi][j][0], acc[mi][j][1]);
            *(float2*)&C[(size_t)(row + 8) * N + col] =
                make_float2(acc[mi][j][2], acc[mi][j][3]);
        }
}

// ---------------- RoPE: Q (scaled, hi/lo) + K (single) -> fp16 ----------------
__global__ __launch_bounds__(256) void rope_qk(const float* __restrict__ cosb,
                                               const float* __restrict__ sinb) {
    int idx = blockIdx.x * blockDim.x + threadIdx.x;
    if (idx >= T_SEQ * 20 * 64) return;
    int d = idx & 63;
    int h = (idx >> 6) % 20;
    int t = idx / (64 * 20);
    float c = cosb[t * 64 + d], sn = sinb[t * 64 + d];
    if (h < 16) {
        int base = t * QKV_DIM + (h >> 2) * 768 + (h & 3) * 128;
        float x1 = g_qkv[base + d], x2 = g_qkv[base + 64 + d];
        float o1 = (x1 * c - x2 * sn) * SCALE_LOG2;
        float o2 = (x2 * c + x1 * sn) * SCALE_LOG2;
        size_t o = (size_t)t * 2048 + h * 128 + d;
        __half h1 = __float2half_rn(o1);
        __half h2 = __float2half_rn(o2);
        g_qh[o] = h1;      g_ql[o] = __float2half_rn(o1 - __half2float(h1));
        g_qh[o + 64] = h2; g_ql[o + 64] = __float2half_rn(o2 - __half2float(h2));
    } else {
        int gi = h - 16;
        int base = t * QKV_DIM + gi * 768 + 512;
        float x1 = g_qkv[base + d], x2 = g_qkv[base + 64 + d];
        size_t o = ((size_t)gi * T_SEQ + t) * 128 + d;
        g_kh[o]      = __float2half_rn(x1 * c - x2 * sn);
        g_kh[o + 64] = __float2half_rn(x2 * c + x1 * sn);
    }
}

// ---------------- V transpose -> [g][d][t] fp16 ----------------
__global__ __launch_bounds__(256) void v_trans() {
    int idx = blockIdx.x * blockDim.x + threadIdx.x;
    if (idx >= NQG * 128 * T_SEQ) return;
    int t = idx & (T_SEQ - 1);
    int d = (idx >> 12) & 127;
    int gi = idx >> 19;
    float v = g_qkv[t * QKV_DIM + gi * 768 + 640 + d];
    g_vh[((size_t)gi * 128 + d) * T_SEQ + t] = __float2half_rn(v);
}

// ---------------- mma.sync flash attention ----------------
// 64 q-rows/CTA, 4 warps (16 rows each), Bc=64, 2-stage KV, 2 CTAs/SM.
// smem: Qh[0:16K) Ql[16K:32K) stages{K 16K, V 16K} x2 at 32K. Total 96KB.
#define AT_Q_BYTES 16384
#define AT_STG_OFF 32768
#define AT_STG_B   32768

__global__ __launch_bounds__(128, 2) void attn_mma() {
    extern __shared__ __align__(128) char smem[];
    uint32_t sb = smem_u32(smem);
    int tid = threadIdx.x;
    int lane = tid & 31, w = tid >> 5;          // 4 warps
    int qb = 63 - blockIdx.x;                   // longest first
    int h = blockIdx.y;
    int g = h >> 2;
    int rw = w * 16;
    int ktmax = qb;

    // ---- Q load (64 rows, hi+lo; folded into first commit group) ----
#pragma unroll
    for (int i = 0; i < 8; i++) {
        int chunk = tid + 128 * i;              // 0..1023
        int r = chunk >> 4, cd = chunk & 15;
        size_t src = (size_t)(qb * 64 + r) * 2048 + h * 128 + cd * 8;
        uint32_t dst = sb + (cd >> 2) * 4096 + sw_off(r, cd & 3);
        cp_async16(dst, g_qh + src);
        cp_async16(dst + AT_Q_BYTES, g_ql + src);
    }

    auto issueKV = [&](int kt, int stg) {
        uint32_t st = sb + AT_STG_OFF + stg * AT_STG_B;
#pragma unroll
        for (int i = 0; i < 8; i++) {
            int chunk = tid + 128 * i;          // 0..1023
            int r = chunk >> 4, cd = chunk & 15;
            size_t src = ((size_t)g * T_SEQ + kt * 64 + r) * 128 + cd * 8;
            uint32_t dst = st + (cd >> 2) * 4096 + sw_off(r, cd & 3);
            cp_async16(dst, g_kh + src);
        }
#pragma unroll
        for (int i = 0; i < 8; i++) {
            int chunk = tid + 128 * i;
            int d = chunk >> 3, sc = chunk & 7;
            size_t src = ((size_t)g * 128 + d) * T_SEQ + kt * 64 + sc * 8;
            uint32_t dst = st + 16384 + (sc >> 2) * 8192 + sw_off(d, sc & 3);
            cp_async16(dst, g_vh + src);
        }
    };

    issueKV(0, 0); CP_COMMIT();
    if (1 <= ktmax) issueKV(1, 1);
    CP_COMMIT();

    float oacc[16][4];
#pragma unroll
    for (int i = 0; i < 16; i++)
#pragma unroll
        for (int j = 0; j < 4; j++) oacc[i][j] = 0.f;
    float mi0 = -1e30f, mi1 = -1e30f, li0 = 0.f, li1 = 0.f;

    int rK = lane & 15, cH = lane >> 4;
    int qr1 = qb * 64 + rw + (lane >> 2);

    for (int kt = 0; kt <= ktmax; kt++) {
        CP_WAIT(1);
        __syncthreads();

        uint32_t KH = sb + AT_STG_OFF + (kt & 1) * AT_STG_B;
        uint32_t VH = KH + 16384;

        // ---- S = (Qh+Ql) K^T (log2-scaled) ----
        float s[8][4];
#pragma unroll
        for (int j = 0; j < 8; j++)
#pragma unroll
            for (int e = 0; e < 4; e++) s[j][e] = 0.f;

#pragma unroll
        for (int kk = 0; kk < 8; kk++) {
            int c = ((kk & 1) << 1) + cH;
            uint32_t qpan = sb + (kk >> 1) * 4096;
            uint32_t ah[4], al2[4];
            ldsm4(ah, qpan + sw_off(rw + rK, c));
            ldsm4(al2, qpan + AT_Q_BYTES + sw_off(rw + rK, c));
            uint32_t kpan = (kk >> 1) * 4096;
#pragma unroll
            for (int ni = 0; ni < 4; ni++) {
                uint32_t kh4[4];
                ldsm4(kh4, KH + kpan + sw_off(ni * 16 + rK, c));
#pragma unroll
                for (int ss = 0; ss < 2; ss++) {
                    mma16816(s[ni * 2 + ss], ah, kh4[ss], kh4[2 + ss]);
                    mma16816(s[ni * 2 + ss], al2, kh4[ss], kh4[2 + ss]);
                }
            }
        }

        // ---- causal mask (diagonal tile only: kt == qb) ----
        if (kt == qb) {
            int colb = kt * 64 + ((lane & 3) << 1);
#pragma unroll
            for (int j = 0; j < 8; j++) {
                int c0 = colb + j * 8;
                if (c0 > qr1)     s[j][0] = -1e30f;
                if (c0 + 1 > qr1) s[j][1] = -1e30f;
                if (c0 > qr1 + 8)     s[j][2] = -1e30f;
                if (c0 + 1 > qr1 + 8) s[j][3] = -1e30f;
            }
        }

        // ---- online softmax (base-2) ----
        float mx0 = -1e30f, mx1 = -1e30f;
#pragma unroll
        for (int j = 0; j < 8; j++) {
            mx0 = fmaxf(mx0, fmaxf(s[j][0], s[j][1]));
            mx1 = fmaxf(mx1, fmaxf(s[j][2], s[j][3]));
        }
        mx0 = fmaxf(mx0, __shfl_xor_sync(0xffffffffu, mx0, 1));
        mx0 = fmaxf(mx0, __shfl_xor_sync(0xffffffffu, mx0, 2));
        mx1 = fmaxf(mx1, __shfl_xor_sync(0xffffffffu, mx1, 1));
        mx1 = fmaxf(mx1, __shfl_xor_sync(0xffffffffu, mx1, 2));
        float mn0 = fmaxf(mi0, mx0), mn1 = fmaxf(mi1, mx1);
        float a0 = exp2f(mi0 - mn0), a1 = exp2f(mi1 - mn1);
        mi0 = mn0; mi1 = mn1;
        float sum0 = 0.f, sum1 = 0.f;
#pragma unroll
        for (int j = 0; j < 8; j++) {
            s[j][0] = exp2f(s[j][0] - mn0);
            s[j][1] = exp2f(s[j][1] - mn0);
            s[j][2] = exp2f(s[j][2] - mn1);
            s[j][3] = exp2f(s[j][3] - mn1);
            sum0 += s[j][0] + s[j][1];
            sum1 += s[j][2] + s[j][3];
        }
        sum0 += __shfl_xor_sync(0xffffffffu, sum0, 1);
        sum0 += __shfl_xor_sync(0xffffffffu, sum0, 2);
        sum1 += __shfl_xor_sync(0xffffffffu, sum1, 1);
        sum1 += __shfl_xor_sync(0xffffffffu, sum1, 2);
        li0 = li0 * a0 + sum0;
        li1 = li1 * a1 + sum1;
        if (a0 != 1.f || a1 != 1.f) {
#pragma unroll
            for (int ni = 0; ni < 16; ni++) {
                oacc[ni][0] *= a0; oacc[ni][1] *= a0;
                oacc[ni][2] *= a1; oacc[ni][3] *= a1;
            }
        }

        // ---- O += P V (single term), P from registers ----
#pragma unroll
        for (int kk2 = 0; kk2 < 4; kk2++) {
            uint32_t hp[4];
            {
                float* p0 = s[2 * kk2];
                float* p1 = s[2 * kk2 + 1];
                hp[0] = pack2h(p0[0], p0[1]);
                hp[1] = pack2h(p0[2], p0[3]);
                hp[2] = pack2h(p1[0], p1[1]);
                hp[3] = pack2h(p1[2], p1[3]);
            }
            int c = ((kk2 & 1) << 1) + cH;
            uint32_t vpan = (kk2 >> 1) * 8192;
#pragma unroll
            for (int ni = 0; ni < 8; ni++) {
                uint32_t vh4[4];
                ldsm4(vh4, VH + vpan + sw_off(ni * 16 + rK, c));
#pragma unroll
                for (int ss = 0; ss < 2; ss++)
                    mma16816(oacc[ni * 2 + ss], hp, vh4[ss], vh4[2 + ss]);
            }
        }

        __syncthreads();   // all warps done reading stage (kt&1) before reuse
        if (kt + 2 <= ktmax) issueKV(kt + 2, (kt + 2) & 1);
        CP_COMMIT();
    }

    // ---- epilogue: O/l -> fp16 (single) ----
    float inv0 = 1.f / li0, inv1 = 1.f / li1;
    size_t row1 = (size_t)qr1 * 2048 + h * 128;
    size_t row2 = row1 + (size_t)8 * 2048;
#pragma unroll
    for (int ni = 0; ni < 16; ni++) {
        int colo = ni * 8 + ((lane & 3) << 1);
        *(uint32_t*)&g_yh[row1 + colo] = pack2h(oacc[ni][0] * inv0, oacc[ni][1] * inv0);
        *(uint32_t*)&g_yh[row2 + colo] = pack2h(oacc[ni][2] * inv1, oacc[ni][3] * inv1);
    }
}

// ---------------- launch ----------------
extern "C" void kernel_launch(void* const* d_in, const int* in_sizes, int n_in,
                              void* d_out, int out_size) {
    const float* x    = (const float*)d_in[0];
    const float* cosb = (const float*)d_in[1];
    const float* sinb = (const float*)d_in[2];
    const float* Wa   = (const float*)d_in[3];
    const float* Wp   = (const float*)d_in[4];
    float* out = (float*)d_out;

    float* qkv_p;
    cudaGetSymbolAddress((void**)&qkv_p, g_qkv);
    __half *xh, *wa, *wp, *yh;
    cudaGetSymbolAddress((void**)&xh, g_xh);
    cudaGetSymbolAddress((void**)&wa, g_wa);
    cudaGetSymbolAddress((void**)&wp, g_wp);
    cudaGetSymbolAddress((void**)&yh, g_yh);

    const int gemm_smem = 4 * STAGE_B;                 // 64 KB (4 stages)
    cudaFuncSetAttribute(gemm_mma, cudaFuncAttributeMaxDynamicSharedMemorySize, gemm_smem);
    const int attn_smem = AT_STG_OFF + 2 * AT_STG_B;   // 96 KB
    cudaFuncSetAttribute(attn_mma, cudaFuncAttributeMaxDynamicSharedMemorySize, attn_smem);

    // 1) convert x and weights to fp16
    {
        int n4 = T_SEQ * C_DIM / 4;
        conv_fp16<<<(n4 + 255) / 256, 256>>>((const float4*)x, (uint32_t*)xh, n4);
        int w4 = QKV_DIM * C_DIM / 4;
        conv_fp16<<<(w4 + 255) / 256, 256>>>((const float4*)Wa, (uint32_t*)wa, w4);
        int p4 = C_DIM * C_DIM / 4;
        conv_fp16<<<(p4 + 255) / 256, 256>>>((const float4*)Wp, (uint32_t*)wp, p4);
    }

    // 2) qkv = x @ W_attn^T (single-term fp16)
    gemm_mma<<<dim3(QKV_DIM / 128, T_SEQ / 128), 256, gemm_smem>>>(
        xh, wa, qkv_p, QKV_DIM, C_DIM);

    // 3) rope + split + v transpose
    rope_qk<<<(T_SEQ * 20 * 64) / 256, 256>>>(cosb, sinb);
    v_trans<<<(NQG * 128 * T_SEQ) / 256, 256>>>();

    // 4) attention (64-row CTAs, 2 CTAs/SM)
    attn_mma<<<dim3(64, NHEAD), 128, attn_smem>>>();

    // 5) out = y @ W_proj^T (single-term fp16)
    gemm_mma<<<dim3(C_DIM / 128, T_SEQ / 128), 256, gemm_smem>>>(
        yh, wp, out, C_DIM, C_DIM);
}

// round 10
// speedup vs baseline: 7.4663x; 1.1280x over previous
#include <cuda_runtime.h>
#include <cuda_fp16.h>
#include <math.h>
#include <stdint.h>

#define T_SEQ 4096
#define C_DIM 2048
#define NHEAD 16
#define HS 128
#define NQG 4
#define QKV_DIM 3072
#define SCALE_LOG2 0.1275071050830161f       // (1/sqrt(128)) * log2(e)

// ---------------- scratch ----------------
__device__ float g_qkv[T_SEQ * QKV_DIM];

__device__ __half g_xh[T_SEQ * C_DIM];        // x as fp16
__device__ __half g_wa[QKV_DIM * C_DIM];
__device__ __half g_wp[C_DIM * C_DIM];

__device__ __half g_qh[T_SEQ * NHEAD * HS];   // [t][h*128+d], scaled by SCALE_LOG2
__device__ __half g_kh[NQG * T_SEQ * HS];     // [g][t][d]
__device__ __half g_vh[NQG * HS * T_SEQ];     // [g][d][t]  (d-major)
__device__ __half g_yh[T_SEQ * C_DIM];        // attention out, fp16

// ---------------- PTX helpers ----------------
__device__ __forceinline__ uint32_t smem_u32(const void* p) {
    uint32_t a;
    asm("{ .reg .u64 t; cvta.to.shared.u64 t, %1; cvt.u32.u64 %0, t; }"
        : "=r"(a) : "l"(p));
    return a;
}
__device__ __forceinline__ void cp_async16(uint32_t s, const void* g) {
    asm volatile("cp.async.cg.shared.global [%0], [%1], 16;" :: "r"(s), "l"(g));
}
#define CP_COMMIT() asm volatile("cp.async.commit_group;" ::: "memory")
#define CP_WAIT(n)  asm volatile("cp.async.wait_group %0;" :: "n"(n) : "memory")

__device__ __forceinline__ void ldsm4(uint32_t* f, uint32_t a) {
    asm volatile("ldmatrix.sync.aligned.m8n8.x4.shared.b16 {%0,%1,%2,%3}, [%4];"
                 : "=r"(f[0]), "=r"(f[1]), "=r"(f[2]), "=r"(f[3]) : "r"(a));
}
__device__ __forceinline__ void mma16816(float* d, const uint32_t* a,
                                         uint32_t b0, uint32_t b1) {
    asm volatile(
        "mma.sync.aligned.m16n8k16.row.col.f32.f16.f16.f32 "
        "{%0,%1,%2,%3}, {%4,%5,%6,%7}, {%8,%9}, {%0,%1,%2,%3};"
        : "+f"(d[0]), "+f"(d[1]), "+f"(d[2]), "+f"(d[3])
        : "r"(a[0]), "r"(a[1]), "r"(a[2]), "r"(a[3]), "r"(b0), "r"(b1));
}
__device__ __forceinline__ uint32_t pack2h(float lo, float hi) {
    uint32_t r;
    asm("cvt.rn.f16x2.f32 %0, %1, %2;" : "=r"(r) : "f"(hi), "f"(lo));
    return r;
}

// 64B-row XOR swizzle (rows of 32 halves, 4x16B chunks) — conflict-free ldmatrix phases
__device__ __forceinline__ int sw_off(int r, int c) {
    return r * 64 + ((c ^ ((r >> 1) & 3)) << 4);
}

// ---------------- fp32 -> fp16 convert, vectorized x4 ----------------
__global__ __launch_bounds__(256) void conv_fp16(const float4* __restrict__ s,
                                                 uint32_t* __restrict__ h, int n4) {
    int i = blockIdx.x * 256 + threadIdx.x;
    if (i < n4) {
        float4 v = s[i];
        h[2 * i]     = pack2h(v.x, v.y);
        h[2 * i + 1] = pack2h(v.z, v.w);
    }
}

// ---------------- mma.sync fp16 GEMM: C = A * B^T ----------------
// CTA 128x128, BK=32, 8 warps (4Mx2N), 2 CTAs/SM, 4-stage pipeline, 1 sync/chunk.
// All 6 ldsm per k16 batched before the 16-mma burst (RAW-stall reduction).
#define BK 32
#define TILE_B 8192
#define STAGE_B (2 * TILE_B)

__global__ __launch_bounds__(256, 2) void gemm_mma(const __half* __restrict__ A,
                                                   const __half* __restrict__ B,
                                                   float* __restrict__ C, int N, int K) {
    extern __shared__ __align__(128) char smem[];
    int tid = threadIdx.x;
    int lane = tid & 31, w = tid >> 5;
    int bm = blockIdx.y * 128, bn = blockIdx.x * 128;
    int mw = (w & 3) * 32, nw = (w >> 2) * 64;
    uint32_t sbase = smem_u32(smem);

    float acc[2][8][4];
#pragma unroll
    for (int i = 0; i < 2; i++)
#pragma unroll
        for (int j = 0; j < 8; j++)
#pragma unroll
            for (int q = 0; q < 4; q++) acc[i][j][q] = 0.f;

    const int NC = K / BK;
    int lr = tid >> 2, lc = tid & 3;

    auto issue = [&](int c, int buf) {
        uint32_t st = sbase + buf * STAGE_B;
        int kc = c * BK;
#pragma unroll
        for (int half = 0; half < 2; half++) {
            int rr = lr + half * 64;
            int so = sw_off(rr, lc);
            size_t gA = (size_t)(bm + rr) * K + kc + lc * 8;
            size_t gB = (size_t)(bn + rr) * K + kc + lc * 8;
            cp_async16(st + so, A + gA);
            cp_async16(st + TILE_B + so, B + gB);
        }
    };

    issue(0, 0); CP_COMMIT();
    issue(1, 1); CP_COMMIT();
    issue(2, 2); CP_COMMIT();

    int rA = mw + (lane & 15);
    int rB = nw + (lane & 15);

    for (int c = 0; c < NC; c++) {
        CP_WAIT(2);
        __syncthreads();

        uint32_t st = sbase + (c & 3) * STAGE_B;
#pragma unroll
        for (int k16 = 0; k16 < 2; k16++) {
            int cchunk = k16 * 2 + (lane >> 4);
            uint32_t ah[2][4], b[4][4];
            ldsm4(ah[0], st + sw_off(rA, cchunk));
            ldsm4(ah[1], st + sw_off(rA + 16, cchunk));
#pragma unroll
            for (int ni = 0; ni < 4; ni++)
                ldsm4(b[ni], st + TILE_B + sw_off(rB + ni * 16, cchunk));
#pragma unroll
            for (int ni = 0; ni < 4; ni++)
#pragma unroll
                for (int s = 0; s < 2; s++) {
                    mma16816(acc[0][ni * 2 + s], ah[0], b[ni][s], b[ni][2 + s]);
                    mma16816(acc[1][ni * 2 + s], ah[1], b[ni][s], b[ni][2 + s]);
                }
        }
        if (c + 3 < NC) issue(c + 3, (c + 3) & 3);
        CP_COMMIT();
    }

    int gid = lane >> 2, q = lane & 3;
#pragma unroll
    for (int mi = 0; mi < 2; mi++)
#pragma unroll
        for (int j = 0; j < 8; j++) {
            int row = bm + mw + mi * 16 + gid;
            int col = bn + nw + j * 8 + q * 2;
            *(float2*)&C[(size_t)row * N + col] =
                make_float2(acc[mi][j][0], acc[mi][j][1]);
            *(float2*)&C[(size_t)(row + 8) * N + col] =
                make_float2(acc[mi][j][2], acc[mi][j][3]);
        }
}

// ---------------- RoPE: Q (scaled) + K -> fp16 ----------------
__global__ __launch_bounds__(256) void rope_qk(const float* __restrict__ cosb,
                                               const float* __restrict__ sinb) {
    int idx = blockIdx.x * blockDim.x + threadIdx.x;
    if (idx >= T_SEQ * 20 * 64) return;
    int d = idx & 63;
    int h = (idx >> 6) % 20;
    int t = idx / (64 * 20);
    float c = cosb[t * 64 + d], sn = sinb[t * 64 + d];
    if (h < 16) {
        int base = t * QKV_DIM + (h >> 2) * 768 + (h & 3) * 128;
        float x1 = g_qkv[base + d], x2 = g_qkv[base + 64 + d];
        size_t o = (size_t)t * 2048 + h * 128 + d;
        g_qh[o]      = __float2half_rn((x1 * c - x2 * sn) * SCALE_LOG2);
        g_qh[o + 64] = __float2half_rn((x2 * c + x1 * sn) * SCALE_LOG2);
    } else {
        int gi = h - 16;
        int base = t * QKV_DIM + gi * 768 + 512;
        float x1 = g_qkv[base + d], x2 = g_qkv[base + 64 + d];
        size_t o = ((size_t)gi * T_SEQ + t) * 128 + d;
        g_kh[o]      = __float2half_rn(x1 * c - x2 * sn);
        g_kh[o + 64] = __float2half_rn(x2 * c + x1 * sn);
    }
}

// ---------------- V transpose -> [g][d][t] fp16 ----------------
__global__ __launch_bounds__(256) void v_trans() {
    int idx = blockIdx.x * blockDim.x + threadIdx.x;
    if (idx >= NQG * 128 * T_SEQ) return;
    int t = idx & (T_SEQ - 1);
    int d = (idx >> 12) & 127;
    int gi = idx >> 19;
    float v = g_qkv[t * QKV_DIM + gi * 768 + 640 + d];
    g_vh[((size_t)gi * 128 + d) * T_SEQ + t] = __float2half_rn(v);
}

// ---------------- mma.sync flash attention (single-term QK + PV) ----------------
// 64 q-rows/CTA, 4 warps, Bc=64, 2-stage KV, 2 CTAs/SM.
// smem: Qh[0:16K) stages{K 16K, V 16K} x2 at 16K. Total 80KB.
#define AT_Q_BYTES 16384
#define AT_STG_OFF 16384
#define AT_STG_B   32768

__global__ __launch_bounds__(128, 2) void attn_mma() {
    extern __shared__ __align__(128) char smem[];
    uint32_t sb = smem_u32(smem);
    int tid = threadIdx.x;
    int lane = tid & 31, w = tid >> 5;          // 4 warps
    int qb = 63 - blockIdx.x;                   // longest first
    int h = blockIdx.y;
    int g = h >> 2;
    int rw = w * 16;
    int ktmax = qb;

    // ---- Q load (64 rows) ----
#pragma unroll
    for (int i = 0; i < 8; i++) {
        int chunk = tid + 128 * i;              // 0..1023
        int r = chunk >> 4, cd = chunk & 15;
        size_t src = (size_t)(qb * 64 + r) * 2048 + h * 128 + cd * 8;
        cp_async16(sb + (cd >> 2) * 4096 + sw_off(r, cd & 3), g_qh + src);
    }

    auto issueKV = [&](int kt, int stg) {
        uint32_t st = sb + AT_STG_OFF + stg * AT_STG_B;
#pragma unroll
        for (int i = 0; i < 8; i++) {
            int chunk = tid + 128 * i;
            int r = chunk >> 4, cd = chunk & 15;
            size_t src = ((size_t)g * T_SEQ + kt * 64 + r) * 128 + cd * 8;
            cp_async16(st + (cd >> 2) * 4096 + sw_off(r, cd & 3), g_kh + src);
        }
#pragma unroll
        for (int i = 0; i < 8; i++) {
            int chunk = tid + 128 * i;
            int d = chunk >> 3, sc = chunk & 7;
            size_t src = ((size_t)g * 128 + d) * T_SEQ + kt * 64 + sc * 8;
            cp_async16(st + 16384 + (sc >> 2) * 8192 + sw_off(d, sc & 3), g_vh + src);
        }
    };

    issueKV(0, 0); CP_COMMIT();
    if (1 <= ktmax) issueKV(1, 1);
    CP_COMMIT();

    float oacc[16][4];
#pragma unroll
    for (int i = 0; i < 16; i++)
#pragma unroll
        for (int j = 0; j < 4; j++) oacc[i][j] = 0.f;
    float mi0 = -1e30f, mi1 = -1e30f, li0 = 0.f, li1 = 0.f;

    int rK = lane & 15, cH = lane >> 4;
    int qr1 = qb * 64 + rw + (lane >> 2);

    for (int kt = 0; kt <= ktmax; kt++) {
        CP_WAIT(1);
        __syncthreads();

        uint32_t KH = sb + AT_STG_OFF + (kt & 1) * AT_STG_B;
        uint32_t VH = KH + 16384;

        // ---- S = Q K^T (single term, log2-scaled), batched ldsm ----
        float s[8][4];
#pragma unroll
        for (int j = 0; j < 8; j++)
#pragma unroll
            for (int e = 0; e < 4; e++) s[j][e] = 0.f;

#pragma unroll
        for (int kk = 0; kk < 8; kk++) {
            int c = ((kk & 1) << 1) + cH;
            uint32_t ah[4], kh[4][4];
            ldsm4(ah, sb + (kk >> 1) * 4096 + sw_off(rw + rK, c));
            uint32_t kpan = KH + (kk >> 1) * 4096;
#pragma unroll
            for (int ni = 0; ni < 4; ni++)
                ldsm4(kh[ni], kpan + sw_off(ni * 16 + rK, c));
#pragma unroll
            for (int ni = 0; ni < 4; ni++)
#pragma unroll
                for (int ss = 0; ss < 2; ss++)
                    mma16816(s[ni * 2 + ss], ah, kh[ni][ss], kh[ni][2 + ss]);
        }

        // ---- causal mask (diagonal tile only: kt == qb) ----
        if (kt == qb) {
            int colb = kt * 64 + ((lane & 3) << 1);
#pragma unroll
            for (int j = 0; j < 8; j++) {
                int c0 = colb + j * 8;
                if (c0 > qr1)     s[j][0] = -1e30f;
                if (c0 + 1 > qr1) s[j][1] = -1e30f;
                if (c0 > qr1 + 8)     s[j][2] = -1e30f;
                if (c0 + 1 > qr1 + 8) s[j][3] = -1e30f;
            }
        }

        // ---- online softmax (base-2) ----
        float mx0 = -1e30f, mx1 = -1e30f;
#pragma unroll
        for (int j = 0; j < 8; j++) {
            mx0 = fmaxf(mx0, fmaxf(s[j][0], s[j][1]));
            mx1 = fmaxf(mx1, fmaxf(s[j][2], s[j][3]));
        }
        mx0 = fmaxf(mx0, __shfl_xor_sync(0xffffffffu, mx0, 1));
        mx0 = fmaxf(mx0, __shfl_xor_sync(0xffffffffu, mx0, 2));
        mx1 = fmaxf(mx1, __shfl_xor_sync(0xffffffffu, mx1, 1));
        mx1 = fmaxf(mx1, __shfl_xor_sync(0xffffffffu, mx1, 2));
        float mn0 = fmaxf(mi0, mx0), mn1 = fmaxf(mi1, mx1);
        float a0 = exp2f(mi0 - mn0), a1 = exp2f(mi1 - mn1);
        mi0 = mn0; mi1 = mn1;
        float sum0 = 0.f, sum1 = 0.f;
#pragma unroll
        for (int j = 0; j < 8; j++) {
            s[j][0] = exp2f(s[j][0] - mn0);
            s[j][1] = exp2f(s[j][1] - mn0);
            s[j][2] = exp2f(s[j][2] - mn1);
            s[j][3] = exp2f(s[j][3] - mn1);
            sum0 += s[j][0] + s[j][1];
            sum1 += s[j][2] + s[j][3];
        }
        sum0 += __shfl_xor_sync(0xffffffffu, sum0, 1);
        sum0 += __shfl_xor_sync(0xffffffffu, sum0, 2);
        sum1 += __shfl_xor_sync(0xffffffffu, sum1, 1);
        sum1 += __shfl_xor_sync(0xffffffffu, sum1, 2);
        li0 = li0 * a0 + sum0;
        li1 = li1 * a1 + sum1;
        if (a0 != 1.f || a1 != 1.f) {
#pragma unroll
            for (int ni = 0; ni < 16; ni++) {
                oacc[ni][0] *= a0; oacc[ni][1] *= a0;
                oacc[ni][2] *= a1; oacc[ni][3] *= a1;
            }
        }

        // ---- O += P V, P from registers; V ldsm batched in groups of 4 ----
#pragma unroll
        for (int kk2 = 0; kk2 < 4; kk2++) {
            uint32_t hp[4];
            {
                float* p0 = s[2 * kk2];
                float* p1 = s[2 * kk2 + 1];
                hp[0] = pack2h(p0[0], p0[1]);
                hp[1] = pack2h(p0[2], p0[3]);
                hp[2] = pack2h(p1[0], p1[1]);
                hp[3] = pack2h(p1[2], p1[3]);
            }
            int c = ((kk2 & 1) << 1) + cH;
            uint32_t vpan = VH + (kk2 >> 1) * 8192;
#pragma unroll
            for (int g2 = 0; g2 < 2; g2++) {
                uint32_t vh[4][4];
#pragma unroll
                for (int n2 = 0; n2 < 4; n2++)
                    ldsm4(vh[n2], vpan + sw_off((g2 * 4 + n2) * 16 + rK, c));
#pragma unroll
                for (int n2 = 0; n2 < 4; n2++)
#pragma unroll
                    for (int ss = 0; ss < 2; ss++)
                        mma16816(oacc[(g2 * 4 + n2) * 2 + ss], hp,
                                 vh[n2][ss], vh[n2][2 + ss]);
            }
        }

        __syncthreads();   // all warps done reading stage (kt&1) before reuse
        if (kt + 2 <= ktmax) issueKV(kt + 2, (kt + 2) & 1);
        CP_COMMIT();
    }

    // ---- epilogue: O/l -> fp16 ----
    float inv0 = 1.f / li0, inv1 = 1.f / li1;
    size_t row1 = (size_t)qr1 * 2048 + h * 128;
    size_t row2 = row1 + (size_t)8 * 2048;
#pragma unroll
    for (int ni = 0; ni < 16; ni++) {
        int colo = ni * 8 + ((lane & 3) << 1);
        *(uint32_t*)&g_yh[row1 + colo] = pack2h(oacc[ni][0] * inv0, oacc[ni][1] * inv0);
        *(uint32_t*)&g_yh[row2 + colo] = pack2h(oacc[ni][2] * inv1, oacc[ni][3] * inv1);
    }
}

// ---------------- launch ----------------
extern "C" void kernel_launch(void* const* d_in, const int* in_sizes, int n_in,
                              void* d_out, int out_size) {
    const float* x    = (const float*)d_in[0];
    const float* cosb = (const float*)d_in[1];
    const float* sinb = (const float*)d_in[2];
    const float* Wa   = (const float*)d_in[3];
    const float* Wp   = (const float*)d_in[4];
    float* out = (float*)d_out;

    float* qkv_p;
    cudaGetSymbolAddress((void**)&qkv_p, g_qkv);
    __half *xh, *wa, *wp, *yh;
    cudaGetSymbolAddress((void**)&xh, g_xh);
    cudaGetSymbolAddress((void**)&wa, g_wa);
    cudaGetSymbolAddress((void**)&wp, g_wp);
    cudaGetSymbolAddress((void**)&yh, g_yh);

    const int gemm_smem = 4 * STAGE_B;                 // 64 KB
    cudaFuncSetAttribute(gemm_mma, cudaFuncAttributeMaxDynamicSharedMemorySize, gemm_smem);
    const int attn_smem = AT_STG_OFF + 2 * AT_STG_B;   // 80 KB
    cudaFuncSetAttribute(attn_mma, cudaFuncAttributeMaxDynamicSharedMemorySize, attn_smem);

    // 1) convert x and weights to fp16
    {
        int n4 = T_SEQ * C_DIM / 4;
        conv_fp16<<<(n4 + 255) / 256, 256>>>((const float4*)x, (uint32_t*)xh, n4);
        int w4 = QKV_DIM * C_DIM / 4;
        conv_fp16<<<(w4 + 255) / 256, 256>>>((const float4*)Wa, (uint32_t*)wa, w4);
        int p4 = C_DIM * C_DIM / 4;
        conv_fp16<<<(p4 + 255) / 256, 256>>>((const float4*)Wp, (uint32_t*)wp, p4);
    }

    // 2) qkv = x @ W_attn^T
    gemm_mma<<<dim3(QKV_DIM / 128, T_SEQ / 128), 256, gemm_smem>>>(
        xh, wa, qkv_p, QKV_DIM, C_DIM);

    // 3) rope + v transpose
    rope_qk<<<(T_SEQ * 20 * 64) / 256, 256>>>(cosb, sinb);
    v_trans<<<(NQG * 128 * T_SEQ) / 256, 256>>>();

    // 4) attention
    attn_mma<<<dim3(64, NHEAD), 128, attn_smem>>>();

    // 5) out = y @ W_proj^T
    gemm_mma<<<dim3(C_DIM / 128, T_SEQ / 128), 256, gemm_smem>>>(
        yh, wp, out, C_DIM, C_DIM);
}

// round 11
// speedup vs baseline: 7.8098x; 1.0460x over previous
#include <cuda_runtime.h>
#include <cuda_fp16.h>
#include <math.h>
#include <stdint.h>

#define T_SEQ 4096
#define C_DIM 2048
#define NHEAD 16
#define HS 128
#define NQG 4
#define QKV_DIM 3072
#define SCALE_LOG2 0.1275071050830161f       // (1/sqrt(128)) * log2(e)

// ---------------- scratch ----------------
__device__ __half g_qkvh[T_SEQ * QKV_DIM];    // qkv as fp16 (GEMM1 output)

__device__ __half g_xh[T_SEQ * C_DIM];        // x as fp16
__device__ __half g_wa[QKV_DIM * C_DIM];
__device__ __half g_wp[C_DIM * C_DIM];

__device__ __half g_qh[T_SEQ * NHEAD * HS];   // [t][h*128+d], scaled by SCALE_LOG2
__device__ __half g_kh[NQG * T_SEQ * HS];     // [g][t][d]
__device__ __half g_vh[NQG * HS * T_SEQ];     // [g][d][t]  (d-major)
__device__ __half g_yh[T_SEQ * C_DIM];        // attention out, fp16

// ---------------- PTX helpers ----------------
__device__ __forceinline__ uint32_t smem_u32(const void* p) {
    uint32_t a;
    asm("{ .reg .u64 t; cvta.to.shared.u64 t, %1; cvt.u32.u64 %0, t; }"
        : "=r"(a) : "l"(p));
    return a;
}
__device__ __forceinline__ void cp_async16(uint32_t s, const void* g) {
    asm volatile("cp.async.cg.shared.global [%0], [%1], 16;" :: "r"(s), "l"(g));
}
#define CP_COMMIT() asm volatile("cp.async.commit_group;" ::: "memory")
#define CP_WAIT(n)  asm volatile("cp.async.wait_group %0;" :: "n"(n) : "memory")

__device__ __forceinline__ void ldsm4(uint32_t* f, uint32_t a) {
    asm volatile("ldmatrix.sync.aligned.m8n8.x4.shared.b16 {%0,%1,%2,%3}, [%4];"
                 : "=r"(f[0]), "=r"(f[1]), "=r"(f[2]), "=r"(f[3]) : "r"(a));
}
__device__ __forceinline__ void mma16816(float* d, const uint32_t* a,
                                         uint32_t b0, uint32_t b1) {
    asm volatile(
        "mma.sync.aligned.m16n8k16.row.col.f32.f16.f16.f32 "
        "{%0,%1,%2,%3}, {%4,%5,%6,%7}, {%8,%9}, {%0,%1,%2,%3};"
        : "+f"(d[0]), "+f"(d[1]), "+f"(d[2]), "+f"(d[3])
        : "r"(a[0]), "r"(a[1]), "r"(a[2]), "r"(a[3]), "r"(b0), "r"(b1));
}
__device__ __forceinline__ uint32_t pack2h(float lo, float hi) {
    uint32_t r;
    asm("cvt.rn.f16x2.f32 %0, %1, %2;" : "=r"(r) : "f"(hi), "f"(lo));
    return r;
}

// 64B-row XOR swizzle (rows of 32 halves, 4x16B chunks) — attention tiles
__device__ __forceinline__ int sw_off(int r, int c) {
    return r * 64 + ((c ^ ((r >> 1) & 3)) << 4);
}
// 128B-row XOR swizzle (rows of 64 halves, 8x16B chunks) — GEMM tiles.
// 8 consecutive rows map a fixed chunk c to 8 distinct 16B bank groups.
__device__ __forceinline__ int sw128(int r, int c) {
    return r * 128 + (((c ^ r) & 7) << 4);
}

// ---------------- fp32 -> fp16 convert, grid-stride x4 (MLP 4) ----------------
__global__ __launch_bounds__(256) void conv_fp16(const float4* __restrict__ s,
                                                 uint32_t* __restrict__ h, int n4) {
    int i0 = blockIdx.x * 256 + threadIdx.x;
    int stride = gridDim.x * 256;
#pragma unroll
    for (int k = 0; k < 4; k++) {
        int idx = i0 + k * stride;
        if (idx < n4) {
            float4 v = s[idx];
            h[2 * idx]     = pack2h(v.x, v.y);
            h[2 * idx + 1] = pack2h(v.z, v.w);
        }
    }
}

// ---------------- mma.sync fp16 GEMM: C = A * B^T ----------------
// CTA 128x128, BK=64, 8 warps (4Mx2N), 2 CTAs/SM, 3-stage x 32KB, 1 sync/chunk.
#define BKG 64
#define TILE_BG (128 * 128)     // 16KB per operand tile
#define STAGE_BG (2 * TILE_BG)  // 32KB

template <bool HALF_OUT>
__global__ __launch_bounds__(256, 2) void gemm_mma(const __half* __restrict__ A,
                                                   const __half* __restrict__ B,
                                                   void* __restrict__ Cv, int N, int K) {
    extern __shared__ __align__(128) char smem[];
    int tid = threadIdx.x;
    int lane = tid & 31, w = tid >> 5;
    int bm = blockIdx.y * 128, bn = blockIdx.x * 128;
    int mw = (w & 3) * 32, nw = (w >> 2) * 64;
    uint32_t sbase = smem_u32(smem);

    float acc[2][8][4];
#pragma unroll
    for (int i = 0; i < 2; i++)
#pragma unroll
        for (int j = 0; j < 8; j++)
#pragma unroll
            for (int q = 0; q < 4; q++) acc[i][j][q] = 0.f;

    const int NC = K / BKG;

    auto issue = [&](int c, int buf) {
        uint32_t st = sbase + buf * STAGE_BG;
        int kc = c * BKG;
#pragma unroll
        for (int k = 0; k < 4; k++) {
            int idx = tid + 256 * k;        // 0..1023
            int r = idx >> 3, cc = idx & 7;
            int so = sw128(r, cc);
            size_t gA = (size_t)(bm + r) * K + kc + cc * 8;
            size_t gB = (size_t)(bn + r) * K + kc + cc * 8;
            cp_async16(st + so, A + gA);
            cp_async16(st + TILE_BG + so, B + gB);
        }
    };

    issue(0, 0); CP_COMMIT();
    issue(1, 1); CP_COMMIT();

    int rA = mw + (lane & 15);
    int rB = nw + (lane & 15);

    for (int c = 0; c < NC; c++) {
        CP_WAIT(1);
        __syncthreads();

        uint32_t st = sbase + (c % 3) * STAGE_BG;
#pragma unroll
        for (int k16 = 0; k16 < 4; k16++) {
            int cchunk = k16 * 2 + (lane >> 4);
            uint32_t ah[2][4], b[4][4];
            ldsm4(ah[0], st + sw128(rA, cchunk));
            ldsm4(ah[1], st + sw128(rA + 16, cchunk));
#pragma unroll
            for (int ni = 0; ni < 4; ni++)
                ldsm4(b[ni], st + TILE_BG + sw128(rB + ni * 16, cchunk));
#pragma unroll
            for (int ni = 0; ni < 4; ni++)
#pragma unroll
                for (int s = 0; s < 2; s++) {
                    mma16816(acc[0][ni * 2 + s], ah[0], b[ni][s], b[ni][2 + s]);
                    mma16816(acc[1][ni * 2 + s], ah[1], b[ni][s], b[ni][2 + s]);
                }
        }
        if (c + 2 < NC) issue(c + 2, (c + 2) % 3);
        CP_COMMIT();
    }

    int gid = lane >> 2, q = lane & 3;
#pragma unroll
    for (int mi = 0; mi < 2; mi++)
#pragma unroll
        for (int j = 0; j < 8; j++) {
            int row = bm + mw + mi * 16 + gid;
            int col = bn + nw + j * 8 + q * 2;
            if constexpr (HALF_OUT) {
                __half* C = (__half*)Cv;
                *(uint32_t*)&C[(size_t)row * N + col] =
                    pack2h(acc[mi][j][0], acc[mi][j][1]);
                *(uint32_t*)&C[(size_t)(row + 8) * N + col] =
                    pack2h(acc[mi][j][2], acc[mi][j][3]);
            } else {
                float* C = (float*)Cv;
                *(float2*)&C[(size_t)row * N + col] =
                    make_float2(acc[mi][j][0], acc[mi][j][1]);
                *(float2*)&C[(size_t)(row + 8) * N + col] =
                    make_float2(acc[mi][j][2], acc[mi][j][3]);
            }
        }
}

// ---------------- RoPE: Q (scaled) + K -> fp16, vectorized (4 d per thread) ----------------
__global__ __launch_bounds__(256) void rope_qk(const float* __restrict__ cosb,
                                               const float* __restrict__ sinb) {
    int idx = blockIdx.x * 256 + threadIdx.x;       // T*20*16 threads
    if (idx >= T_SEQ * 20 * 16) return;
    int d4 = idx & 15;                              // d = d4*4
    int h = (idx >> 4) % 20;
    int t = idx / 320;
    int d = d4 * 4;
    float4 cv = *(const float4*)&cosb[t * 64 + d];
    float4 sv = *(const float4*)&sinb[t * 64 + d];
    float cs[4] = {cv.x, cv.y, cv.z, cv.w};
    float sn[4] = {sv.x, sv.y, sv.z, sv.w};

    int base = (h < 16) ? (t * QKV_DIM + (h >> 2) * 768 + (h & 3) * 128)
                        : (t * QKV_DIM + (h - 16) * 768 + 512);
    // load 4 halves of x1 and x2
    uint2 u1 = *(const uint2*)&g_qkvh[base + d];
    uint2 u2 = *(const uint2*)&g_qkvh[base + 64 + d];
    __half2* h1 = (__half2*)&u1;
    __half2* h2 = (__half2*)&u2;
    float x1[4] = {__low2float(h1[0]), __high2float(h1[0]),
                   __low2float(h1[1]), __high2float(h1[1])};
    float x2[4] = {__low2float(h2[0]), __high2float(h2[0]),
                   __low2float(h2[1]), __high2float(h2[1])};
    float o1[4], o2[4];
#pragma unroll
    for (int k = 0; k < 4; k++) {
        o1[k] = x1[k] * cs[k] - x2[k] * sn[k];
        o2[k] = x2[k] * cs[k] + x1[k] * sn[k];
    }
    if (h < 16) {
#pragma unroll
        for (int k = 0; k < 4; k++) { o1[k] *= SCALE_LOG2; o2[k] *= SCALE_LOG2; }
        size_t o = (size_t)t * 2048 + h * 128 + d;
        *(uint2*)&g_qh[o]      = make_uint2(pack2h(o1[0], o1[1]), pack2h(o1[2], o1[3]));
        *(uint2*)&g_qh[o + 64] = make_uint2(pack2h(o2[0], o2[1]), pack2h(o2[2], o2[3]));
    } else {
        size_t o = ((size_t)(h - 16) * T_SEQ + t) * 128 + d;
        *(uint2*)&g_kh[o]      = make_uint2(pack2h(o1[0], o1[1]), pack2h(o1[2], o1[3]));
        *(uint2*)&g_kh[o + 64] = make_uint2(pack2h(o2[0], o2[1]), pack2h(o2[2], o2[3]));
    }
}

// ---------------- V transpose -> [g][d][t] fp16 ----------------
__global__ __launch_bounds__(256) void v_trans() {
    int idx = blockIdx.x * blockDim.x + threadIdx.x;
    if (idx >= NQG * 128 * T_SEQ) return;
    int t = idx & (T_SEQ - 1);
    int d = (idx >> 12) & 127;
    int gi = idx >> 19;
    g_vh[((size_t)gi * 128 + d) * T_SEQ + t] =
        g_qkvh[t * QKV_DIM + gi * 768 + 640 + d];
}

// ---------------- mma.sync flash attention (single-term QK + PV) ----------------
// 64 q-rows/CTA, 4 warps, Bc=64, 2-stage KV, 2 CTAs/SM. smem 80KB.
#define AT_Q_BYTES 16384
#define AT_STG_OFF 16384
#define AT_STG_B   32768

__global__ __launch_bounds__(128, 2) void attn_mma() {
    extern __shared__ __align__(128) char smem[];
    uint32_t sb = smem_u32(smem);
    int tid = threadIdx.x;
    int lane = tid & 31, w = tid >> 5;          // 4 warps
    int qb = 63 - blockIdx.x;                   // longest first
    int h = blockIdx.y;
    int g = h >> 2;
    int rw = w * 16;
    int ktmax = qb;

    // ---- Q load (64 rows) ----
#pragma unroll
    for (int i = 0; i < 8; i++) {
        int chunk = tid + 128 * i;              // 0..1023
        int r = chunk >> 4, cd = chunk & 15;
        size_t src = (size_t)(qb * 64 + r) * 2048 + h * 128 + cd * 8;
        cp_async16(sb + (cd >> 2) * 4096 + sw_off(r, cd & 3), g_qh + src);
    }

    auto issueKV = [&](int kt, int stg) {
        uint32_t st = sb + AT_STG_OFF + stg * AT_STG_B;
#pragma unroll
        for (int i = 0; i < 8; i++) {
            int chunk = tid + 128 * i;
            int r = chunk >> 4, cd = chunk & 15;
            size_t src = ((size_t)g * T_SEQ + kt * 64 + r) * 128 + cd * 8;
            cp_async16(st + (cd >> 2) * 4096 + sw_off(r, cd & 3), g_kh + src);
        }
#pragma unroll
        for (int i = 0; i < 8; i++) {
            int chunk = tid + 128 * i;
            int d = chunk >> 3, sc = chunk & 7;
            size_t src = ((size_t)g * 128 + d) * T_SEQ + kt * 64 + sc * 8;
            cp_async16(st + 16384 + (sc >> 2) * 8192 + sw_off(d, sc & 3), g_vh + src);
        }
    };

    issueKV(0, 0); CP_COMMIT();
    if (1 <= ktmax) issueKV(1, 1);
    CP_COMMIT();

    float oacc[16][4];
#pragma unroll
    for (int i = 0; i < 16; i++)
#pragma unroll
        for (int j = 0; j < 4; j++) oacc[i][j] = 0.f;
    float mi0 = -1e30f, mi1 = -1e30f, li0 = 0.f, li1 = 0.f;

    int rK = lane & 15, cH = lane >> 4;
    int qr1 = qb * 64 + rw + (lane >> 2);

    for (int kt = 0; kt <= ktmax; kt++) {
        CP_WAIT(1);
        __syncthreads();

        uint32_t KH = sb + AT_STG_OFF + (kt & 1) * AT_STG_B;
        uint32_t VH = KH + 16384;

        // ---- S = Q K^T (single term, log2-scaled), batched ldsm ----
        float s[8][4];
#pragma unroll
        for (int j = 0; j < 8; j++)
#pragma unroll
            for (int e = 0; e < 4; e++) s[j][e] = 0.f;

#pragma unroll
        for (int kk = 0; kk < 8; kk++) {
            int c = ((kk & 1) << 1) + cH;
            uint32_t ah[4], kh[4][4];
            ldsm4(ah, sb + (kk >> 1) * 4096 + sw_off(rw + rK, c));
            uint32_t kpan = KH + (kk >> 1) * 4096;
#pragma unroll
            for (int ni = 0; ni < 4; ni++)
                ldsm4(kh[ni], kpan + sw_off(ni * 16 + rK, c));
#pragma unroll
            for (int ni = 0; ni < 4; ni++)
#pragma unroll
                for (int ss = 0; ss < 2; ss++)
                    mma16816(s[ni * 2 + ss], ah, kh[ni][ss], kh[ni][2 + ss]);
        }

        // ---- causal mask (diagonal tile only: kt == qb) ----
        if (kt == qb) {
            int colb = kt * 64 + ((lane & 3) << 1);
#pragma unroll
            for (int j = 0; j < 8; j++) {
                int c0 = colb + j * 8;
                if (c0 > qr1)     s[j][0] = -1e30f;
                if (c0 + 1 > qr1) s[j][1] = -1e30f;
                if (c0 > qr1 + 8)     s[j][2] = -1e30f;
                if (c0 + 1 > qr1 + 8) s[j][3] = -1e30f;
            }
        }

        // ---- online softmax (base-2) ----
        float mx0 = -1e30f, mx1 = -1e30f;
#pragma unroll
        for (int j = 0; j < 8; j++) {
            mx0 = fmaxf(mx0, fmaxf(s[j][0], s[j][1]));
            mx1 = fmaxf(mx1, fmaxf(s[j][2], s[j][3]));
        }
        mx0 = fmaxf(mx0, __shfl_xor_sync(0xffffffffu, mx0, 1));
        mx0 = fmaxf(mx0, __shfl_xor_sync(0xffffffffu, mx0, 2));
        mx1 = fmaxf(mx1, __shfl_xor_sync(0xffffffffu, mx1, 1));
        mx1 = fmaxf(mx1, __shfl_xor_sync(0xffffffffu, mx1, 2));
        float mn0 = fmaxf(mi0, mx0), mn1 = fmaxf(mi1, mx1);
        float a0 = exp2f(mi0 - mn0), a1 = exp2f(mi1 - mn1);
        mi0 = mn0; mi1 = mn1;
        float sum0 = 0.f, sum1 = 0.f;
#pragma unroll
        for (int j = 0; j < 8; j++) {
            s[j][0] = exp2f(s[j][0] - mn0);
            s[j][1] = exp2f(s[j][1] - mn0);
            s[j][2] = exp2f(s[j][2] - mn1);
            s[j][3] = exp2f(s[j][3] - mn1);
            sum0 += s[j][0] + s[j][1];
            sum1 += s[j][2] + s[j][3];
        }
        sum0 += __shfl_xor_sync(0xffffffffu, sum0, 1);
        sum0 += __shfl_xor_sync(0xffffffffu, sum0, 2);
        sum1 += __shfl_xor_sync(0xffffffffu, sum1, 1);
        sum1 += __shfl_xor_sync(0xffffffffu, sum1, 2);
        li0 = li0 * a0 + sum0;
        li1 = li1 * a1 + sum1;
        if (a0 != 1.f || a1 != 1.f) {
#pragma unroll
            for (int ni = 0; ni < 16; ni++) {
                oacc[ni][0] *= a0; oacc[ni][1] *= a0;
                oacc[ni][2] *= a1; oacc[ni][3] *= a1;
            }
        }

        // ---- O += P V, P from registers; V ldsm batched in groups of 4 ----
#pragma unroll
        for (int kk2 = 0; kk2 < 4; kk2++) {
            uint32_t hp[4];
            {
                float* p0 = s[2 * kk2];
                float* p1 = s[2 * kk2 + 1];
                hp[0] = pack2h(p0[0], p0[1]);
                hp[1] = pack2h(p0[2], p0[3]);
                hp[2] = pack2h(p1[0], p1[1]);
                hp[3] = pack2h(p1[2], p1[3]);
            }
            int c = ((kk2 & 1) << 1) + cH;
            uint32_t vpan = VH + (kk2 >> 1) * 8192;
#pragma unroll
            for (int g2 = 0; g2 < 2; g2++) {
                uint32_t vh[4][4];
#pragma unroll
                for (int n2 = 0; n2 < 4; n2++)
                    ldsm4(vh[n2], vpan + sw_off((g2 * 4 + n2) * 16 + rK, c));
#pragma unroll
                for (int n2 = 0; n2 < 4; n2++)
#pragma unroll
                    for (int ss = 0; ss < 2; ss++)
                        mma16816(oacc[(g2 * 4 + n2) * 2 + ss], hp,
                                 vh[n2][ss], vh[n2][2 + ss]);
            }
        }

        __syncthreads();   // all warps done reading stage (kt&1) before reuse
        if (kt + 2 <= ktmax) issueKV(kt + 2, (kt + 2) & 1);
        CP_COMMIT();
    }

    // ---- epilogue: O/l -> fp16 ----
    float inv0 = 1.f / li0, inv1 = 1.f / li1;
    size_t row1 = (size_t)qr1 * 2048 + h * 128;
    size_t row2 = row1 + (size_t)8 * 2048;
#pragma unroll
    for (int ni = 0; ni < 16; ni++) {
        int colo = ni * 8 + ((lane & 3) << 1);
        *(uint32_t*)&g_yh[row1 + colo] = pack2h(oacc[ni][0] * inv0, oacc[ni][1] * inv0);
        *(uint32_t*)&g_yh[row2 + colo] = pack2h(oacc[ni][2] * inv1, oacc[ni][3] * inv1);
    }
}

// ---------------- launch ----------------
extern "C" void kernel_launch(void* const* d_in, const int* in_sizes, int n_in,
                              void* d_out, int out_size) {
    const float* x    = (const float*)d_in[0];
    const float* cosb = (const float*)d_in[1];
    const float* sinb = (const float*)d_in[2];
    const float* Wa   = (const float*)d_in[3];
    const float* Wp   = (const float*)d_in[4];
    float* out = (float*)d_out;

    __half *qkvh, *xh, *wa, *wp, *yh;
    cudaGetSymbolAddress((void**)&qkvh, g_qkvh);
    cudaGetSymbolAddress((void**)&xh, g_xh);
    cudaGetSymbolAddress((void**)&wa, g_wa);
    cudaGetSymbolAddress((void**)&wp, g_wp);
    cudaGetSymbolAddress((void**)&yh, g_yh);

    const int gemm_smem = 3 * STAGE_BG;                // 96 KB
    cudaFuncSetAttribute(gemm_mma<true>,
                         cudaFuncAttributeMaxDynamicSharedMemorySize, gemm_smem);
    cudaFuncSetAttribute(gemm_mma<false>,
                         cudaFuncAttributeMaxDynamicSharedMemorySize, gemm_smem);
    const int attn_smem = AT_STG_OFF + 2 * AT_STG_B;   // 80 KB
    cudaFuncSetAttribute(attn_mma, cudaFuncAttributeMaxDynamicSharedMemorySize, attn_smem);

    // 1) convert x and weights to fp16 (grid-stride x4)
    {
        int n4 = T_SEQ * C_DIM / 4;
        conv_fp16<<<(n4 + 1023) / 1024, 256>>>((const float4*)x, (uint32_t*)xh, n4);
        int w4 = QKV_DIM * C_DIM / 4;
        conv_fp16<<<(w4 + 1023) / 1024, 256>>>((const float4*)Wa, (uint32_t*)wa, w4);
        int p4 = C_DIM * C_DIM / 4;
        conv_fp16<<<(p4 + 1023) / 1024, 256>>>((const float4*)Wp, (uint32_t*)wp, p4);
    }

    // 2) qkv = x @ W_attn^T  (fp16 output)
    gemm_mma<true><<<dim3(QKV_DIM / 128, T_SEQ / 128), 256, gemm_smem>>>(
        xh, wa, qkvh, QKV_DIM, C_DIM);

    // 3) rope + v transpose
    rope_qk<<<(T_SEQ * 20 * 16) / 256, 256>>>(cosb, sinb);
    v_trans<<<(NQG * 128 * T_SEQ) / 256, 256>>>();

    // 4) attention
    attn_mma<<<dim3(64, NHEAD), 128, attn_smem>>>();

    // 5) out = y @ W_proj^T  (fp32 output)
    gemm_mma<false><<<dim3(C_DIM / 128, T_SEQ / 128), 256, gemm_smem>>>(
        yh, wp, out, C_DIM, C_DIM);
}